// round 7
// baseline (speedup 1.0000x reference)
#include <cuda_runtime.h>
#include <cuda_bf16.h>
#include <math.h>
#include <stdint.h>

// Problem constants
#define BS      2048
#define NE      64
#define NQ      16
#define EMBED   512
#define NHEAD   8
#define HD      64

// ---------------------------------------------------------------------------
// Scratch (__device__ globals — allocation-free)
// ---------------------------------------------------------------------------
__device__ __nv_bfloat16 g_eh[(size_t)BS * NE * 512];   // entities hi
__device__ __nv_bfloat16 g_el[(size_t)BS * NE * 512];   // entities lo
__device__ __nv_bfloat16 g_wh[1536 * 512];              // W_in hi
__device__ __nv_bfloat16 g_wl[1536 * 512];              // W_in lo
__device__ __nv_bfloat16 g_oh[512 * 512];               // W_out hi
__device__ __nv_bfloat16 g_ol[512 * 512];               // W_out lo
__device__ float         g_q [(size_t)BS * NQ * 512];   // Q   fp32
__device__ float         g_kv[(size_t)BS * NE * 1024];  // K|V fp32
__device__ __nv_bfloat16 g_ah[(size_t)BS * NQ * 512];   // attn out hi
__device__ __nv_bfloat16 g_al[(size_t)BS * NQ * 512];   // attn out lo

__device__ __forceinline__ float neg_inf() { return __int_as_float(0xff800000u); }

__device__ __forceinline__ uint32_t smem_u32(const void* p) {
    uint32_t a;
    asm("{ .reg .u64 t; cvta.to.shared.u64 t, %1; cvt.u32.u64 %0, t; }" : "=r"(a) : "l"(p));
    return a;
}
#define SW64(bo) ((bo) ^ (((bo) >> 3) & 0x30))

#define CP_ASYNC16(dst, src) \
    asm volatile("cp.async.cg.shared.global [%0], [%1], 16;" :: "r"(dst), "l"(src) : "memory")
#define CP_COMMIT() asm volatile("cp.async.commit_group;" ::: "memory")
#define CP_WAIT2()  asm volatile("cp.async.wait_group 2;" ::: "memory")

#define LDMATRIX_X4(r0, r1, r2, r3, addr) \
    asm volatile("ldmatrix.sync.aligned.m8n8.x4.shared.b16 {%0,%1,%2,%3}, [%4];" \
        : "=r"(r0), "=r"(r1), "=r"(r2), "=r"(r3) : "r"(addr))

#define MMA_BF16(c, a, b) \
    asm volatile("mma.sync.aligned.m16n8k16.row.col.f32.bf16.bf16.f32 " \
        "{%0,%1,%2,%3}, {%4,%5,%6,%7}, {%8,%9}, {%0,%1,%2,%3};" \
        : "+f"((c)[0]), "+f"((c)[1]), "+f"((c)[2]), "+f"((c)[3]) \
        : "r"((a)[0]), "r"((a)[1]), "r"((a)[2]), "r"((a)[3]), "r"((b)[0]), "r"((b)[1]))

// ---------------------------------------------------------------------------
// Split fp32 -> (bf16 hi, bf16 lo).  sel: 0=entities, 1=W_in, 2=W_out
// ---------------------------------------------------------------------------
__global__ void __launch_bounds__(256)
split_kernel(const float* __restrict__ src, int sel, int n4)
{
    __nv_bfloat16 *hi, *lo;
    if (sel == 0)      { hi = g_eh; lo = g_el; }
    else if (sel == 1) { hi = g_wh; lo = g_wl; }
    else               { hi = g_oh; lo = g_ol; }

    for (int i = blockIdx.x * blockDim.x + threadIdx.x; i < n4;
         i += gridDim.x * blockDim.x) {
        const float4 v = ((const float4*)src)[i];
        float f[4] = {v.x, v.y, v.z, v.w};
        unsigned short hs[4], ls[4];
#pragma unroll
        for (int j = 0; j < 4; j++) {
            __nv_bfloat16 hb = __float2bfloat16(f[j]);
            hs[j] = __bfloat16_as_ushort(hb);
            ls[j] = __bfloat16_as_ushort(__float2bfloat16(f[j] - __bfloat162float(hb)));
        }
        uint2 hv, lv;
        hv.x = (uint32_t)hs[0] | ((uint32_t)hs[1] << 16);
        hv.y = (uint32_t)hs[2] | ((uint32_t)hs[3] << 16);
        lv.x = (uint32_t)ls[0] | ((uint32_t)ls[1] << 16);
        lv.y = (uint32_t)ls[2] | ((uint32_t)ls[3] << 16);
        ((uint2*)hi)[i] = hv;
        ((uint2*)lo)[i] = lv;
    }
}

// ---------------------------------------------------------------------------
// mma.sync bf16x3 GEMM, 4-stage cp.async pipeline:
// C[m,n] = sum_d A[m,d]*B[n,d], terms Ah*Bh + Ah*Bl + Al*Bh (fp32 accum).
// CTA tile 128x256, 512 threads (16 warps: 2M x 8N), warp tile 64x32.
// BK=32 (64B rows, SW64 swizzle). Stage 48KB: Ah 8K|Al 8K|Bh 16K|Bl 16K.
// 4 stages (192KB smem), 16 k-chunks, schedule: wait(2) -> bar -> issue(t+3)
// -> compute(t). One __syncthreads per chunk, 3 chunks in flight.
// MODE 0: KV proj (C=g_kv, ldc=1024)  MODE 1: Q proj (gathered A rows)
// MODE 2: out proj (bias + post_mask)
// ---------------------------------------------------------------------------
#define STAGE_BYTES 49152
#define OFF_AL      8192
#define OFF_BH      16384
#define OFF_BL      32768
#define GSMEM_TOTAL (4 * STAGE_BYTES)
#define NCHUNK      16

template <int MODE>
__global__ void __launch_bounds__(512, 1)
mma_gemm(float* __restrict__ Cout,
         const float* __restrict__ bias,
         const unsigned int* __restrict__ mask)
{
    extern __shared__ char smem[];
    const uint32_t sb = smem_u32(smem);
    const int tid  = threadIdx.x;
    const int wid  = tid >> 5;
    const int lane = tid & 31;
    const int wm   = wid & 1;          // 0..1  (M)
    const int wn   = wid >> 1;         // 0..7  (N)
    const int row0 = blockIdx.y * 128;
    const int col0 = blockIdx.x * 256;

    const __nv_bfloat16 *Ahp, *Alp, *Bhp, *Blp;
    if (MODE == 0)      { Ahp = g_eh; Alp = g_el; Bhp = g_wh + 512 * 512; Blp = g_wl + 512 * 512; }
    else if (MODE == 1) { Ahp = g_eh; Alp = g_el; Bhp = g_wh;             Blp = g_wl; }
    else                { Ahp = g_ah; Alp = g_al; Bhp = g_oh;             Blp = g_ol; }
    float* C = (MODE == 0) ? g_kv : (MODE == 1) ? g_q : Cout;
    const int ldc = (MODE == 0) ? 1024 : 512;

    float acc[4][4][4];
#pragma unroll
    for (int i = 0; i < 4; i++)
#pragma unroll
        for (int j = 0; j < 4; j++)
#pragma unroll
            for (int k = 0; k < 4; k++) acc[i][j][k] = 0.0f;

    // ---- async loader: all four operand tiles of k-chunk t into stage t%4 ----
    auto issue_load = [&](int t) {
        const int kc = t * 32;
        const uint32_t st = sb + (uint32_t)(t & 3) * STAGE_BYTES;
        {   // Ah, Al: 128 rows x 4 cols of 16B -> 1 cp per array per thread
            const int r = tid >> 2, c = tid & 3;
            const int gr = row0 + r;
            const int ar = (MODE == 1) ? (((gr >> 4) << 6) + (gr & 15)) : gr;
            const uint32_t sw = SW64((uint32_t)(r * 64 + c * 16));
            CP_ASYNC16(st + sw,          Ahp + (size_t)ar * 512 + kc + c * 8);
            CP_ASYNC16(st + OFF_AL + sw, Alp + (size_t)ar * 512 + kc + c * 8);
        }
#pragma unroll
        for (int i = 0; i < 2; i++) {   // Bh, Bl: 256 rows x 4 cols -> 2 cp each
            const int u = tid + i * 512;
            const int r = u >> 2, c = u & 3;
            const uint32_t sw = SW64((uint32_t)(r * 64 + c * 16));
            CP_ASYNC16(st + OFF_BH + sw, Bhp + (size_t)(col0 + r) * 512 + kc + c * 8);
            CP_ASYNC16(st + OFF_BL + sw, Blp + (size_t)(col0 + r) * 512 + kc + c * 8);
        }
        CP_COMMIT();
    };

    issue_load(0);
    issue_load(1);
    issue_load(2);

    const int l8   = lane & 7;
    const int lsel = lane >> 3;                      // 0..3 (ldmatrix quad)

    for (int t = 0; t < NCHUNK; t++) {
        CP_WAIT2();                                  // chunk t landed (3rd-newest group)
        __syncthreads();                             // publish + guard stage reuse
        if (t + 3 < NCHUNK) issue_load(t + 3);
        else                CP_COMMIT();             // empty group keeps count exact

        const uint32_t st = sb + (uint32_t)(t & 3) * STAGE_BYTES;

#pragma unroll
        for (int ks = 0; ks < 2; ks++) {             // 2 x k16 per chunk
            const int ra = wm * 64 + l8 + (lsel & 1) * 8;
            const int ca = ks * 2 + (lsel >> 1);     // 16B col 0..3
            const int rb = wn * 32 + (lsel >> 1) * 8 + l8;
            const int cb = ks * 2 + (lsel & 1);

            uint32_t ah[4][4], al[4][4], bh[4][2], bl[4][2];
#pragma unroll
            for (int am = 0; am < 4; am++) {
                const int r = ra + am * 16;
                const uint32_t off = SW64((uint32_t)(r * 64 + ca * 16));
                LDMATRIX_X4(ah[am][0], ah[am][1], ah[am][2], ah[am][3], st + off);
            }
#pragma unroll
            for (int bp = 0; bp < 2; bp++) {
                const int r = rb + bp * 16;
                const uint32_t off = SW64((uint32_t)(r * 64 + cb * 16));
                LDMATRIX_X4(bh[2 * bp][0], bh[2 * bp][1], bh[2 * bp + 1][0], bh[2 * bp + 1][1],
                            st + OFF_BH + off);
            }
            // term 0: Ah * Bh
#pragma unroll
            for (int am = 0; am < 4; am++)
#pragma unroll
                for (int nt = 0; nt < 4; nt++)
                    MMA_BF16(acc[am][nt], ah[am], bh[nt]);
            // term 1: Ah * Bl
#pragma unroll
            for (int bp = 0; bp < 2; bp++) {
                const int r = rb + bp * 16;
                const uint32_t off = SW64((uint32_t)(r * 64 + cb * 16));
                LDMATRIX_X4(bl[2 * bp][0], bl[2 * bp][1], bl[2 * bp + 1][0], bl[2 * bp + 1][1],
                            st + OFF_BL + off);
            }
#pragma unroll
            for (int am = 0; am < 4; am++)
#pragma unroll
                for (int nt = 0; nt < 4; nt++)
                    MMA_BF16(acc[am][nt], ah[am], bl[nt]);
            // term 2: Al * Bh
#pragma unroll
            for (int am = 0; am < 4; am++) {
                const int r = ra + am * 16;
                const uint32_t off = SW64((uint32_t)(r * 64 + ca * 16));
                LDMATRIX_X4(al[am][0], al[am][1], al[am][2], al[am][3], st + OFF_AL + off);
            }
#pragma unroll
            for (int am = 0; am < 4; am++)
#pragma unroll
                for (int nt = 0; nt < 4; nt++)
                    MMA_BF16(acc[am][nt], al[am], bh[nt]);
        }
    }

    // ---- epilogue: warp tile 64x32, frag (g,tg) layout ----
    const int g  = lane >> 2;
    const int tg = lane & 3;
#pragma unroll
    for (int am = 0; am < 4; am++) {
        const int r0 = row0 + wm * 64 + am * 16 + g;
        const int r1 = r0 + 8;
        bool z0 = false, z1 = false;
        if (MODE == 2) { z0 = (mask[r0] != 0u); z1 = (mask[r1] != 0u); }
#pragma unroll
        for (int nt = 0; nt < 4; nt++) {
            const int col = col0 + wn * 32 + nt * 8 + tg * 2;
            float2 v0 = make_float2(acc[am][nt][0], acc[am][nt][1]);
            float2 v1 = make_float2(acc[am][nt][2], acc[am][nt][3]);
            if (MODE == 2) {
                const float bb0 = bias[col], bb1 = bias[col + 1];
                v0.x = z0 ? 0.0f : v0.x + bb0;  v0.y = z0 ? 0.0f : v0.y + bb1;
                v1.x = z1 ? 0.0f : v1.x + bb0;  v1.y = z1 ? 0.0f : v1.y + bb1;
            }
            *(float2*)(C + (size_t)r0 * ldc + col) = v0;
            *(float2*)(C + (size_t)r1 * ldc + col) = v1;
        }
    }
}

// ---------------------------------------------------------------------------
// Attention: one block per (batch, head). 128 threads. Emits bf16 hi/lo.
// ---------------------------------------------------------------------------
__global__ void __launch_bounds__(128)
attn_kernel(const unsigned int* __restrict__ pre_mask)
{
    __shared__ float qs[16][68];
    __shared__ float ks[64][68];
    __shared__ float vs[64][68];
    __shared__ float at[16][68];

    const int b = blockIdx.x;
    const int h = blockIdx.y;
    const int tid = threadIdx.x;

#pragma unroll
    for (int rep = 0; rep < 2; rep++) {
        const int uu = tid + rep * 128;
        const int i = uu >> 4, d4 = uu & 15;
        *(float4*)&qs[i][d4 * 4] =
            *(const float4*)(g_q + ((size_t)(b * 16 + i)) * 512 + h * 64 + d4 * 4);
    }
#pragma unroll
    for (int rep = 0; rep < 8; rep++) {
        const int uu = tid + rep * 128;
        const int n = uu >> 4, d4 = uu & 15;
        const size_t base = ((size_t)(b * 64 + n)) * 1024 + h * 64 + d4 * 4;
        *(float4*)&ks[n][d4 * 4] = *(const float4*)(g_kv + base);
        *(float4*)&vs[n][d4 * 4] = *(const float4*)(g_kv + base + 512);
    }
    __syncthreads();

    const int i = tid >> 3;
    const int c = tid & 7;
    const unsigned int* pm = pre_mask + ((size_t)b * 64 + i) * 64;

    float lg[8];
    {
        float dacc[8] = {0, 0, 0, 0, 0, 0, 0, 0};
        for (int d4 = 0; d4 < 16; d4++) {
            const float4 q = *(const float4*)&qs[i][d4 * 4];
#pragma unroll
            for (int j = 0; j < 8; j++) {
                const float4 kv = *(const float4*)&ks[c + j * 8][d4 * 4];
                dacc[j] = fmaf(q.x, kv.x, dacc[j]);
                dacc[j] = fmaf(q.y, kv.y, dacc[j]);
                dacc[j] = fmaf(q.z, kv.z, dacc[j]);
                dacc[j] = fmaf(q.w, kv.w, dacc[j]);
            }
        }
        const float NI = neg_inf();
        float mx = NI;
#pragma unroll
        for (int j = 0; j < 8; j++) {
            lg[j] = (pm[c + j * 8] != 0u) ? NI : dacc[j] * 0.125f;
            mx = fmaxf(mx, lg[j]);
        }
        mx = fmaxf(mx, __shfl_xor_sync(0xffffffffu, mx, 1, 8));
        mx = fmaxf(mx, __shfl_xor_sync(0xffffffffu, mx, 2, 8));
        mx = fmaxf(mx, __shfl_xor_sync(0xffffffffu, mx, 4, 8));
        const bool any = (mx != NI);
        float sum = 0.0f;
#pragma unroll
        for (int j = 0; j < 8; j++) {
            const float e = any ? __expf(lg[j] - mx) : 0.0f;
            lg[j] = e;
            sum += e;
        }
        sum += __shfl_xor_sync(0xffffffffu, sum, 1, 8);
        sum += __shfl_xor_sync(0xffffffffu, sum, 2, 8);
        sum += __shfl_xor_sync(0xffffffffu, sum, 4, 8);
        const float inv = (sum > 0.0f) ? (1.0f / sum) : 0.0f;
#pragma unroll
        for (int j = 0; j < 8; j++)
            at[i][c + j * 8] = lg[j] * inv;
    }
    __syncthreads();

    float4 o0 = make_float4(0, 0, 0, 0), o1 = make_float4(0, 0, 0, 0);
#pragma unroll 8
    for (int n = 0; n < 64; n++) {
        const float a = at[i][n];
        const float4 v0 = *(const float4*)&vs[n][c * 8];
        const float4 v1 = *(const float4*)&vs[n][c * 8 + 4];
        o0.x = fmaf(a, v0.x, o0.x); o0.y = fmaf(a, v0.y, o0.y);
        o0.z = fmaf(a, v0.z, o0.z); o0.w = fmaf(a, v0.w, o0.w);
        o1.x = fmaf(a, v1.x, o1.x); o1.y = fmaf(a, v1.y, o1.y);
        o1.z = fmaf(a, v1.z, o1.z); o1.w = fmaf(a, v1.w, o1.w);
    }
    float ov[8] = {o0.x, o0.y, o0.z, o0.w, o1.x, o1.y, o1.z, o1.w};
    unsigned short hs[8], ls[8];
#pragma unroll
    for (int j = 0; j < 8; j++) {
        __nv_bfloat16 hb = __float2bfloat16(ov[j]);
        hs[j] = __bfloat16_as_ushort(hb);
        ls[j] = __bfloat16_as_ushort(__float2bfloat16(ov[j] - __bfloat162float(hb)));
    }
    uint4 hv, lv;
    hv.x = (uint32_t)hs[0] | ((uint32_t)hs[1] << 16);
    hv.y = (uint32_t)hs[2] | ((uint32_t)hs[3] << 16);
    hv.z = (uint32_t)hs[4] | ((uint32_t)hs[5] << 16);
    hv.w = (uint32_t)hs[6] | ((uint32_t)hs[7] << 16);
    lv.x = (uint32_t)ls[0] | ((uint32_t)ls[1] << 16);
    lv.y = (uint32_t)ls[2] | ((uint32_t)ls[3] << 16);
    lv.z = (uint32_t)ls[4] | ((uint32_t)ls[5] << 16);
    lv.w = (uint32_t)ls[6] | ((uint32_t)ls[7] << 16);
    const size_t base = ((size_t)(b * 16 + i)) * 512 + h * 64 + c * 8;
    *(uint4*)(g_ah + base) = hv;
    *(uint4*)(g_al + base) = lv;
}

// ---------------------------------------------------------------------------
extern "C" void kernel_launch(void* const* d_in, const int* in_sizes, int n_in,
                              void* d_out, int out_size)
{
    const float*        entities  = (const float*)d_in[0];
    const unsigned int* pre_mask  = (const unsigned int*)d_in[1];
    const unsigned int* post_mask = (const unsigned int*)d_in[2];
    const float*        W_in      = (const float*)d_in[3];
    const float*        W_out     = (const float*)d_in[4];
    const float*        b_out     = (const float*)d_in[5];
    float*              out       = (float*)d_out;

    cudaFuncSetAttribute(mma_gemm<0>, cudaFuncAttributeMaxDynamicSharedMemorySize, GSMEM_TOTAL);
    cudaFuncSetAttribute(mma_gemm<1>, cudaFuncAttributeMaxDynamicSharedMemorySize, GSMEM_TOTAL);
    cudaFuncSetAttribute(mma_gemm<2>, cudaFuncAttributeMaxDynamicSharedMemorySize, GSMEM_TOTAL);

    // hi/lo splits
    split_kernel<<<8192, 256>>>(entities, 0, (BS * NE * 512) / 4);
    split_kernel<<<768,  256>>>(W_in,     1, (1536 * 512) / 4);
    split_kernel<<<256,  256>>>(W_out,    2, (512 * 512) / 4);

    // KV projection: M=131072, N=1024
    mma_gemm<0><<<dim3(4, 1024), 512, GSMEM_TOTAL>>>(nullptr, nullptr, nullptr);
    // Q projection: M=32768 (gathered rows), N=512
    mma_gemm<1><<<dim3(2, 256), 512, GSMEM_TOTAL>>>(nullptr, nullptr, nullptr);
    // Attention
    attn_kernel<<<dim3(BS, NHEAD), 128>>>(pre_mask);
    // Output projection + bias + post_mask
    mma_gemm<2><<<dim3(2, 256), 512, GSMEM_TOTAL>>>(out, b_out, post_mask);
}

// round 8
// speedup vs baseline: 1.0332x; 1.0332x over previous
#include <cuda_runtime.h>
#include <cuda_bf16.h>
#include <math.h>
#include <stdint.h>

// Problem constants
#define BS      2048
#define NE      64
#define NQ      16
#define EMBED   512
#define NHEAD   8
#define HD      64

// ---------------------------------------------------------------------------
// Scratch (__device__ globals — allocation-free)
// ---------------------------------------------------------------------------
__device__ __nv_bfloat16 g_eh[(size_t)BS * NE * 512];   // entities hi
__device__ __nv_bfloat16 g_el[(size_t)BS * NE * 512];   // entities lo
__device__ __nv_bfloat16 g_wh[1536 * 512];              // W_in hi
__device__ __nv_bfloat16 g_wl[1536 * 512];              // W_in lo
__device__ __nv_bfloat16 g_oh[512 * 512];               // W_out hi
__device__ __nv_bfloat16 g_ol[512 * 512];               // W_out lo
__device__ float         g_q [(size_t)BS * NQ * 512];   // Q   fp32
__device__ float         g_kv[(size_t)BS * NE * 1024];  // K|V fp32
__device__ __nv_bfloat16 g_ah[(size_t)BS * NQ * 512];   // attn out hi
__device__ __nv_bfloat16 g_al[(size_t)BS * NQ * 512];   // attn out lo

__device__ __forceinline__ float neg_inf() { return __int_as_float(0xff800000u); }

__device__ __forceinline__ uint32_t smem_u32(const void* p) {
    uint32_t a;
    asm("{ .reg .u64 t; cvta.to.shared.u64 t, %1; cvt.u32.u64 %0, t; }" : "=r"(a) : "l"(p));
    return a;
}
#define SW64(bo) ((bo) ^ (((bo) >> 3) & 0x30))

#define CP_ASYNC16(dst, src) \
    asm volatile("cp.async.cg.shared.global [%0], [%1], 16;" :: "r"(dst), "l"(src) : "memory")
#define CP_COMMIT() asm volatile("cp.async.commit_group;" ::: "memory")
#define CP_WAIT1()  asm volatile("cp.async.wait_group 1;" ::: "memory")

#define LDMATRIX_X4(r0, r1, r2, r3, addr) \
    asm volatile("ldmatrix.sync.aligned.m8n8.x4.shared.b16 {%0,%1,%2,%3}, [%4];" \
        : "=r"(r0), "=r"(r1), "=r"(r2), "=r"(r3) : "r"(addr))

#define MMA_BF16(c, a, b) \
    asm volatile("mma.sync.aligned.m16n8k16.row.col.f32.bf16.bf16.f32 " \
        "{%0,%1,%2,%3}, {%4,%5,%6,%7}, {%8,%9}, {%0,%1,%2,%3};" \
        : "+f"((c)[0]), "+f"((c)[1]), "+f"((c)[2]), "+f"((c)[3]) \
        : "r"((a)[0]), "r"((a)[1]), "r"((a)[2]), "r"((a)[3]), "r"((b)[0]), "r"((b)[1]))

// ---------------------------------------------------------------------------
// Split fp32 -> (bf16 hi, bf16 lo).  sel: 0=entities, 1=W_in, 2=W_out
// ---------------------------------------------------------------------------
__global__ void __launch_bounds__(256)
split_kernel(const float* __restrict__ src, int sel, int n4)
{
    __nv_bfloat16 *hi, *lo;
    if (sel == 0)      { hi = g_eh; lo = g_el; }
    else if (sel == 1) { hi = g_wh; lo = g_wl; }
    else               { hi = g_oh; lo = g_ol; }

    for (int i = blockIdx.x * blockDim.x + threadIdx.x; i < n4;
         i += gridDim.x * blockDim.x) {
        const float4 v = ((const float4*)src)[i];
        float f[4] = {v.x, v.y, v.z, v.w};
        unsigned short hs[4], ls[4];
#pragma unroll
        for (int j = 0; j < 4; j++) {
            __nv_bfloat16 hb = __float2bfloat16(f[j]);
            hs[j] = __bfloat16_as_ushort(hb);
            ls[j] = __bfloat16_as_ushort(__float2bfloat16(f[j] - __bfloat162float(hb)));
        }
        uint2 hv, lv;
        hv.x = (uint32_t)hs[0] | ((uint32_t)hs[1] << 16);
        hv.y = (uint32_t)hs[2] | ((uint32_t)hs[3] << 16);
        lv.x = (uint32_t)ls[0] | ((uint32_t)ls[1] << 16);
        lv.y = (uint32_t)ls[2] | ((uint32_t)ls[3] << 16);
        ((uint2*)hi)[i] = hv;
        ((uint2*)lo)[i] = lv;
    }
}

// ---------------------------------------------------------------------------
// mma.sync bf16x3 GEMM, 2 CTAs/SM:
// C[m,n] = sum_d A[m,d]*B[n,d], terms Ah*Bh + Ah*Bl + Al*Bh (fp32 accum).
// CTA tile 128x128, 256 threads (8 warps: 2M x 4N), warp tile 64x32.
// BK=32 (64B rows, SW64). Stage 32KB: Ah 8K|Al 8K|Bh 8K|Bl 8K.
// 3 stages (96KB/CTA) -> 2 CTAs/SM; their barrier bubbles interleave.
// Schedule: wait(1) -> bar -> issue(t+2) -> compute(t). 16 chunks.
// MODE 0: KV proj (C=g_kv, ldc=1024)  MODE 1: Q proj (gathered A rows)
// MODE 2: out proj (bias + post_mask)
// ---------------------------------------------------------------------------
#define STAGE_BYTES 32768
#define OFF_AL      8192
#define OFF_BH      16384
#define OFF_BL      24576
#define GSMEM_TOTAL (3 * STAGE_BYTES)
#define NCHUNK      16

template <int MODE>
__global__ void __launch_bounds__(256, 2)
mma_gemm(float* __restrict__ Cout,
         const float* __restrict__ bias,
         const unsigned int* __restrict__ mask)
{
    extern __shared__ char smem[];
    const uint32_t sb = smem_u32(smem);
    const int tid  = threadIdx.x;
    const int wid  = tid >> 5;
    const int lane = tid & 31;
    const int wm   = wid >> 2;         // 0..1  (M)
    const int wn   = wid & 3;          // 0..3  (N)
    const int row0 = blockIdx.y * 128;
    const int col0 = blockIdx.x * 128;

    const __nv_bfloat16 *Ahp, *Alp, *Bhp, *Blp;
    if (MODE == 0)      { Ahp = g_eh; Alp = g_el; Bhp = g_wh + 512 * 512; Blp = g_wl + 512 * 512; }
    else if (MODE == 1) { Ahp = g_eh; Alp = g_el; Bhp = g_wh;             Blp = g_wl; }
    else                { Ahp = g_ah; Alp = g_al; Bhp = g_oh;             Blp = g_ol; }
    float* C = (MODE == 0) ? g_kv : (MODE == 1) ? g_q : Cout;
    const int ldc = (MODE == 0) ? 1024 : 512;

    float acc[4][4][4];
#pragma unroll
    for (int i = 0; i < 4; i++)
#pragma unroll
        for (int j = 0; j < 4; j++)
#pragma unroll
            for (int k = 0; k < 4; k++) acc[i][j][k] = 0.0f;

    // ---- async loader: k-chunk t (BK=32) into stage t%3 ----
    auto issue_load = [&](int t) {
        const int kc = t * 32;
        const uint32_t st = sb + (uint32_t)(t % 3) * STAGE_BYTES;
#pragma unroll
        for (int i = 0; i < 2; i++) {   // 128 rows x 4 x 16B per array, 2/thread
            const int u = tid + i * 256;
            const int r = u >> 2, c = u & 3;
            const uint32_t sw = SW64((uint32_t)(r * 64 + c * 16));
            const int gr = row0 + r;
            const int ar = (MODE == 1) ? (((gr >> 4) << 6) + (gr & 15)) : gr;
            CP_ASYNC16(st + sw,          Ahp + (size_t)ar * 512 + kc + c * 8);
            CP_ASYNC16(st + OFF_AL + sw, Alp + (size_t)ar * 512 + kc + c * 8);
            CP_ASYNC16(st + OFF_BH + sw, Bhp + (size_t)(col0 + r) * 512 + kc + c * 8);
            CP_ASYNC16(st + OFF_BL + sw, Blp + (size_t)(col0 + r) * 512 + kc + c * 8);
        }
        CP_COMMIT();
    };

    issue_load(0);
    issue_load(1);

    const int l8   = lane & 7;
    const int lsel = lane >> 3;                      // 0..3 (ldmatrix quad)

    for (int t = 0; t < NCHUNK; t++) {
        CP_WAIT1();                                  // chunk t landed
        __syncthreads();                             // publish + free stage (t+2)%3
        if (t + 2 < NCHUNK) issue_load(t + 2);
        else                CP_COMMIT();             // keep group count aligned

        const uint32_t st = sb + (uint32_t)(t % 3) * STAGE_BYTES;

#pragma unroll
        for (int ks = 0; ks < 2; ks++) {             // 2 x k16 per chunk
            const int ra = wm * 64 + l8 + (lsel & 1) * 8;
            const int ca = ks * 2 + (lsel >> 1);     // 16B col 0..3
            const int rb = wn * 32 + (lsel >> 1) * 8 + l8;
            const int cb = ks * 2 + (lsel & 1);

            uint32_t ah[4][4], al[4][4], bh[4][2], bl[4][2];
#pragma unroll
            for (int am = 0; am < 4; am++) {
                const int r = ra + am * 16;
                const uint32_t off = SW64((uint32_t)(r * 64 + ca * 16));
                LDMATRIX_X4(ah[am][0], ah[am][1], ah[am][2], ah[am][3], st + off);
            }
#pragma unroll
            for (int bp = 0; bp < 2; bp++) {
                const int r = rb + bp * 16;
                const uint32_t off = SW64((uint32_t)(r * 64 + cb * 16));
                LDMATRIX_X4(bh[2 * bp][0], bh[2 * bp][1], bh[2 * bp + 1][0], bh[2 * bp + 1][1],
                            st + OFF_BH + off);
            }
            // term 0: Ah * Bh
#pragma unroll
            for (int am = 0; am < 4; am++)
#pragma unroll
                for (int nt = 0; nt < 4; nt++)
                    MMA_BF16(acc[am][nt], ah[am], bh[nt]);
            // term 1: Ah * Bl
#pragma unroll
            for (int bp = 0; bp < 2; bp++) {
                const int r = rb + bp * 16;
                const uint32_t off = SW64((uint32_t)(r * 64 + cb * 16));
                LDMATRIX_X4(bl[2 * bp][0], bl[2 * bp][1], bl[2 * bp + 1][0], bl[2 * bp + 1][1],
                            st + OFF_BL + off);
            }
#pragma unroll
            for (int am = 0; am < 4; am++)
#pragma unroll
                for (int nt = 0; nt < 4; nt++)
                    MMA_BF16(acc[am][nt], ah[am], bl[nt]);
            // term 2: Al * Bh
#pragma unroll
            for (int am = 0; am < 4; am++) {
                const int r = ra + am * 16;
                const uint32_t off = SW64((uint32_t)(r * 64 + ca * 16));
                LDMATRIX_X4(al[am][0], al[am][1], al[am][2], al[am][3], st + OFF_AL + off);
            }
#pragma unroll
            for (int am = 0; am < 4; am++)
#pragma unroll
                for (int nt = 0; nt < 4; nt++)
                    MMA_BF16(acc[am][nt], al[am], bh[nt]);
        }
    }

    // ---- epilogue: warp tile 64x32, frag (g,tg) layout ----
    const int g  = lane >> 2;
    const int tg = lane & 3;
#pragma unroll
    for (int am = 0; am < 4; am++) {
        const int r0 = row0 + wm * 64 + am * 16 + g;
        const int r1 = r0 + 8;
        bool z0 = false, z1 = false;
        if (MODE == 2) { z0 = (mask[r0] != 0u); z1 = (mask[r1] != 0u); }
#pragma unroll
        for (int nt = 0; nt < 4; nt++) {
            const int col = col0 + wn * 32 + nt * 8 + tg * 2;
            float2 v0 = make_float2(acc[am][nt][0], acc[am][nt][1]);
            float2 v1 = make_float2(acc[am][nt][2], acc[am][nt][3]);
            if (MODE == 2) {
                const float bb0 = bias[col], bb1 = bias[col + 1];
                v0.x = z0 ? 0.0f : v0.x + bb0;  v0.y = z0 ? 0.0f : v0.y + bb1;
                v1.x = z1 ? 0.0f : v1.x + bb0;  v1.y = z1 ? 0.0f : v1.y + bb1;
            }
            *(float2*)(C + (size_t)r0 * ldc + col) = v0;
            *(float2*)(C + (size_t)r1 * ldc + col) = v1;
        }
    }
}

// ---------------------------------------------------------------------------
// Attention: one block per (batch, head). 128 threads. Emits bf16 hi/lo.
// ---------------------------------------------------------------------------
__global__ void __launch_bounds__(128)
attn_kernel(const unsigned int* __restrict__ pre_mask)
{
    __shared__ float qs[16][68];
    __shared__ float ks[64][68];
    __shared__ float vs[64][68];
    __shared__ float at[16][68];

    const int b = blockIdx.x;
    const int h = blockIdx.y;
    const int tid = threadIdx.x;

#pragma unroll
    for (int rep = 0; rep < 2; rep++) {
        const int uu = tid + rep * 128;
        const int i = uu >> 4, d4 = uu & 15;
        *(float4*)&qs[i][d4 * 4] =
            *(const float4*)(g_q + ((size_t)(b * 16 + i)) * 512 + h * 64 + d4 * 4);
    }
#pragma unroll
    for (int rep = 0; rep < 8; rep++) {
        const int uu = tid + rep * 128;
        const int n = uu >> 4, d4 = uu & 15;
        const size_t base = ((size_t)(b * 64 + n)) * 1024 + h * 64 + d4 * 4;
        *(float4*)&ks[n][d4 * 4] = *(const float4*)(g_kv + base);
        *(float4*)&vs[n][d4 * 4] = *(const float4*)(g_kv + base + 512);
    }
    __syncthreads();

    const int i = tid >> 3;
    const int c = tid & 7;
    const unsigned int* pm = pre_mask + ((size_t)b * 64 + i) * 64;

    float lg[8];
    {
        float dacc[8] = {0, 0, 0, 0, 0, 0, 0, 0};
        for (int d4 = 0; d4 < 16; d4++) {
            const float4 q = *(const float4*)&qs[i][d4 * 4];
#pragma unroll
            for (int j = 0; j < 8; j++) {
                const float4 kv = *(const float4*)&ks[c + j * 8][d4 * 4];
                dacc[j] = fmaf(q.x, kv.x, dacc[j]);
                dacc[j] = fmaf(q.y, kv.y, dacc[j]);
                dacc[j] = fmaf(q.z, kv.z, dacc[j]);
                dacc[j] = fmaf(q.w, kv.w, dacc[j]);
            }
        }
        const float NI = neg_inf();
        float mx = NI;
#pragma unroll
        for (int j = 0; j < 8; j++) {
            lg[j] = (pm[c + j * 8] != 0u) ? NI : dacc[j] * 0.125f;
            mx = fmaxf(mx, lg[j]);
        }
        mx = fmaxf(mx, __shfl_xor_sync(0xffffffffu, mx, 1, 8));
        mx = fmaxf(mx, __shfl_xor_sync(0xffffffffu, mx, 2, 8));
        mx = fmaxf(mx, __shfl_xor_sync(0xffffffffu, mx, 4, 8));
        const bool any = (mx != NI);
        float sum = 0.0f;
#pragma unroll
        for (int j = 0; j < 8; j++) {
            const float e = any ? __expf(lg[j] - mx) : 0.0f;
            lg[j] = e;
            sum += e;
        }
        sum += __shfl_xor_sync(0xffffffffu, sum, 1, 8);
        sum += __shfl_xor_sync(0xffffffffu, sum, 2, 8);
        sum += __shfl_xor_sync(0xffffffffu, sum, 4, 8);
        const float inv = (sum > 0.0f) ? (1.0f / sum) : 0.0f;
#pragma unroll
        for (int j = 0; j < 8; j++)
            at[i][c + j * 8] = lg[j] * inv;
    }
    __syncthreads();

    float4 o0 = make_float4(0, 0, 0, 0), o1 = make_float4(0, 0, 0, 0);
#pragma unroll 8
    for (int n = 0; n < 64; n++) {
        const float a = at[i][n];
        const float4 v0 = *(const float4*)&vs[n][c * 8];
        const float4 v1 = *(const float4*)&vs[n][c * 8 + 4];
        o0.x = fmaf(a, v0.x, o0.x); o0.y = fmaf(a, v0.y, o0.y);
        o0.z = fmaf(a, v0.z, o0.z); o0.w = fmaf(a, v0.w, o0.w);
        o1.x = fmaf(a, v1.x, o1.x); o1.y = fmaf(a, v1.y, o1.y);
        o1.z = fmaf(a, v1.z, o1.z); o1.w = fmaf(a, v1.w, o1.w);
    }
    float ov[8] = {o0.x, o0.y, o0.z, o0.w, o1.x, o1.y, o1.z, o1.w};
    unsigned short hs[8], ls[8];
#pragma unroll
    for (int j = 0; j < 8; j++) {
        __nv_bfloat16 hb = __float2bfloat16(ov[j]);
        hs[j] = __bfloat16_as_ushort(hb);
        ls[j] = __bfloat16_as_ushort(__float2bfloat16(ov[j] - __bfloat162float(hb)));
    }
    uint4 hv, lv;
    hv.x = (uint32_t)hs[0] | ((uint32_t)hs[1] << 16);
    hv.y = (uint32_t)hs[2] | ((uint32_t)hs[3] << 16);
    hv.z = (uint32_t)hs[4] | ((uint32_t)hs[5] << 16);
    hv.w = (uint32_t)hs[6] | ((uint32_t)hs[7] << 16);
    lv.x = (uint32_t)ls[0] | ((uint32_t)ls[1] << 16);
    lv.y = (uint32_t)ls[2] | ((uint32_t)ls[3] << 16);
    lv.z = (uint32_t)ls[4] | ((uint32_t)ls[5] << 16);
    lv.w = (uint32_t)ls[6] | ((uint32_t)ls[7] << 16);
    const size_t base = ((size_t)(b * 16 + i)) * 512 + h * 64 + c * 8;
    *(uint4*)(g_ah + base) = hv;
    *(uint4*)(g_al + base) = lv;
}

// ---------------------------------------------------------------------------
extern "C" void kernel_launch(void* const* d_in, const int* in_sizes, int n_in,
                              void* d_out, int out_size)
{
    const float*        entities  = (const float*)d_in[0];
    const unsigned int* pre_mask  = (const unsigned int*)d_in[1];
    const unsigned int* post_mask = (const unsigned int*)d_in[2];
    const float*        W_in      = (const float*)d_in[3];
    const float*        W_out     = (const float*)d_in[4];
    const float*        b_out     = (const float*)d_in[5];
    float*              out       = (float*)d_out;

    cudaFuncSetAttribute(mma_gemm<0>, cudaFuncAttributeMaxDynamicSharedMemorySize, GSMEM_TOTAL);
    cudaFuncSetAttribute(mma_gemm<1>, cudaFuncAttributeMaxDynamicSharedMemorySize, GSMEM_TOTAL);
    cudaFuncSetAttribute(mma_gemm<2>, cudaFuncAttributeMaxDynamicSharedMemorySize, GSMEM_TOTAL);

    // hi/lo splits
    split_kernel<<<8192, 256>>>(entities, 0, (BS * NE * 512) / 4);
    split_kernel<<<768,  256>>>(W_in,     1, (1536 * 512) / 4);
    split_kernel<<<256,  256>>>(W_out,    2, (512 * 512) / 4);

    // KV projection: M=131072, N=1024
    mma_gemm<0><<<dim3(8, 1024), 256, GSMEM_TOTAL>>>(nullptr, nullptr, nullptr);
    // Q projection: M=32768 (gathered rows), N=512
    mma_gemm<1><<<dim3(4, 256), 256, GSMEM_TOTAL>>>(nullptr, nullptr, nullptr);
    // Attention
    attn_kernel<<<dim3(BS, NHEAD), 128>>>(pre_mask);
    // Output projection + bias + post_mask
    mma_gemm<2><<<dim3(4, 256), 256, GSMEM_TOTAL>>>(out, b_out, post_mask);
}

// round 9
// speedup vs baseline: 1.0433x; 1.0098x over previous
#include <cuda_runtime.h>
#include <cuda_bf16.h>
#include <math.h>
#include <stdint.h>

// Problem constants
#define BS      2048
#define NE      64
#define NQ      16
#define EMBED   512
#define NHEAD   8
#define HD      64

// ---------------------------------------------------------------------------
// Scratch (__device__ globals — allocation-free)
// ---------------------------------------------------------------------------
__device__ __nv_bfloat16 g_eh[(size_t)BS * NE * 512];   // entities hi
__device__ __nv_bfloat16 g_el[(size_t)BS * NE * 512];   // entities lo
__device__ __nv_bfloat16 g_wh[1536 * 512];              // W_in hi
__device__ __nv_bfloat16 g_wl[1536 * 512];              // W_in lo
__device__ __nv_bfloat16 g_oh[512 * 512];               // W_out hi
__device__ __nv_bfloat16 g_ol[512 * 512];               // W_out lo
__device__ float         g_q [(size_t)BS * NQ * 512];   // Q   fp32
__device__ float         g_kv[(size_t)BS * NE * 1024];  // K|V fp32
__device__ __nv_bfloat16 g_ah[(size_t)BS * NQ * 512];   // attn out hi
__device__ __nv_bfloat16 g_al[(size_t)BS * NQ * 512];   // attn out lo

__device__ __forceinline__ float neg_inf() { return __int_as_float(0xff800000u); }

__device__ __forceinline__ uint32_t smem_u32(const void* p) {
    uint32_t a;
    asm("{ .reg .u64 t; cvta.to.shared.u64 t, %1; cvt.u32.u64 %0, t; }" : "=r"(a) : "l"(p));
    return a;
}
#define SW128(bo) ((bo) ^ (((bo) >> 3) & 0x70))

#define CP_ASYNC16(dst, src) \
    asm volatile("cp.async.cg.shared.global [%0], [%1], 16;" :: "r"(dst), "l"(src) : "memory")
#define CP_COMMIT() asm volatile("cp.async.commit_group;" ::: "memory")
#define CP_WAIT1()  asm volatile("cp.async.wait_group 1;" ::: "memory")

#define LDMATRIX_X4(r0, r1, r2, r3, addr) \
    asm volatile("ldmatrix.sync.aligned.m8n8.x4.shared.b16 {%0,%1,%2,%3}, [%4];" \
        : "=r"(r0), "=r"(r1), "=r"(r2), "=r"(r3) : "r"(addr))

#define MMA_BF16(c, a, b) \
    asm volatile("mma.sync.aligned.m16n8k16.row.col.f32.bf16.bf16.f32 " \
        "{%0,%1,%2,%3}, {%4,%5,%6,%7}, {%8,%9}, {%0,%1,%2,%3};" \
        : "+f"((c)[0]), "+f"((c)[1]), "+f"((c)[2]), "+f"((c)[3]) \
        : "r"((a)[0]), "r"((a)[1]), "r"((a)[2]), "r"((a)[3]), "r"((b)[0]), "r"((b)[1]))

// ---------------------------------------------------------------------------
// Split fp32 -> (bf16 hi, bf16 lo).  sel: 0=entities, 1=W_in, 2=W_out
// ---------------------------------------------------------------------------
__global__ void __launch_bounds__(256)
split_kernel(const float* __restrict__ src, int sel, int n4)
{
    __nv_bfloat16 *hi, *lo;
    if (sel == 0)      { hi = g_eh; lo = g_el; }
    else if (sel == 1) { hi = g_wh; lo = g_wl; }
    else               { hi = g_oh; lo = g_ol; }

    for (int i = blockIdx.x * blockDim.x + threadIdx.x; i < n4;
         i += gridDim.x * blockDim.x) {
        const float4 v = ((const float4*)src)[i];
        float f[4] = {v.x, v.y, v.z, v.w};
        unsigned short hs[4], ls[4];
#pragma unroll
        for (int j = 0; j < 4; j++) {
            __nv_bfloat16 hb = __float2bfloat16(f[j]);
            hs[j] = __bfloat16_as_ushort(hb);
            ls[j] = __bfloat16_as_ushort(__float2bfloat16(f[j] - __bfloat162float(hb)));
        }
        uint2 hv, lv;
        hv.x = (uint32_t)hs[0] | ((uint32_t)hs[1] << 16);
        hv.y = (uint32_t)hs[2] | ((uint32_t)hs[3] << 16);
        lv.x = (uint32_t)ls[0] | ((uint32_t)ls[1] << 16);
        lv.y = (uint32_t)ls[2] | ((uint32_t)ls[3] << 16);
        ((uint2*)hi)[i] = hv;
        ((uint2*)lo)[i] = lv;
    }
}

// ---------------------------------------------------------------------------
// mma.sync bf16x3 GEMM, asymmetric pipeline:
// C[m,n] = sum_d A[m,d]*B[n,d], terms Ah*Bh + Ah*Bl + Al*Bh (fp32 accum).
// CTA tile 128x256, 512 threads (16 warps: 2M x 8N), warp tile 64x32.
// BK=64 (128B rows, SW128). A (streaming, DRAM): 3 stages x 32KB (depth 2).
// B (weights, L2-hot): 2 stages x 64KB (depth 1). Total 224KB smem.
// One __syncthreads per chunk. Commit order B-then-A so wait_group(1)
// completes {A(t), B(t)} leaving exactly A(t+1) in flight.
// MODE 0: KV proj (C=g_kv, ldc=1024)  MODE 1: Q proj (gathered A rows)
// MODE 2: out proj (bias + post_mask)
// ---------------------------------------------------------------------------
#define A_STAGE  32768                 // Ah 16K | Al 16K
#define B_STAGE  65536                 // Bh 32K | Bl 32K
#define OFF_AL   16384
#define OFF_BL   32768
#define B_BASE   (3 * A_STAGE)         // 98304
#define GSMEM_TOTAL (B_BASE + 2 * B_STAGE)   // 229376 = 224KB
#define NITER 8

template <int MODE>
__global__ void __launch_bounds__(512, 1)
mma_gemm(float* __restrict__ Cout,
         const float* __restrict__ bias,
         const unsigned int* __restrict__ mask)
{
    extern __shared__ char smem[];
    const uint32_t sb = smem_u32(smem);
    const int tid  = threadIdx.x;
    const int wid  = tid >> 5;
    const int lane = tid & 31;
    const int wm   = wid & 1;          // 0..1  (M)
    const int wn   = wid >> 1;         // 0..7  (N)
    const int row0 = blockIdx.y * 128;
    const int col0 = blockIdx.x * 256;

    const __nv_bfloat16 *Ahp, *Alp, *Bhp, *Blp;
    if (MODE == 0)      { Ahp = g_eh; Alp = g_el; Bhp = g_wh + 512 * 512; Blp = g_wl + 512 * 512; }
    else if (MODE == 1) { Ahp = g_eh; Alp = g_el; Bhp = g_wh;             Blp = g_wl; }
    else                { Ahp = g_ah; Alp = g_al; Bhp = g_oh;             Blp = g_ol; }
    float* C = (MODE == 0) ? g_kv : (MODE == 1) ? g_q : Cout;
    const int ldc = (MODE == 0) ? 1024 : 512;

    float acc[4][4][4];
#pragma unroll
    for (int i = 0; i < 4; i++)
#pragma unroll
        for (int j = 0; j < 4; j++)
#pragma unroll
            for (int k = 0; k < 4; k++) acc[i][j][k] = 0.0f;

    // ---- A loader: chunk t (BK=64) into A-stage t%3 ----
    auto issue_A = [&](int t) {
        if (t < NITER) {
            const int kc = t * 64;
            const uint32_t st = sb + (uint32_t)(t % 3) * A_STAGE;
#pragma unroll
            for (int i = 0; i < 2; i++) {        // 128 rows x 8 x 16B
                const int u = tid + i * 512;
                const int r = u >> 3, c = u & 7;
                const int gr = row0 + r;
                const int ar = (MODE == 1) ? (((gr >> 4) << 6) + (gr & 15)) : gr;
                const uint32_t sw = SW128((uint32_t)(r * 128 + c * 16));
                CP_ASYNC16(st + sw,          Ahp + (size_t)ar * 512 + kc + c * 8);
                CP_ASYNC16(st + OFF_AL + sw, Alp + (size_t)ar * 512 + kc + c * 8);
            }
        }
        CP_COMMIT();                             // empty group keeps count exact
    };
    // ---- B loader: chunk t into B-stage t%2 ----
    auto issue_B = [&](int t) {
        if (t < NITER) {
            const int kc = t * 64;
            const uint32_t st = sb + B_BASE + (uint32_t)(t & 1) * B_STAGE;
#pragma unroll
            for (int i = 0; i < 4; i++) {        // 256 rows x 8 x 16B
                const int u = tid + i * 512;
                const int r = u >> 3, c = u & 7;
                const uint32_t sw = SW128((uint32_t)(r * 128 + c * 16));
                CP_ASYNC16(st + sw,          Bhp + (size_t)(col0 + r) * 512 + kc + c * 8);
                CP_ASYNC16(st + OFF_BL + sw, Blp + (size_t)(col0 + r) * 512 + kc + c * 8);
            }
        }
        CP_COMMIT();
    };

    // prologue: pending groups [A0, B0, A1]
    issue_A(0);
    issue_B(0);
    issue_A(1);

    const int l8   = lane & 7;
    const int lsel = lane >> 3;                  // 0..3 (ldmatrix quad)

    for (int t = 0; t < NITER; t++) {
        CP_WAIT1();                              // A(t), B(t) done; A(t+1) in flight
        __syncthreads();                         // all warps past compute(t-1): stages free
        issue_B(t + 1);                          // B first, then A (retirement order)
        issue_A(t + 2);

        const uint32_t stA = sb + (uint32_t)(t % 3) * A_STAGE;
        const uint32_t stB = sb + B_BASE + (uint32_t)(t & 1) * B_STAGE;

#pragma unroll
        for (int ks = 0; ks < 4; ks++) {         // 4 x k16 per chunk
            const int ra = wm * 64 + l8 + (lsel & 1) * 8;
            const int ca = ks * 2 + (lsel >> 1);
            const int rb = wn * 32 + (lsel >> 1) * 8 + l8;
            const int cb = ks * 2 + (lsel & 1);

            uint32_t ah[4][4], al[4][4], bh[4][2], bl[4][2];
#pragma unroll
            for (int am = 0; am < 4; am++) {
                const int r = ra + am * 16;
                const uint32_t off = (uint32_t)(r * 128 + ((ca ^ (r & 7)) << 4));
                LDMATRIX_X4(ah[am][0], ah[am][1], ah[am][2], ah[am][3], stA + off);
            }
#pragma unroll
            for (int bp = 0; bp < 2; bp++) {
                const int r = rb + bp * 16;
                const uint32_t off = (uint32_t)(r * 128 + ((cb ^ (r & 7)) << 4));
                LDMATRIX_X4(bh[2 * bp][0], bh[2 * bp][1], bh[2 * bp + 1][0], bh[2 * bp + 1][1],
                            stB + off);
            }
            // term 0: Ah * Bh
#pragma unroll
            for (int am = 0; am < 4; am++)
#pragma unroll
                for (int nt = 0; nt < 4; nt++)
                    MMA_BF16(acc[am][nt], ah[am], bh[nt]);
            // term 1: Ah * Bl
#pragma unroll
            for (int bp = 0; bp < 2; bp++) {
                const int r = rb + bp * 16;
                const uint32_t off = (uint32_t)(r * 128 + ((cb ^ (r & 7)) << 4));
                LDMATRIX_X4(bl[2 * bp][0], bl[2 * bp][1], bl[2 * bp + 1][0], bl[2 * bp + 1][1],
                            stB + OFF_BL + off);
            }
#pragma unroll
            for (int am = 0; am < 4; am++)
#pragma unroll
                for (int nt = 0; nt < 4; nt++)
                    MMA_BF16(acc[am][nt], ah[am], bl[nt]);
            // term 2: Al * Bh
#pragma unroll
            for (int am = 0; am < 4; am++) {
                const int r = ra + am * 16;
                const uint32_t off = (uint32_t)(r * 128 + ((ca ^ (r & 7)) << 4));
                LDMATRIX_X4(al[am][0], al[am][1], al[am][2], al[am][3], stA + OFF_AL + off);
            }
#pragma unroll
            for (int am = 0; am < 4; am++)
#pragma unroll
                for (int nt = 0; nt < 4; nt++)
                    MMA_BF16(acc[am][nt], al[am], bh[nt]);
        }
    }

    // ---- epilogue: warp tile 64x32, frag (g,tg) layout ----
    const int g  = lane >> 2;
    const int tg = lane & 3;
#pragma unroll
    for (int am = 0; am < 4; am++) {
        const int r0 = row0 + wm * 64 + am * 16 + g;
        const int r1 = r0 + 8;
        bool z0 = false, z1 = false;
        if (MODE == 2) { z0 = (mask[r0] != 0u); z1 = (mask[r1] != 0u); }
#pragma unroll
        for (int nt = 0; nt < 4; nt++) {
            const int col = col0 + wn * 32 + nt * 8 + tg * 2;
            float2 v0 = make_float2(acc[am][nt][0], acc[am][nt][1]);
            float2 v1 = make_float2(acc[am][nt][2], acc[am][nt][3]);
            if (MODE == 2) {
                const float bb0 = bias[col], bb1 = bias[col + 1];
                v0.x = z0 ? 0.0f : v0.x + bb0;  v0.y = z0 ? 0.0f : v0.y + bb1;
                v1.x = z1 ? 0.0f : v1.x + bb0;  v1.y = z1 ? 0.0f : v1.y + bb1;
            }
            *(float2*)(C + (size_t)r0 * ldc + col) = v0;
            *(float2*)(C + (size_t)r1 * ldc + col) = v1;
        }
    }
}

// ---------------------------------------------------------------------------
// Attention: one block per (batch, head). 128 threads. Emits bf16 hi/lo.
// ---------------------------------------------------------------------------
__global__ void __launch_bounds__(128)
attn_kernel(const unsigned int* __restrict__ pre_mask)
{
    __shared__ float qs[16][68];
    __shared__ float ks[64][68];
    __shared__ float vs[64][68];
    __shared__ float at[16][68];

    const int b = blockIdx.x;
    const int h = blockIdx.y;
    const int tid = threadIdx.x;

#pragma unroll
    for (int rep = 0; rep < 2; rep++) {
        const int uu = tid + rep * 128;
        const int i = uu >> 4, d4 = uu & 15;
        *(float4*)&qs[i][d4 * 4] =
            *(const float4*)(g_q + ((size_t)(b * 16 + i)) * 512 + h * 64 + d4 * 4);
    }
#pragma unroll
    for (int rep = 0; rep < 8; rep++) {
        const int uu = tid + rep * 128;
        const int n = uu >> 4, d4 = uu & 15;
        const size_t base = ((size_t)(b * 64 + n)) * 1024 + h * 64 + d4 * 4;
        *(float4*)&ks[n][d4 * 4] = *(const float4*)(g_kv + base);
        *(float4*)&vs[n][d4 * 4] = *(const float4*)(g_kv + base + 512);
    }
    __syncthreads();

    const int i = tid >> 3;
    const int c = tid & 7;
    const unsigned int* pm = pre_mask + ((size_t)b * 64 + i) * 64;

    float lg[8];
    {
        float dacc[8] = {0, 0, 0, 0, 0, 0, 0, 0};
        for (int d4 = 0; d4 < 16; d4++) {
            const float4 q = *(const float4*)&qs[i][d4 * 4];
#pragma unroll
            for (int j = 0; j < 8; j++) {
                const float4 kv = *(const float4*)&ks[c + j * 8][d4 * 4];
                dacc[j] = fmaf(q.x, kv.x, dacc[j]);
                dacc[j] = fmaf(q.y, kv.y, dacc[j]);
                dacc[j] = fmaf(q.z, kv.z, dacc[j]);
                dacc[j] = fmaf(q.w, kv.w, dacc[j]);
            }
        }
        const float NI = neg_inf();
        float mx = NI;
#pragma unroll
        for (int j = 0; j < 8; j++) {
            lg[j] = (pm[c + j * 8] != 0u) ? NI : dacc[j] * 0.125f;
            mx = fmaxf(mx, lg[j]);
        }
        mx = fmaxf(mx, __shfl_xor_sync(0xffffffffu, mx, 1, 8));
        mx = fmaxf(mx, __shfl_xor_sync(0xffffffffu, mx, 2, 8));
        mx = fmaxf(mx, __shfl_xor_sync(0xffffffffu, mx, 4, 8));
        const bool any = (mx != NI);
        float sum = 0.0f;
#pragma unroll
        for (int j = 0; j < 8; j++) {
            const float e = any ? __expf(lg[j] - mx) : 0.0f;
            lg[j] = e;
            sum += e;
        }
        sum += __shfl_xor_sync(0xffffffffu, sum, 1, 8);
        sum += __shfl_xor_sync(0xffffffffu, sum, 2, 8);
        sum += __shfl_xor_sync(0xffffffffu, sum, 4, 8);
        const float inv = (sum > 0.0f) ? (1.0f / sum) : 0.0f;
#pragma unroll
        for (int j = 0; j < 8; j++)
            at[i][c + j * 8] = lg[j] * inv;
    }
    __syncthreads();

    float4 o0 = make_float4(0, 0, 0, 0), o1 = make_float4(0, 0, 0, 0);
#pragma unroll 8
    for (int n = 0; n < 64; n++) {
        const float a = at[i][n];
        const float4 v0 = *(const float4*)&vs[n][c * 8];
        const float4 v1 = *(const float4*)&vs[n][c * 8 + 4];
        o0.x = fmaf(a, v0.x, o0.x); o0.y = fmaf(a, v0.y, o0.y);
        o0.z = fmaf(a, v0.z, o0.z); o0.w = fmaf(a, v0.w, o0.w);
        o1.x = fmaf(a, v1.x, o1.x); o1.y = fmaf(a, v1.y, o1.y);
        o1.z = fmaf(a, v1.z, o1.z); o1.w = fmaf(a, v1.w, o1.w);
    }
    float ov[8] = {o0.x, o0.y, o0.z, o0.w, o1.x, o1.y, o1.z, o1.w};
    unsigned short hs[8], ls[8];
#pragma unroll
    for (int j = 0; j < 8; j++) {
        __nv_bfloat16 hb = __float2bfloat16(ov[j]);
        hs[j] = __bfloat16_as_ushort(hb);
        ls[j] = __bfloat16_as_ushort(__float2bfloat16(ov[j] - __bfloat162float(hb)));
    }
    uint4 hv, lv;
    hv.x = (uint32_t)hs[0] | ((uint32_t)hs[1] << 16);
    hv.y = (uint32_t)hs[2] | ((uint32_t)hs[3] << 16);
    hv.z = (uint32_t)hs[4] | ((uint32_t)hs[5] << 16);
    hv.w = (uint32_t)hs[6] | ((uint32_t)hs[7] << 16);
    lv.x = (uint32_t)ls[0] | ((uint32_t)ls[1] << 16);
    lv.y = (uint32_t)ls[2] | ((uint32_t)ls[3] << 16);
    lv.z = (uint32_t)ls[4] | ((uint32_t)ls[5] << 16);
    lv.w = (uint32_t)ls[6] | ((uint32_t)ls[7] << 16);
    const size_t base = ((size_t)(b * 16 + i)) * 512 + h * 64 + c * 8;
    *(uint4*)(g_ah + base) = hv;
    *(uint4*)(g_al + base) = lv;
}

// ---------------------------------------------------------------------------
extern "C" void kernel_launch(void* const* d_in, const int* in_sizes, int n_in,
                              void* d_out, int out_size)
{
    const float*        entities  = (const float*)d_in[0];
    const unsigned int* pre_mask  = (const unsigned int*)d_in[1];
    const unsigned int* post_mask = (const unsigned int*)d_in[2];
    const float*        W_in      = (const float*)d_in[3];
    const float*        W_out     = (const float*)d_in[4];
    const float*        b_out     = (const float*)d_in[5];
    float*              out       = (float*)d_out;

    cudaFuncSetAttribute(mma_gemm<0>, cudaFuncAttributeMaxDynamicSharedMemorySize, GSMEM_TOTAL);
    cudaFuncSetAttribute(mma_gemm<1>, cudaFuncAttributeMaxDynamicSharedMemorySize, GSMEM_TOTAL);
    cudaFuncSetAttribute(mma_gemm<2>, cudaFuncAttributeMaxDynamicSharedMemorySize, GSMEM_TOTAL);

    // hi/lo splits
    split_kernel<<<8192, 256>>>(entities, 0, (BS * NE * 512) / 4);
    split_kernel<<<768,  256>>>(W_in,     1, (1536 * 512) / 4);
    split_kernel<<<256,  256>>>(W_out,    2, (512 * 512) / 4);

    // KV projection: M=131072, N=1024
    mma_gemm<0><<<dim3(4, 1024), 512, GSMEM_TOTAL>>>(nullptr, nullptr, nullptr);
    // Q projection: M=32768 (gathered rows), N=512
    mma_gemm<1><<<dim3(2, 256), 512, GSMEM_TOTAL>>>(nullptr, nullptr, nullptr);
    // Attention
    attn_kernel<<<dim3(BS, NHEAD), 128>>>(pre_mask);
    // Output projection + bias + post_mask
    mma_gemm<2><<<dim3(2, 256), 512, GSMEM_TOTAL>>>(out, b_out, post_mask);
}

// round 10
// speedup vs baseline: 1.0528x; 1.0091x over previous
#include <cuda_runtime.h>
#include <cuda_bf16.h>
#include <math.h>
#include <stdint.h>

// Problem constants
#define BS      2048
#define NE      64
#define NQ      16
#define EMBED   512
#define NHEAD   8
#define HD      64

// ---------------------------------------------------------------------------
// Scratch (__device__ globals — allocation-free)
// ---------------------------------------------------------------------------
__device__ __nv_bfloat16 g_eh[(size_t)BS * NE * 512];   // entities hi
__device__ __nv_bfloat16 g_el[(size_t)BS * NE * 512];   // entities lo
__device__ __nv_bfloat16 g_wh[1536 * 512];              // W_in hi
__device__ __nv_bfloat16 g_wl[1536 * 512];              // W_in lo
__device__ __nv_bfloat16 g_oh[512 * 512];               // W_out hi
__device__ __nv_bfloat16 g_ol[512 * 512];               // W_out lo
__device__ float         g_q [(size_t)BS * NQ * 512];   // Q   fp32
__device__ float         g_kv[(size_t)BS * NE * 1024];  // K|V fp32
__device__ __nv_bfloat16 g_ah[(size_t)BS * NQ * 512];   // attn out hi
__device__ __nv_bfloat16 g_al[(size_t)BS * NQ * 512];   // attn out lo

__device__ __forceinline__ float neg_inf() { return __int_as_float(0xff800000u); }

__device__ __forceinline__ uint32_t smem_u32(const void* p) {
    uint32_t a;
    asm("{ .reg .u64 t; cvta.to.shared.u64 t, %1; cvt.u32.u64 %0, t; }" : "=r"(a) : "l"(p));
    return a;
}
#define SW128(bo) ((bo) ^ (((bo) >> 3) & 0x70))

#define CP_ASYNC16(dst, src) \
    asm volatile("cp.async.cg.shared.global [%0], [%1], 16;" :: "r"(dst), "l"(src) : "memory")
#define CP_COMMIT() asm volatile("cp.async.commit_group;" ::: "memory")
#define CP_WAIT0()  asm volatile("cp.async.wait_group 0;" ::: "memory")

#define BAR_SYNC(id, cnt) \
    asm volatile("bar.sync %0, %1;" :: "r"(id), "r"(cnt) : "memory")

#define LDMATRIX_X4(r0, r1, r2, r3, addr) \
    asm volatile("ldmatrix.sync.aligned.m8n8.x4.shared.b16 {%0,%1,%2,%3}, [%4];" \
        : "=r"(r0), "=r"(r1), "=r"(r2), "=r"(r3) : "r"(addr))

#define MMA_BF16(c, a, b) \
    asm volatile("mma.sync.aligned.m16n8k16.row.col.f32.bf16.bf16.f32 " \
        "{%0,%1,%2,%3}, {%4,%5,%6,%7}, {%8,%9}, {%0,%1,%2,%3};" \
        : "+f"((c)[0]), "+f"((c)[1]), "+f"((c)[2]), "+f"((c)[3]) \
        : "r"((a)[0]), "r"((a)[1]), "r"((a)[2]), "r"((a)[3]), "r"((b)[0]), "r"((b)[1]))

// ---------------------------------------------------------------------------
// Single merged split kernel: fp32 -> (bf16 hi, bf16 lo) for all 3 tensors.
// Blocks [0,8192): entities, [8192,8960): W_in, [8960,9216): W_out.
// ---------------------------------------------------------------------------
__global__ void __launch_bounds__(256)
split_all(const float* __restrict__ ent,
          const float* __restrict__ win,
          const float* __restrict__ wout)
{
    const int b = blockIdx.x;
    const float* src; __nv_bfloat16 *hi, *lo; int n4, lb, nb;
    if (b < 8192)      { src = ent;  hi = g_eh; lo = g_el; n4 = (BS * NE * 512) / 4; lb = b;        nb = 8192; }
    else if (b < 8960) { src = win;  hi = g_wh; lo = g_wl; n4 = (1536 * 512) / 4;    lb = b - 8192; nb = 768; }
    else               { src = wout; hi = g_oh; lo = g_ol; n4 = (512 * 512) / 4;     lb = b - 8960; nb = 256; }

    for (int i = lb * 256 + threadIdx.x; i < n4; i += nb * 256) {
        const float4 v = ((const float4*)src)[i];
        float f[4] = {v.x, v.y, v.z, v.w};
        unsigned short hs[4], ls[4];
#pragma unroll
        for (int j = 0; j < 4; j++) {
            __nv_bfloat16 hb = __float2bfloat16(f[j]);
            hs[j] = __bfloat16_as_ushort(hb);
            ls[j] = __bfloat16_as_ushort(__float2bfloat16(f[j] - __bfloat162float(hb)));
        }
        uint2 hv, lv;
        hv.x = (uint32_t)hs[0] | ((uint32_t)hs[1] << 16);
        hv.y = (uint32_t)hs[2] | ((uint32_t)hs[3] << 16);
        lv.x = (uint32_t)ls[0] | ((uint32_t)ls[1] << 16);
        lv.y = (uint32_t)ls[2] | ((uint32_t)ls[3] << 16);
        ((uint2*)hi)[i] = hv;
        ((uint2*)lo)[i] = lv;
    }
}

// ---------------------------------------------------------------------------
// GEMM core: mma.sync bf16x3 (Ah*Bh + Ah*Bl + Al*Bh, fp32 accum).
// CTA tile 128x256, 512 threads (16 warps: wm=wid>>3 (M), wn=wid&7 (N)),
// warp tile 64x32. BK=64, SW128 rows. 2-stage A (64KB) + 2-stage B (128KB).
// Operand loading privatized: each M-half loads its own A rows, each
// N-column warp-pair loads its own B rows. Sync via NAMED barriers only:
// bar(1+wm, 256) for A-half, bar(3+wn, 64) for B-pair — no CTA-wide drain.
// Schedule per chunk: wait_group(0) -> bars -> issue(t+1) -> compute(t).
// ---------------------------------------------------------------------------
#define A_STAGE  32768                 // Ah 16K | Al 16K
#define B_STAGE  65536                 // Bh 32K | Bl 32K
#define B_BASE   (2 * A_STAGE)         // 65536
#define GSMEM_TOTAL (B_BASE + 2 * B_STAGE)   // 196608 = 192KB
#define NITER 8

template <bool OUTPROJ>
__device__ __forceinline__ void gemm_core(
    const __nv_bfloat16* __restrict__ Ahp, const __nv_bfloat16* __restrict__ Alp,
    const __nv_bfloat16* __restrict__ Bhp, const __nv_bfloat16* __restrict__ Blp,
    float* __restrict__ C, int ldc, bool gatherQ, int row0, int col0,
    const float* __restrict__ bias, const unsigned int* __restrict__ mask,
    uint32_t sb)
{
    const int tid  = threadIdx.x;
    const int wid  = tid >> 5;
    const int lane = tid & 31;
    const int wm   = wid >> 3;             // 0..1 (M half)
    const int wn   = wid & 7;              // 0..7 (N pair)
    const int htid = tid & 255;            // half-local thread id
    const int ptid = ((tid >> 8) << 5) | (tid & 31);   // pair-local 0..63

    float acc[4][4][4];
#pragma unroll
    for (int i = 0; i < 4; i++)
#pragma unroll
        for (int j = 0; j < 4; j++)
#pragma unroll
            for (int k = 0; k < 4; k++) acc[i][j][k] = 0.0f;

    // ---- privatized loader: chunk t into stage t&1 (1 group/thread) ----
    auto issue_load = [&](int t) {
        const int kc = t * 64;
        const uint32_t stA = sb + (uint32_t)(t & 1) * A_STAGE;
        const uint32_t stB = sb + B_BASE + (uint32_t)(t & 1) * B_STAGE;
#pragma unroll
        for (int i = 0; i < 2; i++) {      // A half: 64 rows x 8 c16, hi+lo
            const int u = htid + i * 256;
            const int r = u >> 3, c = u & 7;
            const int rf = wm * 64 + r;
            const int gr = row0 + rf;
            const int ar = gatherQ ? (((gr >> 4) << 6) + (gr & 15)) : gr;
            const uint32_t sw = SW128((uint32_t)(rf * 128 + c * 16));
            CP_ASYNC16(stA + sw,         Ahp + (size_t)ar * 512 + kc + c * 8);
            CP_ASYNC16(stA + 16384 + sw, Alp + (size_t)ar * 512 + kc + c * 8);
        }
#pragma unroll
        for (int i = 0; i < 4; i++) {      // B pair: 32 rows x 8 c16, hi+lo
            const int u = ptid + i * 64;
            const int r = u >> 3, c = u & 7;
            const int rf = wn * 32 + r;
            const uint32_t sw = SW128((uint32_t)(rf * 128 + c * 16));
            CP_ASYNC16(stB + sw,         Bhp + (size_t)(col0 + rf) * 512 + kc + c * 8);
            CP_ASYNC16(stB + 32768 + sw, Blp + (size_t)(col0 + rf) * 512 + kc + c * 8);
        }
        CP_COMMIT();
    };

    issue_load(0);

    const int l8   = lane & 7;
    const int lsel = lane >> 3;

    for (int t = 0; t < NITER; t++) {
        CP_WAIT0();                        // my chunk-t slice landed
        BAR_SYNC(1 + wm, 256);             // A-half mates done: stage visible+free
        BAR_SYNC(3 + wn, 64);              // B-pair mates done
        if (t + 1 < NITER) issue_load(t + 1);   // safe: readers of stage (t+1)&1 passed bars

        const uint32_t stA = sb + (uint32_t)(t & 1) * A_STAGE;
        const uint32_t stB = sb + B_BASE + (uint32_t)(t & 1) * B_STAGE;

#pragma unroll
        for (int ks = 0; ks < 4; ks++) {   // 4 x k16 per chunk
            const int ra = wm * 64 + l8 + (lsel & 1) * 8;
            const int ca = ks * 2 + (lsel >> 1);
            const int rb = wn * 32 + (lsel >> 1) * 8 + l8;
            const int cb = ks * 2 + (lsel & 1);

            uint32_t ah[4][4], al[4][4], bh[4][2], bl[4][2];
#pragma unroll
            for (int am = 0; am < 4; am++) {
                const int r = ra + am * 16;
                const uint32_t off = (uint32_t)(r * 128 + ((ca ^ (r & 7)) << 4));
                LDMATRIX_X4(ah[am][0], ah[am][1], ah[am][2], ah[am][3], stA + off);
            }
#pragma unroll
            for (int bp = 0; bp < 2; bp++) {
                const int r = rb + bp * 16;
                const uint32_t off = (uint32_t)(r * 128 + ((cb ^ (r & 7)) << 4));
                LDMATRIX_X4(bh[2 * bp][0], bh[2 * bp][1], bh[2 * bp + 1][0], bh[2 * bp + 1][1],
                            stB + off);
            }
            // term 0: Ah * Bh
#pragma unroll
            for (int am = 0; am < 4; am++)
#pragma unroll
                for (int nt = 0; nt < 4; nt++)
                    MMA_BF16(acc[am][nt], ah[am], bh[nt]);
            // term 1: Ah * Bl
#pragma unroll
            for (int bp = 0; bp < 2; bp++) {
                const int r = rb + bp * 16;
                const uint32_t off = (uint32_t)(r * 128 + ((cb ^ (r & 7)) << 4));
                LDMATRIX_X4(bl[2 * bp][0], bl[2 * bp][1], bl[2 * bp + 1][0], bl[2 * bp + 1][1],
                            stB + 32768 + off);
            }
#pragma unroll
            for (int am = 0; am < 4; am++)
#pragma unroll
                for (int nt = 0; nt < 4; nt++)
                    MMA_BF16(acc[am][nt], ah[am], bl[nt]);
            // term 2: Al * Bh
#pragma unroll
            for (int am = 0; am < 4; am++) {
                const int r = ra + am * 16;
                const uint32_t off = (uint32_t)(r * 128 + ((ca ^ (r & 7)) << 4));
                LDMATRIX_X4(al[am][0], al[am][1], al[am][2], al[am][3], stA + 16384 + off);
            }
#pragma unroll
            for (int am = 0; am < 4; am++)
#pragma unroll
                for (int nt = 0; nt < 4; nt++)
                    MMA_BF16(acc[am][nt], al[am], bh[nt]);
        }
    }

    // ---- epilogue (registers only; no barrier needed) ----
    const int g  = lane >> 2;
    const int tg = lane & 3;
#pragma unroll
    for (int am = 0; am < 4; am++) {
        const int r0 = row0 + wm * 64 + am * 16 + g;
        const int r1 = r0 + 8;
        bool z0 = false, z1 = false;
        if (OUTPROJ) { z0 = (mask[r0] != 0u); z1 = (mask[r1] != 0u); }
#pragma unroll
        for (int nt = 0; nt < 4; nt++) {
            const int col = col0 + wn * 32 + nt * 8 + tg * 2;
            float2 v0 = make_float2(acc[am][nt][0], acc[am][nt][1]);
            float2 v1 = make_float2(acc[am][nt][2], acc[am][nt][3]);
            if (OUTPROJ) {
                const float bb0 = bias[col], bb1 = bias[col + 1];
                v0.x = z0 ? 0.0f : v0.x + bb0;  v0.y = z0 ? 0.0f : v0.y + bb1;
                v1.x = z1 ? 0.0f : v1.x + bb0;  v1.y = z1 ? 0.0f : v1.y + bb1;
            }
            *(float2*)(C + (size_t)r0 * ldc + col) = v0;
            *(float2*)(C + (size_t)r1 * ldc + col) = v1;
        }
    }
}

// Fused KV + Q projection: blocks [0,4096) = KV (4 x 1024 tiles),
// blocks [4096,4608) = Q (2 x 256 tiles, gathered A rows).
__global__ void __launch_bounds__(512, 1)
fused_qkv_gemm()
{
    extern __shared__ char smem[];
    const uint32_t sb = smem_u32(smem);
    const int bid = blockIdx.x;
    const bool isQ = bid >= 4096;
    int bx, by;
    if (!isQ) { bx = bid & 3;  by = bid >> 2; }
    else      { const int b2 = bid - 4096; bx = b2 & 1; by = b2 >> 1; }
    const int row0 = by * 128, col0 = bx * 256;
    const __nv_bfloat16* Bhp = isQ ? g_wh : g_wh + 512 * 512;
    const __nv_bfloat16* Blp = isQ ? g_wl : g_wl + 512 * 512;
    float* C = isQ ? g_q : g_kv;
    const int ldc = isQ ? 512 : 1024;
    gemm_core<false>(g_eh, g_el, Bhp, Blp, C, ldc, isQ, row0, col0,
                     nullptr, nullptr, sb);
}

// Output projection: bias + post_mask epilogue.
__global__ void __launch_bounds__(512, 1)
out_gemm(float* __restrict__ Cout,
         const float* __restrict__ bias,
         const unsigned int* __restrict__ mask)
{
    extern __shared__ char smem[];
    const uint32_t sb = smem_u32(smem);
    const int row0 = blockIdx.y * 128, col0 = blockIdx.x * 256;
    gemm_core<true>(g_ah, g_al, g_oh, g_ol, Cout, 512, false, row0, col0,
                    bias, mask, sb);
}

// ---------------------------------------------------------------------------
// Attention: one block per (batch, head). 128 threads. Emits bf16 hi/lo.
// ---------------------------------------------------------------------------
__global__ void __launch_bounds__(128)
attn_kernel(const unsigned int* __restrict__ pre_mask)
{
    __shared__ float qs[16][68];
    __shared__ float ks[64][68];
    __shared__ float vs[64][68];
    __shared__ float at[16][68];

    const int b = blockIdx.x;
    const int h = blockIdx.y;
    const int tid = threadIdx.x;

#pragma unroll
    for (int rep = 0; rep < 2; rep++) {
        const int uu = tid + rep * 128;
        const int i = uu >> 4, d4 = uu & 15;
        *(float4*)&qs[i][d4 * 4] =
            *(const float4*)(g_q + ((size_t)(b * 16 + i)) * 512 + h * 64 + d4 * 4);
    }
#pragma unroll
    for (int rep = 0; rep < 8; rep++) {
        const int uu = tid + rep * 128;
        const int n = uu >> 4, d4 = uu & 15;
        const size_t base = ((size_t)(b * 64 + n)) * 1024 + h * 64 + d4 * 4;
        *(float4*)&ks[n][d4 * 4] = *(const float4*)(g_kv + base);
        *(float4*)&vs[n][d4 * 4] = *(const float4*)(g_kv + base + 512);
    }
    __syncthreads();

    const int i = tid >> 3;
    const int c = tid & 7;
    const unsigned int* pm = pre_mask + ((size_t)b * 64 + i) * 64;

    float lg[8];
    {
        float dacc[8] = {0, 0, 0, 0, 0, 0, 0, 0};
        for (int d4 = 0; d4 < 16; d4++) {
            const float4 q = *(const float4*)&qs[i][d4 * 4];
#pragma unroll
            for (int j = 0; j < 8; j++) {
                const float4 kv = *(const float4*)&ks[c + j * 8][d4 * 4];
                dacc[j] = fmaf(q.x, kv.x, dacc[j]);
                dacc[j] = fmaf(q.y, kv.y, dacc[j]);
                dacc[j] = fmaf(q.z, kv.z, dacc[j]);
                dacc[j] = fmaf(q.w, kv.w, dacc[j]);
            }
        }
        const float NI = neg_inf();
        float mx = NI;
#pragma unroll
        for (int j = 0; j < 8; j++) {
            lg[j] = (pm[c + j * 8] != 0u) ? NI : dacc[j] * 0.125f;
            mx = fmaxf(mx, lg[j]);
        }
        mx = fmaxf(mx, __shfl_xor_sync(0xffffffffu, mx, 1, 8));
        mx = fmaxf(mx, __shfl_xor_sync(0xffffffffu, mx, 2, 8));
        mx = fmaxf(mx, __shfl_xor_sync(0xffffffffu, mx, 4, 8));
        const bool any = (mx != NI);
        float sum = 0.0f;
#pragma unroll
        for (int j = 0; j < 8; j++) {
            const float e = any ? __expf(lg[j] - mx) : 0.0f;
            lg[j] = e;
            sum += e;
        }
        sum += __shfl_xor_sync(0xffffffffu, sum, 1, 8);
        sum += __shfl_xor_sync(0xffffffffu, sum, 2, 8);
        sum += __shfl_xor_sync(0xffffffffu, sum, 4, 8);
        const float inv = (sum > 0.0f) ? (1.0f / sum) : 0.0f;
#pragma unroll
        for (int j = 0; j < 8; j++)
            at[i][c + j * 8] = lg[j] * inv;
    }
    __syncthreads();

    float4 o0 = make_float4(0, 0, 0, 0), o1 = make_float4(0, 0, 0, 0);
#pragma unroll 8
    for (int n = 0; n < 64; n++) {
        const float a = at[i][n];
        const float4 v0 = *(const float4*)&vs[n][c * 8];
        const float4 v1 = *(const float4*)&vs[n][c * 8 + 4];
        o0.x = fmaf(a, v0.x, o0.x); o0.y = fmaf(a, v0.y, o0.y);
        o0.z = fmaf(a, v0.z, o0.z); o0.w = fmaf(a, v0.w, o0.w);
        o1.x = fmaf(a, v1.x, o1.x); o1.y = fmaf(a, v1.y, o1.y);
        o1.z = fmaf(a, v1.z, o1.z); o1.w = fmaf(a, v1.w, o1.w);
    }
    float ov[8] = {o0.x, o0.y, o0.z, o0.w, o1.x, o1.y, o1.z, o1.w};
    unsigned short hs[8], ls[8];
#pragma unroll
    for (int j = 0; j < 8; j++) {
        __nv_bfloat16 hb = __float2bfloat16(ov[j]);
        hs[j] = __bfloat16_as_ushort(hb);
        ls[j] = __bfloat16_as_ushort(__float2bfloat16(ov[j] - __bfloat162float(hb)));
    }
    uint4 hv, lv;
    hv.x = (uint32_t)hs[0] | ((uint32_t)hs[1] << 16);
    hv.y = (uint32_t)hs[2] | ((uint32_t)hs[3] << 16);
    hv.z = (uint32_t)hs[4] | ((uint32_t)hs[5] << 16);
    hv.w = (uint32_t)hs[6] | ((uint32_t)hs[7] << 16);
    lv.x = (uint32_t)ls[0] | ((uint32_t)ls[1] << 16);
    lv.y = (uint32_t)ls[2] | ((uint32_t)ls[3] << 16);
    lv.z = (uint32_t)ls[4] | ((uint32_t)ls[5] << 16);
    lv.w = (uint32_t)ls[6] | ((uint32_t)ls[7] << 16);
    const size_t base = ((size_t)(b * 16 + i)) * 512 + h * 64 + c * 8;
    *(uint4*)(g_ah + base) = hv;
    *(uint4*)(g_al + base) = lv;
}

// ---------------------------------------------------------------------------
extern "C" void kernel_launch(void* const* d_in, const int* in_sizes, int n_in,
                              void* d_out, int out_size)
{
    const float*        entities  = (const float*)d_in[0];
    const unsigned int* pre_mask  = (const unsigned int*)d_in[1];
    const unsigned int* post_mask = (const unsigned int*)d_in[2];
    const float*        W_in      = (const float*)d_in[3];
    const float*        W_out     = (const float*)d_in[4];
    const float*        b_out     = (const float*)d_in[5];
    float*              out       = (float*)d_out;

    cudaFuncSetAttribute(fused_qkv_gemm, cudaFuncAttributeMaxDynamicSharedMemorySize, GSMEM_TOTAL);
    cudaFuncSetAttribute(out_gemm,       cudaFuncAttributeMaxDynamicSharedMemorySize, GSMEM_TOTAL);

    // all hi/lo splits in one launch
    split_all<<<9216, 256>>>(entities, W_in, W_out);

    // KV projection (4096 blocks) + Q projection (512 blocks) fused
    fused_qkv_gemm<<<4608, 512, GSMEM_TOTAL>>>();

    // Attention
    attn_kernel<<<dim3(BS, NHEAD), 128>>>(pre_mask);

    // Output projection + bias + post_mask
    out_gemm<<<dim3(2, 256), 512, GSMEM_TOTAL>>>(out, b_out, post_mask);
}

// round 11
// speedup vs baseline: 1.3024x; 1.2371x over previous
#include <cuda_runtime.h>
#include <cuda_fp16.h>
#include <math.h>
#include <stdint.h>

// Problem constants
#define BS      2048
#define NE      64
#define NQ      16
#define EMBED   512
#define NHEAD   8
#define HD      64

#define WSCALE     512.0f          // weights pre-scaled by 2^9 (exact)
#define INV_WSCALE (1.0f / 512.0f)

// ---------------------------------------------------------------------------
// Scratch (__device__ globals — allocation-free)
// ---------------------------------------------------------------------------
__device__ __half g_ef[(size_t)BS * NE * 512];   // entities fp16 (single)
__device__ __half g_wh[1536 * 512];              // W_in*512 hi
__device__ __half g_wl[1536 * 512];              // W_in*512 lo
__device__ __half g_oh[512 * 512];               // W_out*512 hi
__device__ __half g_ol[512 * 512];               // W_out*512 lo
__device__ float  g_q [(size_t)BS * NQ * 512];   // Q   fp32
__device__ float  g_kv[(size_t)BS * NE * 1024];  // K|V fp32
__device__ __half g_af[(size_t)BS * NQ * 512];   // attn out fp16 (single)

__device__ __forceinline__ float neg_inf() { return __int_as_float(0xff800000u); }

__device__ __forceinline__ uint32_t smem_u32(const void* p) {
    uint32_t a;
    asm("{ .reg .u64 t; cvta.to.shared.u64 t, %1; cvt.u32.u64 %0, t; }" : "=r"(a) : "l"(p));
    return a;
}
#define SW128(bo) ((bo) ^ (((bo) >> 3) & 0x70))

#define CP_ASYNC16(dst, src) \
    asm volatile("cp.async.cg.shared.global [%0], [%1], 16;" :: "r"(dst), "l"(src) : "memory")
#define CP_COMMIT() asm volatile("cp.async.commit_group;" ::: "memory")
#define CP_WAIT0()  asm volatile("cp.async.wait_group 0;" ::: "memory")

#define BAR_SYNC(id, cnt) \
    asm volatile("bar.sync %0, %1;" :: "r"(id), "r"(cnt) : "memory")

#define LDMATRIX_X4(r0, r1, r2, r3, addr) \
    asm volatile("ldmatrix.sync.aligned.m8n8.x4.shared.b16 {%0,%1,%2,%3}, [%4];" \
        : "=r"(r0), "=r"(r1), "=r"(r2), "=r"(r3) : "r"(addr))

#define MMA_F16(c, a, b) \
    asm volatile("mma.sync.aligned.m16n8k16.row.col.f32.f16.f16.f32 " \
        "{%0,%1,%2,%3}, {%4,%5,%6,%7}, {%8,%9}, {%0,%1,%2,%3};" \
        : "+f"((c)[0]), "+f"((c)[1]), "+f"((c)[2]), "+f"((c)[3]) \
        : "r"((a)[0]), "r"((a)[1]), "r"((a)[2]), "r"((a)[3]), "r"((b)[0]), "r"((b)[1]))

// ---------------------------------------------------------------------------
// Merged conversion kernel:
//  entities -> fp16 single; W_in, W_out -> (fp16 hi, fp16 lo) of 512*W.
// Blocks [0,8192): entities, [8192,8960): W_in, [8960,9216): W_out.
// ---------------------------------------------------------------------------
__global__ void __launch_bounds__(256)
split_all(const float* __restrict__ ent,
          const float* __restrict__ win,
          const float* __restrict__ wout)
{
    const int b = blockIdx.x;
    if (b < 8192) {                       // entities: fp32 -> fp16 single
        const int n4 = (BS * NE * 512) / 4;
        for (int i = b * 256 + threadIdx.x; i < n4; i += 8192 * 256) {
            const float4 v = ((const float4*)ent)[i];
            uint2 o;
            o.x = (uint32_t)__half_as_ushort(__float2half_rn(v.x)) |
                  ((uint32_t)__half_as_ushort(__float2half_rn(v.y)) << 16);
            o.y = (uint32_t)__half_as_ushort(__float2half_rn(v.z)) |
                  ((uint32_t)__half_as_ushort(__float2half_rn(v.w)) << 16);
            ((uint2*)g_ef)[i] = o;
        }
        return;
    }
    const float* src; __half *hi, *lo; int n4, lb, nb;
    if (b < 8960) { src = win;  hi = g_wh; lo = g_wl; n4 = (1536 * 512) / 4; lb = b - 8192; nb = 768; }
    else          { src = wout; hi = g_oh; lo = g_ol; n4 = (512 * 512) / 4;  lb = b - 8960; nb = 256; }

    for (int i = lb * 256 + threadIdx.x; i < n4; i += nb * 256) {
        const float4 v = ((const float4*)src)[i];
        float f[4] = {v.x * WSCALE, v.y * WSCALE, v.z * WSCALE, v.w * WSCALE};
        unsigned short hs[4], ls[4];
#pragma unroll
        for (int j = 0; j < 4; j++) {
            const __half hb = __float2half_rn(f[j]);
            hs[j] = __half_as_ushort(hb);
            ls[j] = __half_as_ushort(__float2half_rn(f[j] - __half2float(hb)));
        }
        uint2 hv, lv;
        hv.x = (uint32_t)hs[0] | ((uint32_t)hs[1] << 16);
        hv.y = (uint32_t)hs[2] | ((uint32_t)hs[3] << 16);
        lv.x = (uint32_t)ls[0] | ((uint32_t)ls[1] << 16);
        lv.y = (uint32_t)ls[2] | ((uint32_t)ls[3] << 16);
        ((uint2*)hi)[i] = hv;
        ((uint2*)lo)[i] = lv;
    }
}

// ---------------------------------------------------------------------------
// GEMM core: fp16x2 (A*Bh + A*Bl, fp32 accum; B pre-scaled by 512, epilogue
// multiplies by 1/512). CTA tile 128x256, 512 threads (16 warps: wm=wid>>3,
// wn=wid&7), warp tile 64x32. BK=64, SW128 rows.
// Stage: A 16K (2 stages @ 0) | Bh 32K + Bl 32K (2 stages @ 32K). 160KB.
// Privatized loads + named barriers (A-half: bar 1+wm/256, B-pair: bar 3+wn/64).
// Schedule per chunk: wait_group(0) -> bars -> issue(t+1) -> compute(t).
// ---------------------------------------------------------------------------
#define A_STAGE  16384
#define B_STAGE  65536                 // Bh 32K | Bl 32K
#define B_BASE   (2 * A_STAGE)         // 32768
#define OFF_BL   32768
#define GSMEM_TOTAL (B_BASE + 2 * B_STAGE)   // 163840 = 160KB
#define NITER 8

template <bool OUTPROJ>
__device__ __forceinline__ void gemm_core(
    const __half* __restrict__ Afp,
    const __half* __restrict__ Bhp, const __half* __restrict__ Blp,
    float* __restrict__ C, int ldc, bool gatherQ, int row0, int col0,
    const float* __restrict__ bias, const unsigned int* __restrict__ mask,
    uint32_t sb)
{
    const int tid  = threadIdx.x;
    const int wid  = tid >> 5;
    const int lane = tid & 31;
    const int wm   = wid >> 3;             // 0..1 (M half)
    const int wn   = wid & 7;              // 0..7 (N pair)
    const int htid = tid & 255;            // half-local thread id
    const int ptid = ((tid >> 8) << 5) | (tid & 31);   // pair-local 0..63

    float acc[4][4][4];
#pragma unroll
    for (int i = 0; i < 4; i++)
#pragma unroll
        for (int j = 0; j < 4; j++)
#pragma unroll
            for (int k = 0; k < 4; k++) acc[i][j][k] = 0.0f;

    // ---- privatized loader: chunk t into stage t&1 (1 group/thread) ----
    auto issue_load = [&](int t) {
        const int kc = t * 64;
        const uint32_t stA = sb + (uint32_t)(t & 1) * A_STAGE;
        const uint32_t stB = sb + B_BASE + (uint32_t)(t & 1) * B_STAGE;
#pragma unroll
        for (int i = 0; i < 2; i++) {      // A half: 64 rows x 8 c16
            const int u = htid + i * 256;
            const int r = u >> 3, c = u & 7;
            const int rf = wm * 64 + r;
            const int gr = row0 + rf;
            const int ar = gatherQ ? (((gr >> 4) << 6) + (gr & 15)) : gr;
            const uint32_t sw = SW128((uint32_t)(rf * 128 + c * 16));
            CP_ASYNC16(stA + sw, Afp + (size_t)ar * 512 + kc + c * 8);
        }
#pragma unroll
        for (int i = 0; i < 4; i++) {      // B pair: 32 rows x 8 c16, hi+lo
            const int u = ptid + i * 64;
            const int r = u >> 3, c = u & 7;
            const int rf = wn * 32 + r;
            const uint32_t sw = SW128((uint32_t)(rf * 128 + c * 16));
            CP_ASYNC16(stB + sw,          Bhp + (size_t)(col0 + rf) * 512 + kc + c * 8);
            CP_ASYNC16(stB + OFF_BL + sw, Blp + (size_t)(col0 + rf) * 512 + kc + c * 8);
        }
        CP_COMMIT();
    };

    issue_load(0);

    const int l8   = lane & 7;
    const int lsel = lane >> 3;

    for (int t = 0; t < NITER; t++) {
        CP_WAIT0();                        // my chunk-t slice landed
        BAR_SYNC(1 + wm, 256);             // A-half mates done
        BAR_SYNC(3 + wn, 64);              // B-pair mates done
        if (t + 1 < NITER) issue_load(t + 1);

        const uint32_t stA = sb + (uint32_t)(t & 1) * A_STAGE;
        const uint32_t stB = sb + B_BASE + (uint32_t)(t & 1) * B_STAGE;

#pragma unroll
        for (int ks = 0; ks < 4; ks++) {   // 4 x k16 per chunk
            const int ra = wm * 64 + l8 + (lsel & 1) * 8;
            const int ca = ks * 2 + (lsel >> 1);
            const int rb = wn * 32 + (lsel >> 1) * 8 + l8;
            const int cb = ks * 2 + (lsel & 1);

            uint32_t a[4][4], bh[4][2], bl[4][2];
#pragma unroll
            for (int am = 0; am < 4; am++) {
                const int r = ra + am * 16;
                const uint32_t off = (uint32_t)(r * 128 + ((ca ^ (r & 7)) << 4));
                LDMATRIX_X4(a[am][0], a[am][1], a[am][2], a[am][3], stA + off);
            }
#pragma unroll
            for (int bp = 0; bp < 2; bp++) {
                const int r = rb + bp * 16;
                const uint32_t off = (uint32_t)(r * 128 + ((cb ^ (r & 7)) << 4));
                LDMATRIX_X4(bh[2 * bp][0], bh[2 * bp][1], bh[2 * bp + 1][0], bh[2 * bp + 1][1],
                            stB + off);
            }
            // term 0: A * Bh
#pragma unroll
            for (int am = 0; am < 4; am++)
#pragma unroll
                for (int nt = 0; nt < 4; nt++)
                    MMA_F16(acc[am][nt], a[am], bh[nt]);
            // term 1: A * Bl
#pragma unroll
            for (int bp = 0; bp < 2; bp++) {
                const int r = rb + bp * 16;
                const uint32_t off = (uint32_t)(r * 128 + ((cb ^ (r & 7)) << 4));
                LDMATRIX_X4(bl[2 * bp][0], bl[2 * bp][1], bl[2 * bp + 1][0], bl[2 * bp + 1][1],
                            stB + OFF_BL + off);
            }
#pragma unroll
            for (int am = 0; am < 4; am++)
#pragma unroll
                for (int nt = 0; nt < 4; nt++)
                    MMA_F16(acc[am][nt], a[am], bl[nt]);
        }
    }

    // ---- epilogue: unscale by 1/512 (+ bias/mask for out projection) ----
    const int g  = lane >> 2;
    const int tg = lane & 3;
#pragma unroll
    for (int am = 0; am < 4; am++) {
        const int r0 = row0 + wm * 64 + am * 16 + g;
        const int r1 = r0 + 8;
        bool z0 = false, z1 = false;
        if (OUTPROJ) { z0 = (mask[r0] != 0u); z1 = (mask[r1] != 0u); }
#pragma unroll
        for (int nt = 0; nt < 4; nt++) {
            const int col = col0 + wn * 32 + nt * 8 + tg * 2;
            float2 v0 = make_float2(acc[am][nt][0] * INV_WSCALE, acc[am][nt][1] * INV_WSCALE);
            float2 v1 = make_float2(acc[am][nt][2] * INV_WSCALE, acc[am][nt][3] * INV_WSCALE);
            if (OUTPROJ) {
                const float bb0 = bias[col], bb1 = bias[col + 1];
                v0.x = z0 ? 0.0f : v0.x + bb0;  v0.y = z0 ? 0.0f : v0.y + bb1;
                v1.x = z1 ? 0.0f : v1.x + bb0;  v1.y = z1 ? 0.0f : v1.y + bb1;
            }
            *(float2*)(C + (size_t)r0 * ldc + col) = v0;
            *(float2*)(C + (size_t)r1 * ldc + col) = v1;
        }
    }
}

// Fused KV + Q projection: blocks [0,4096) = KV, [4096,4608) = Q (gathered).
__global__ void __launch_bounds__(512, 1)
fused_qkv_gemm()
{
    extern __shared__ char smem[];
    const uint32_t sb = smem_u32(smem);
    const int bid = blockIdx.x;
    const bool isQ = bid >= 4096;
    int bx, by;
    if (!isQ) { bx = bid & 3;  by = bid >> 2; }
    else      { const int b2 = bid - 4096; bx = b2 & 1; by = b2 >> 1; }
    const int row0 = by * 128, col0 = bx * 256;
    const __half* Bhp = isQ ? g_wh : g_wh + 512 * 512;
    const __half* Blp = isQ ? g_wl : g_wl + 512 * 512;
    float* C = isQ ? g_q : g_kv;
    const int ldc = isQ ? 512 : 1024;
    gemm_core<false>(g_ef, Bhp, Blp, C, ldc, isQ, row0, col0, nullptr, nullptr, sb);
}

// Output projection: bias + post_mask epilogue.
__global__ void __launch_bounds__(512, 1)
out_gemm(float* __restrict__ Cout,
         const float* __restrict__ bias,
         const unsigned int* __restrict__ mask)
{
    extern __shared__ char smem[];
    const uint32_t sb = smem_u32(smem);
    const int row0 = blockIdx.y * 128, col0 = blockIdx.x * 256;
    gemm_core<true>(g_af, g_oh, g_ol, Cout, 512, false, row0, col0, bias, mask, sb);
}

// ---------------------------------------------------------------------------
// Attention: one block per (batch, head). 128 threads. Emits fp16 attn-out.
// ---------------------------------------------------------------------------
__global__ void __launch_bounds__(128)
attn_kernel(const unsigned int* __restrict__ pre_mask)
{
    __shared__ float qs[16][68];
    __shared__ float ks[64][68];
    __shared__ float vs[64][68];
    __shared__ float at[16][68];

    const int b = blockIdx.x;
    const int h = blockIdx.y;
    const int tid = threadIdx.x;

#pragma unroll
    for (int rep = 0; rep < 2; rep++) {
        const int uu = tid + rep * 128;
        const int i = uu >> 4, d4 = uu & 15;
        *(float4*)&qs[i][d4 * 4] =
            *(const float4*)(g_q + ((size_t)(b * 16 + i)) * 512 + h * 64 + d4 * 4);
    }
#pragma unroll
    for (int rep = 0; rep < 8; rep++) {
        const int uu = tid + rep * 128;
        const int n = uu >> 4, d4 = uu & 15;
        const size_t base = ((size_t)(b * 64 + n)) * 1024 + h * 64 + d4 * 4;
        *(float4*)&ks[n][d4 * 4] = *(const float4*)(g_kv + base);
        *(float4*)&vs[n][d4 * 4] = *(const float4*)(g_kv + base + 512);
    }
    __syncthreads();

    const int i = tid >> 3;
    const int c = tid & 7;
    const unsigned int* pm = pre_mask + ((size_t)b * 64 + i) * 64;

    float lg[8];
    {
        float dacc[8] = {0, 0, 0, 0, 0, 0, 0, 0};
        for (int d4 = 0; d4 < 16; d4++) {
            const float4 q = *(const float4*)&qs[i][d4 * 4];
#pragma unroll
            for (int j = 0; j < 8; j++) {
                const float4 kv = *(const float4*)&ks[c + j * 8][d4 * 4];
                dacc[j] = fmaf(q.x, kv.x, dacc[j]);
                dacc[j] = fmaf(q.y, kv.y, dacc[j]);
                dacc[j] = fmaf(q.z, kv.z, dacc[j]);
                dacc[j] = fmaf(q.w, kv.w, dacc[j]);
            }
        }
        const float NI = neg_inf();
        float mx = NI;
#pragma unroll
        for (int j = 0; j < 8; j++) {
            lg[j] = (pm[c + j * 8] != 0u) ? NI : dacc[j] * 0.125f;
            mx = fmaxf(mx, lg[j]);
        }
        mx = fmaxf(mx, __shfl_xor_sync(0xffffffffu, mx, 1, 8));
        mx = fmaxf(mx, __shfl_xor_sync(0xffffffffu, mx, 2, 8));
        mx = fmaxf(mx, __shfl_xor_sync(0xffffffffu, mx, 4, 8));
        const bool any = (mx != NI);
        float sum = 0.0f;
#pragma unroll
        for (int j = 0; j < 8; j++) {
            const float e = any ? __expf(lg[j] - mx) : 0.0f;
            lg[j] = e;
            sum += e;
        }
        sum += __shfl_xor_sync(0xffffffffu, sum, 1, 8);
        sum += __shfl_xor_sync(0xffffffffu, sum, 2, 8);
        sum += __shfl_xor_sync(0xffffffffu, sum, 4, 8);
        const float inv = (sum > 0.0f) ? (1.0f / sum) : 0.0f;
#pragma unroll
        for (int j = 0; j < 8; j++)
            at[i][c + j * 8] = lg[j] * inv;
    }
    __syncthreads();

    float4 o0 = make_float4(0, 0, 0, 0), o1 = make_float4(0, 0, 0, 0);
#pragma unroll 8
    for (int n = 0; n < 64; n++) {
        const float a = at[i][n];
        const float4 v0 = *(const float4*)&vs[n][c * 8];
        const float4 v1 = *(const float4*)&vs[n][c * 8 + 4];
        o0.x = fmaf(a, v0.x, o0.x); o0.y = fmaf(a, v0.y, o0.y);
        o0.z = fmaf(a, v0.z, o0.z); o0.w = fmaf(a, v0.w, o0.w);
        o1.x = fmaf(a, v1.x, o1.x); o1.y = fmaf(a, v1.y, o1.y);
        o1.z = fmaf(a, v1.z, o1.z); o1.w = fmaf(a, v1.w, o1.w);
    }
    float ov[8] = {o0.x, o0.y, o0.z, o0.w, o1.x, o1.y, o1.z, o1.w};
    uint4 pv;
    unsigned short s[8];
#pragma unroll
    for (int j = 0; j < 8; j++) s[j] = __half_as_ushort(__float2half_rn(ov[j]));
    pv.x = (uint32_t)s[0] | ((uint32_t)s[1] << 16);
    pv.y = (uint32_t)s[2] | ((uint32_t)s[3] << 16);
    pv.z = (uint32_t)s[4] | ((uint32_t)s[5] << 16);
    pv.w = (uint32_t)s[6] | ((uint32_t)s[7] << 16);
    const size_t base = ((size_t)(b * 16 + i)) * 512 + h * 64 + c * 8;
    *(uint4*)(g_af + base) = pv;
}

// ---------------------------------------------------------------------------
extern "C" void kernel_launch(void* const* d_in, const int* in_sizes, int n_in,
                              void* d_out, int out_size)
{
    const float*        entities  = (const float*)d_in[0];
    const unsigned int* pre_mask  = (const unsigned int*)d_in[1];
    const unsigned int* post_mask = (const unsigned int*)d_in[2];
    const float*        W_in      = (const float*)d_in[3];
    const float*        W_out     = (const float*)d_in[4];
    const float*        b_out     = (const float*)d_in[5];
    float*              out       = (float*)d_out;

    cudaFuncSetAttribute(fused_qkv_gemm, cudaFuncAttributeMaxDynamicSharedMemorySize, GSMEM_TOTAL);
    cudaFuncSetAttribute(out_gemm,       cudaFuncAttributeMaxDynamicSharedMemorySize, GSMEM_TOTAL);

    // conversions: entities->fp16, weights->fp16 hi/lo (x512)
    split_all<<<9216, 256>>>(entities, W_in, W_out);

    // KV projection (4096 blocks) + Q projection (512 blocks) fused
    fused_qkv_gemm<<<4608, 512, GSMEM_TOTAL>>>();

    // Attention
    attn_kernel<<<dim3(BS, NHEAD), 128>>>(pre_mask);

    // Output projection + bias + post_mask
    out_gemm<<<dim3(2, 256), 512, GSMEM_TOTAL>>>(out, b_out, post_mask);
}

// round 12
// speedup vs baseline: 1.5555x; 1.1943x over previous
#include <cuda_runtime.h>
#include <cuda_fp16.h>
#include <math.h>
#include <stdint.h>

// Problem constants
#define BS      2048
#define NE      64
#define NQ      16
#define EMBED   512
#define NHEAD   8
#define HD      64

#define WSCALE     512.0f          // weights pre-scaled by 2^9 (exact)
#define INV_WSCALE (1.0f / 512.0f)

// ---------------------------------------------------------------------------
// Scratch (__device__ globals — allocation-free)
// ---------------------------------------------------------------------------
__device__ __half g_ef[(size_t)BS * NE * 512];    // entities fp16 (single)
__device__ __half g_wh[1536 * 512];               // W_in*512 hi
__device__ __half g_wl[1536 * 512];               // W_in*512 lo
__device__ __half g_oh[512 * 512];                // W_out*512 hi
__device__ __half g_ol[512 * 512];                // W_out*512 lo
__device__ float  g_q [(size_t)BS * NQ * 512];    // Q fp32 (accuracy headroom)
__device__ __half g_kv16[(size_t)BS * NE * 1024]; // K|V fp16 interleaved (256MB)
__device__ __half g_af[(size_t)BS * NQ * 512];    // attn out fp16 (single)

__device__ __forceinline__ float neg_inf() { return __int_as_float(0xff800000u); }

__device__ __forceinline__ uint32_t smem_u32(const void* p) {
    uint32_t a;
    asm("{ .reg .u64 t; cvta.to.shared.u64 t, %1; cvt.u32.u64 %0, t; }" : "=r"(a) : "l"(p));
    return a;
}
#define SW128(bo) ((bo) ^ (((bo) >> 3) & 0x70))

#define CP_ASYNC16(dst, src) \
    asm volatile("cp.async.cg.shared.global [%0], [%1], 16;" :: "r"(dst), "l"(src) : "memory")
#define CP_COMMIT() asm volatile("cp.async.commit_group;" ::: "memory")
#define CP_WAIT0()  asm volatile("cp.async.wait_group 0;" ::: "memory")

#define BAR_SYNC(id, cnt) \
    asm volatile("bar.sync %0, %1;" :: "r"(id), "r"(cnt) : "memory")

#define LDMATRIX_X4(r0, r1, r2, r3, addr) \
    asm volatile("ldmatrix.sync.aligned.m8n8.x4.shared.b16 {%0,%1,%2,%3}, [%4];" \
        : "=r"(r0), "=r"(r1), "=r"(r2), "=r"(r3) : "r"(addr))

#define MMA_F16(c, a, b) \
    asm volatile("mma.sync.aligned.m16n8k16.row.col.f32.f16.f16.f32 " \
        "{%0,%1,%2,%3}, {%4,%5,%6,%7}, {%8,%9}, {%0,%1,%2,%3};" \
        : "+f"((c)[0]), "+f"((c)[1]), "+f"((c)[2]), "+f"((c)[3]) \
        : "r"((a)[0]), "r"((a)[1]), "r"((a)[2]), "r"((a)[3]), "r"((b)[0]), "r"((b)[1]))

// ---------------------------------------------------------------------------
// Merged conversion kernel:
//  entities -> fp16 single; W_in, W_out -> (fp16 hi, fp16 lo) of 512*W.
// ---------------------------------------------------------------------------
__global__ void __launch_bounds__(256)
split_all(const float* __restrict__ ent,
          const float* __restrict__ win,
          const float* __restrict__ wout)
{
    const int b = blockIdx.x;
    if (b < 8192) {                       // entities: fp32 -> fp16 single
        const int n4 = (BS * NE * 512) / 4;
        for (int i = b * 256 + threadIdx.x; i < n4; i += 8192 * 256) {
            const float4 v = ((const float4*)ent)[i];
            uint2 o;
            o.x = (uint32_t)__half_as_ushort(__float2half_rn(v.x)) |
                  ((uint32_t)__half_as_ushort(__float2half_rn(v.y)) << 16);
            o.y = (uint32_t)__half_as_ushort(__float2half_rn(v.z)) |
                  ((uint32_t)__half_as_ushort(__float2half_rn(v.w)) << 16);
            ((uint2*)g_ef)[i] = o;
        }
        return;
    }
    const float* src; __half *hi, *lo; int n4, lb, nb;
    if (b < 8960) { src = win;  hi = g_wh; lo = g_wl; n4 = (1536 * 512) / 4; lb = b - 8192; nb = 768; }
    else          { src = wout; hi = g_oh; lo = g_ol; n4 = (512 * 512) / 4;  lb = b - 8960; nb = 256; }

    for (int i = lb * 256 + threadIdx.x; i < n4; i += nb * 256) {
        const float4 v = ((const float4*)src)[i];
        float f[4] = {v.x * WSCALE, v.y * WSCALE, v.z * WSCALE, v.w * WSCALE};
        unsigned short hs[4], ls[4];
#pragma unroll
        for (int j = 0; j < 4; j++) {
            const __half hb = __float2half_rn(f[j]);
            hs[j] = __half_as_ushort(hb);
            ls[j] = __half_as_ushort(__float2half_rn(f[j] - __half2float(hb)));
        }
        uint2 hv, lv;
        hv.x = (uint32_t)hs[0] | ((uint32_t)hs[1] << 16);
        hv.y = (uint32_t)hs[2] | ((uint32_t)hs[3] << 16);
        lv.x = (uint32_t)ls[0] | ((uint32_t)ls[1] << 16);
        lv.y = (uint32_t)ls[2] | ((uint32_t)ls[3] << 16);
        ((uint2*)hi)[i] = hv;
        ((uint2*)lo)[i] = lv;
    }
}

// ---------------------------------------------------------------------------
// GEMM core: fp16x2 (A*Bh + A*Bl, fp32 accum; B pre-scaled by 512, epilogue
// multiplies by 1/512). CTA tile 128x256, 512 threads, warp tile 64x32.
// BK=64, SW128. Stage: A 16K | Bh 32K | Bl 32K, 2 stages = 160KB.
// Privatized loads + named barriers. HOUT: write fp16 half2 (KV path).
// ---------------------------------------------------------------------------
#define A_STAGE  16384
#define B_STAGE  65536
#define B_BASE   (2 * A_STAGE)
#define OFF_BL   32768
#define GSMEM_TOTAL (B_BASE + 2 * B_STAGE)   // 160KB
#define NITER 8

template <bool OUTPROJ, bool HOUT>
__device__ __forceinline__ void gemm_core(
    const __half* __restrict__ Afp,
    const __half* __restrict__ Bhp, const __half* __restrict__ Blp,
    void* __restrict__ Cv, int ldc, bool gatherQ, int row0, int col0,
    const float* __restrict__ bias, const unsigned int* __restrict__ mask,
    uint32_t sb)
{
    const int tid  = threadIdx.x;
    const int wid  = tid >> 5;
    const int lane = tid & 31;
    const int wm   = wid >> 3;
    const int wn   = wid & 7;
    const int htid = tid & 255;
    const int ptid = ((tid >> 8) << 5) | (tid & 31);

    float acc[4][4][4];
#pragma unroll
    for (int i = 0; i < 4; i++)
#pragma unroll
        for (int j = 0; j < 4; j++)
#pragma unroll
            for (int k = 0; k < 4; k++) acc[i][j][k] = 0.0f;

    auto issue_load = [&](int t) {
        const int kc = t * 64;
        const uint32_t stA = sb + (uint32_t)(t & 1) * A_STAGE;
        const uint32_t stB = sb + B_BASE + (uint32_t)(t & 1) * B_STAGE;
#pragma unroll
        for (int i = 0; i < 2; i++) {
            const int u = htid + i * 256;
            const int r = u >> 3, c = u & 7;
            const int rf = wm * 64 + r;
            const int gr = row0 + rf;
            const int ar = gatherQ ? (((gr >> 4) << 6) + (gr & 15)) : gr;
            const uint32_t sw = SW128((uint32_t)(rf * 128 + c * 16));
            CP_ASYNC16(stA + sw, Afp + (size_t)ar * 512 + kc + c * 8);
        }
#pragma unroll
        for (int i = 0; i < 4; i++) {
            const int u = ptid + i * 64;
            const int r = u >> 3, c = u & 7;
            const int rf = wn * 32 + r;
            const uint32_t sw = SW128((uint32_t)(rf * 128 + c * 16));
            CP_ASYNC16(stB + sw,          Bhp + (size_t)(col0 + rf) * 512 + kc + c * 8);
            CP_ASYNC16(stB + OFF_BL + sw, Blp + (size_t)(col0 + rf) * 512 + kc + c * 8);
        }
        CP_COMMIT();
    };

    issue_load(0);

    const int l8   = lane & 7;
    const int lsel = lane >> 3;

    for (int t = 0; t < NITER; t++) {
        CP_WAIT0();
        BAR_SYNC(1 + wm, 256);
        BAR_SYNC(3 + wn, 64);
        if (t + 1 < NITER) issue_load(t + 1);

        const uint32_t stA = sb + (uint32_t)(t & 1) * A_STAGE;
        const uint32_t stB = sb + B_BASE + (uint32_t)(t & 1) * B_STAGE;

#pragma unroll
        for (int ks = 0; ks < 4; ks++) {
            const int ra = wm * 64 + l8 + (lsel & 1) * 8;
            const int ca = ks * 2 + (lsel >> 1);
            const int rb = wn * 32 + (lsel >> 1) * 8 + l8;
            const int cb = ks * 2 + (lsel & 1);

            uint32_t a[4][4], bh[4][2], bl[4][2];
#pragma unroll
            for (int am = 0; am < 4; am++) {
                const int r = ra + am * 16;
                const uint32_t off = (uint32_t)(r * 128 + ((ca ^ (r & 7)) << 4));
                LDMATRIX_X4(a[am][0], a[am][1], a[am][2], a[am][3], stA + off);
            }
#pragma unroll
            for (int bp = 0; bp < 2; bp++) {
                const int r = rb + bp * 16;
                const uint32_t off = (uint32_t)(r * 128 + ((cb ^ (r & 7)) << 4));
                LDMATRIX_X4(bh[2 * bp][0], bh[2 * bp][1], bh[2 * bp + 1][0], bh[2 * bp + 1][1],
                            stB + off);
            }
#pragma unroll
            for (int am = 0; am < 4; am++)
#pragma unroll
                for (int nt = 0; nt < 4; nt++)
                    MMA_F16(acc[am][nt], a[am], bh[nt]);
#pragma unroll
            for (int bp = 0; bp < 2; bp++) {
                const int r = rb + bp * 16;
                const uint32_t off = (uint32_t)(r * 128 + ((cb ^ (r & 7)) << 4));
                LDMATRIX_X4(bl[2 * bp][0], bl[2 * bp][1], bl[2 * bp + 1][0], bl[2 * bp + 1][1],
                            stB + OFF_BL + off);
            }
#pragma unroll
            for (int am = 0; am < 4; am++)
#pragma unroll
                for (int nt = 0; nt < 4; nt++)
                    MMA_F16(acc[am][nt], a[am], bl[nt]);
        }
    }

    // ---- epilogue: unscale by 1/512; fp16 or fp32 output ----
    const int g  = lane >> 2;
    const int tg = lane & 3;
#pragma unroll
    for (int am = 0; am < 4; am++) {
        const int r0 = row0 + wm * 64 + am * 16 + g;
        const int r1 = r0 + 8;
        bool z0 = false, z1 = false;
        if (OUTPROJ) { z0 = (mask[r0] != 0u); z1 = (mask[r1] != 0u); }
#pragma unroll
        for (int nt = 0; nt < 4; nt++) {
            const int col = col0 + wn * 32 + nt * 8 + tg * 2;
            float2 v0 = make_float2(acc[am][nt][0] * INV_WSCALE, acc[am][nt][1] * INV_WSCALE);
            float2 v1 = make_float2(acc[am][nt][2] * INV_WSCALE, acc[am][nt][3] * INV_WSCALE);
            if (OUTPROJ) {
                const float bb0 = bias[col], bb1 = bias[col + 1];
                v0.x = z0 ? 0.0f : v0.x + bb0;  v0.y = z0 ? 0.0f : v0.y + bb1;
                v1.x = z1 ? 0.0f : v1.x + bb0;  v1.y = z1 ? 0.0f : v1.y + bb1;
            }
            if (HOUT) {
                __half* Ch = (__half*)Cv;
                *(__half2*)(Ch + (size_t)r0 * ldc + col) = __float22half2_rn(v0);
                *(__half2*)(Ch + (size_t)r1 * ldc + col) = __float22half2_rn(v1);
            } else {
                float* Cf = (float*)Cv;
                *(float2*)(Cf + (size_t)r0 * ldc + col) = v0;
                *(float2*)(Cf + (size_t)r1 * ldc + col) = v1;
            }
        }
    }
}

// Fused KV + Q projection: blocks [0,4096) = KV (fp16 out), [4096,4608) = Q (fp32).
__global__ void __launch_bounds__(512, 1)
fused_qkv_gemm()
{
    extern __shared__ char smem[];
    const uint32_t sb = smem_u32(smem);
    const int bid = blockIdx.x;
    if (bid < 4096) {
        const int bx = bid & 3, by = bid >> 2;
        gemm_core<false, true>(g_ef, g_wh + 512 * 512, g_wl + 512 * 512,
                               g_kv16, 1024, false, by * 128, bx * 256,
                               nullptr, nullptr, sb);
    } else {
        const int b2 = bid - 4096;
        const int bx = b2 & 1, by = b2 >> 1;
        gemm_core<false, false>(g_ef, g_wh, g_wl,
                                g_q, 512, true, by * 128, bx * 256,
                                nullptr, nullptr, sb);
    }
}

// Output projection: bias + post_mask epilogue, fp32 out.
__global__ void __launch_bounds__(512, 1)
out_gemm(float* __restrict__ Cout,
         const float* __restrict__ bias,
         const unsigned int* __restrict__ mask)
{
    extern __shared__ char smem[];
    const uint32_t sb = smem_u32(smem);
    gemm_core<true, false>(g_af, g_oh, g_ol, Cout, 512, false,
                           blockIdx.y * 128, blockIdx.x * 256, bias, mask, sb);
}

// ---------------------------------------------------------------------------
// Attention: one block per (batch, head). 128 threads. fp16 K/V, fp32 Q/math.
// smem ~27KB -> ~8 CTAs/SM.
// ---------------------------------------------------------------------------
__global__ void __launch_bounds__(128)
attn_kernel(const unsigned int* __restrict__ pre_mask)
{
    __shared__ float    qs[16][68];
    __shared__ uint32_t ks_u[64][36];   // 32 data uints (64 halves) + 4 pad
    __shared__ uint32_t vs_u[64][36];
    __shared__ float    at[16][68];

    const int b = blockIdx.x;
    const int h = blockIdx.y;
    const int tid = threadIdx.x;

    // Q tile (16x64 fp32)
#pragma unroll
    for (int rep = 0; rep < 2; rep++) {
        const int uu = tid + rep * 128;
        const int i = uu >> 4, d4 = uu & 15;
        *(float4*)&qs[i][d4 * 4] =
            *(const float4*)(g_q + ((size_t)(b * 16 + i)) * 512 + h * 64 + d4 * 4);
    }
    // K,V tiles (64x64 fp16): 8 x uint4 per row each
#pragma unroll
    for (int rep = 0; rep < 4; rep++) {
        const int u = tid + rep * 128;
        const int n = u >> 3, d8 = u & 7;
        const size_t base = ((size_t)(b * 64 + n)) * 1024 + h * 64 + d8 * 8;
        *(uint4*)&ks_u[n][d8 * 4] = *(const uint4*)(g_kv16 + base);
        *(uint4*)&vs_u[n][d8 * 4] = *(const uint4*)(g_kv16 + base + 512);
    }
    __syncthreads();

    const int i = tid >> 3;
    const int c = tid & 7;
    const unsigned int* pm = pre_mask + ((size_t)b * 64 + i) * 64;

    float lg[8];
    {
        float dacc[8] = {0, 0, 0, 0, 0, 0, 0, 0};
        for (int d4 = 0; d4 < 16; d4++) {
            const float4 q = *(const float4*)&qs[i][d4 * 4];
#pragma unroll
            for (int j = 0; j < 8; j++) {
                const uint2 kk = *(const uint2*)&ks_u[c + j * 8][d4 * 2];
                const float2 k01 = __half22float2(*(const __half2*)&kk.x);
                const float2 k23 = __half22float2(*(const __half2*)&kk.y);
                dacc[j] = fmaf(q.x, k01.x, dacc[j]);
                dacc[j] = fmaf(q.y, k01.y, dacc[j]);
                dacc[j] = fmaf(q.z, k23.x, dacc[j]);
                dacc[j] = fmaf(q.w, k23.y, dacc[j]);
            }
        }
        const float NI = neg_inf();
        float mx = NI;
#pragma unroll
        for (int j = 0; j < 8; j++) {
            lg[j] = (pm[c + j * 8] != 0u) ? NI : dacc[j] * 0.125f;
            mx = fmaxf(mx, lg[j]);
        }
        mx = fmaxf(mx, __shfl_xor_sync(0xffffffffu, mx, 1, 8));
        mx = fmaxf(mx, __shfl_xor_sync(0xffffffffu, mx, 2, 8));
        mx = fmaxf(mx, __shfl_xor_sync(0xffffffffu, mx, 4, 8));
        const bool any = (mx != NI);
        float sum = 0.0f;
#pragma unroll
        for (int j = 0; j < 8; j++) {
            const float e = any ? __expf(lg[j] - mx) : 0.0f;
            lg[j] = e;
            sum += e;
        }
        sum += __shfl_xor_sync(0xffffffffu, sum, 1, 8);
        sum += __shfl_xor_sync(0xffffffffu, sum, 2, 8);
        sum += __shfl_xor_sync(0xffffffffu, sum, 4, 8);
        const float inv = (sum > 0.0f) ? (1.0f / sum) : 0.0f;
#pragma unroll
        for (int j = 0; j < 8; j++)
            at[i][c + j * 8] = lg[j] * inv;
    }
    __syncthreads();

    // AV: thread owns d = c*8 .. c*8+7 (uints c*4..c*4+3)
    float o[8] = {0, 0, 0, 0, 0, 0, 0, 0};
#pragma unroll 8
    for (int n = 0; n < 64; n++) {
        const float a = at[i][n];
        const uint4 vv = *(const uint4*)&vs_u[n][c * 4];
        const float2 p0 = __half22float2(*(const __half2*)&vv.x);
        const float2 p1 = __half22float2(*(const __half2*)&vv.y);
        const float2 p2 = __half22float2(*(const __half2*)&vv.z);
        const float2 p3 = __half22float2(*(const __half2*)&vv.w);
        o[0] = fmaf(a, p0.x, o[0]); o[1] = fmaf(a, p0.y, o[1]);
        o[2] = fmaf(a, p1.x, o[2]); o[3] = fmaf(a, p1.y, o[3]);
        o[4] = fmaf(a, p2.x, o[4]); o[5] = fmaf(a, p2.y, o[5]);
        o[6] = fmaf(a, p3.x, o[6]); o[7] = fmaf(a, p3.y, o[7]);
    }
    uint4 pv;
    unsigned short s[8];
#pragma unroll
    for (int j = 0; j < 8; j++) s[j] = __half_as_ushort(__float2half_rn(o[j]));
    pv.x = (uint32_t)s[0] | ((uint32_t)s[1] << 16);
    pv.y = (uint32_t)s[2] | ((uint32_t)s[3] << 16);
    pv.z = (uint32_t)s[4] | ((uint32_t)s[5] << 16);
    pv.w = (uint32_t)s[6] | ((uint32_t)s[7] << 16);
    const size_t base = ((size_t)(b * 16 + i)) * 512 + h * 64 + c * 8;
    *(uint4*)(g_af + base) = pv;
}

// ---------------------------------------------------------------------------
extern "C" void kernel_launch(void* const* d_in, const int* in_sizes, int n_in,
                              void* d_out, int out_size)
{
    const float*        entities  = (const float*)d_in[0];
    const unsigned int* pre_mask  = (const unsigned int*)d_in[1];
    const unsigned int* post_mask = (const unsigned int*)d_in[2];
    const float*        W_in      = (const float*)d_in[3];
    const float*        W_out     = (const float*)d_in[4];
    const float*        b_out     = (const float*)d_in[5];
    float*              out       = (float*)d_out;

    cudaFuncSetAttribute(fused_qkv_gemm, cudaFuncAttributeMaxDynamicSharedMemorySize, GSMEM_TOTAL);
    cudaFuncSetAttribute(out_gemm,       cudaFuncAttributeMaxDynamicSharedMemorySize, GSMEM_TOTAL);

    // conversions: entities->fp16, weights->fp16 hi/lo (x512)
    split_all<<<9216, 256>>>(entities, W_in, W_out);

    // KV projection (fp16 out) + Q projection (fp32 out) fused
    fused_qkv_gemm<<<4608, 512, GSMEM_TOTAL>>>();

    // Attention (fp16 K/V)
    attn_kernel<<<dim3(BS, NHEAD), 128>>>(pre_mask);

    // Output projection + bias + post_mask
    out_gemm<<<dim3(2, 256), 512, GSMEM_TOTAL>>>(out, b_out, post_mask);
}

// round 13
// speedup vs baseline: 2.0304x; 1.3052x over previous
#include <cuda_runtime.h>
#include <cuda_fp16.h>
#include <math.h>
#include <stdint.h>

// Problem constants
#define BS      2048
#define NE      64
#define NQ      16
#define EMBED   512
#define NHEAD   8
#define HD      64

#define WSCALE     512.0f          // weights pre-scaled by 2^9 (exact)
#define INV_WSCALE (1.0f / 512.0f)

// ---------------------------------------------------------------------------
// Scratch (__device__ globals — allocation-free)
// ---------------------------------------------------------------------------
__device__ __half g_ef[(size_t)BS * NE * 512];    // entities fp16 (single)
__device__ __half g_wh[1536 * 512];               // W_in*512 hi
__device__ __half g_wl[1536 * 512];               // W_in*512 lo (Q rows only used)
__device__ __half g_oh[512 * 512];                // W_out*512 hi
__device__ __half g_ol[512 * 512];                // W_out*512 lo
__device__ float  g_q [(size_t)BS * NQ * 512];    // Q fp32 (accuracy headroom)
__device__ __half g_kv16[(size_t)BS * NE * 1024]; // K|V fp16 interleaved
__device__ __half g_af[(size_t)BS * NQ * 512];    // attn out fp16 (single)

__device__ __forceinline__ float neg_inf() { return __int_as_float(0xff800000u); }

__device__ __forceinline__ uint32_t smem_u32(const void* p) {
    uint32_t a;
    asm("{ .reg .u64 t; cvta.to.shared.u64 t, %1; cvt.u32.u64 %0, t; }" : "=r"(a) : "l"(p));
    return a;
}
#define SW128(bo) ((bo) ^ (((bo) >> 3) & 0x70))

#define CP_ASYNC16(dst, src) \
    asm volatile("cp.async.cg.shared.global [%0], [%1], 16;" :: "r"(dst), "l"(src) : "memory")
#define CP_COMMIT() asm volatile("cp.async.commit_group;" ::: "memory")
#define CP_WAIT0()  asm volatile("cp.async.wait_group 0;" ::: "memory")

#define BAR_SYNC(id, cnt) \
    asm volatile("bar.sync %0, %1;" :: "r"(id), "r"(cnt) : "memory")

#define LDMATRIX_X4(r0, r1, r2, r3, addr) \
    asm volatile("ldmatrix.sync.aligned.m8n8.x4.shared.b16 {%0,%1,%2,%3}, [%4];" \
        : "=r"(r0), "=r"(r1), "=r"(r2), "=r"(r3) : "r"(addr))

#define MMA_F16(c, a, b) \
    asm volatile("mma.sync.aligned.m16n8k16.row.col.f32.f16.f16.f32 " \
        "{%0,%1,%2,%3}, {%4,%5,%6,%7}, {%8,%9}, {%0,%1,%2,%3};" \
        : "+f"((c)[0]), "+f"((c)[1]), "+f"((c)[2]), "+f"((c)[3]) \
        : "r"((a)[0]), "r"((a)[1]), "r"((a)[2]), "r"((a)[3]), "r"((b)[0]), "r"((b)[1]))

// ---------------------------------------------------------------------------
// Merged conversion kernel:
//  entities -> fp16 single; W_in, W_out -> (fp16 hi, fp16 lo) of 512*W.
// ---------------------------------------------------------------------------
__global__ void __launch_bounds__(256)
split_all(const float* __restrict__ ent,
          const float* __restrict__ win,
          const float* __restrict__ wout)
{
    const int b = blockIdx.x;
    if (b < 8192) {                       // entities: fp32 -> fp16 single
        const int n4 = (BS * NE * 512) / 4;
        for (int i = b * 256 + threadIdx.x; i < n4; i += 8192 * 256) {
            const float4 v = ((const float4*)ent)[i];
            uint2 o;
            o.x = (uint32_t)__half_as_ushort(__float2half_rn(v.x)) |
                  ((uint32_t)__half_as_ushort(__float2half_rn(v.y)) << 16);
            o.y = (uint32_t)__half_as_ushort(__float2half_rn(v.z)) |
                  ((uint32_t)__half_as_ushort(__float2half_rn(v.w)) << 16);
            ((uint2*)g_ef)[i] = o;
        }
        return;
    }
    const float* src; __half *hi, *lo; int n4, lb, nb;
    if (b < 8960) { src = win;  hi = g_wh; lo = g_wl; n4 = (1536 * 512) / 4; lb = b - 8192; nb = 768; }
    else          { src = wout; hi = g_oh; lo = g_ol; n4 = (512 * 512) / 4;  lb = b - 8960; nb = 256; }

    for (int i = lb * 256 + threadIdx.x; i < n4; i += nb * 256) {
        const float4 v = ((const float4*)src)[i];
        float f[4] = {v.x * WSCALE, v.y * WSCALE, v.z * WSCALE, v.w * WSCALE};
        unsigned short hs[4], ls[4];
#pragma unroll
        for (int j = 0; j < 4; j++) {
            const __half hb = __float2half_rn(f[j]);
            hs[j] = __half_as_ushort(hb);
            ls[j] = __half_as_ushort(__float2half_rn(f[j] - __half2float(hb)));
        }
        uint2 hv, lv;
        hv.x = (uint32_t)hs[0] | ((uint32_t)hs[1] << 16);
        hv.y = (uint32_t)hs[2] | ((uint32_t)hs[3] << 16);
        lv.x = (uint32_t)ls[0] | ((uint32_t)ls[1] << 16);
        lv.y = (uint32_t)ls[2] | ((uint32_t)ls[3] << 16);
        ((uint2*)hi)[i] = hv;
        ((uint2*)lo)[i] = lv;
    }
}

// ---------------------------------------------------------------------------
// GEMM core: fp16 x NTERMS (A*Bh [+ A*Bl], fp32 accum; B pre-scaled by 512,
// epilogue multiplies by 1/512). CTA tile 128x256, 512 threads, warp 64x32.
// BK=64, SW128. Stage: A 16K | Bh 32K | Bl 32K, 2 stages = 160KB.
// Privatized loads + named barriers. HOUT: write fp16 half2 (KV path).
// ---------------------------------------------------------------------------
#define A_STAGE  16384
#define B_STAGE  65536
#define B_BASE   (2 * A_STAGE)
#define OFF_BL   32768
#define GSMEM_TOTAL (B_BASE + 2 * B_STAGE)   // 160KB
#define NITER 8

template <bool OUTPROJ, bool HOUT, bool TWOTERM>
__device__ __forceinline__ void gemm_core(
    const __half* __restrict__ Afp,
    const __half* __restrict__ Bhp, const __half* __restrict__ Blp,
    void* __restrict__ Cv, int ldc, bool gatherQ, int row0, int col0,
    const float* __restrict__ bias, const unsigned int* __restrict__ mask,
    uint32_t sb)
{
    const int tid  = threadIdx.x;
    const int wid  = tid >> 5;
    const int lane = tid & 31;
    const int wm   = wid >> 3;
    const int wn   = wid & 7;
    const int htid = tid & 255;
    const int ptid = ((tid >> 8) << 5) | (tid & 31);

    float acc[4][4][4];
#pragma unroll
    for (int i = 0; i < 4; i++)
#pragma unroll
        for (int j = 0; j < 4; j++)
#pragma unroll
            for (int k = 0; k < 4; k++) acc[i][j][k] = 0.0f;

    auto issue_load = [&](int t) {
        const int kc = t * 64;
        const uint32_t stA = sb + (uint32_t)(t & 1) * A_STAGE;
        const uint32_t stB = sb + B_BASE + (uint32_t)(t & 1) * B_STAGE;
#pragma unroll
        for (int i = 0; i < 2; i++) {
            const int u = htid + i * 256;
            const int r = u >> 3, c = u & 7;
            const int rf = wm * 64 + r;
            const int gr = row0 + rf;
            const int ar = gatherQ ? (((gr >> 4) << 6) + (gr & 15)) : gr;
            const uint32_t sw = SW128((uint32_t)(rf * 128 + c * 16));
            CP_ASYNC16(stA + sw, Afp + (size_t)ar * 512 + kc + c * 8);
        }
#pragma unroll
        for (int i = 0; i < 4; i++) {
            const int u = ptid + i * 64;
            const int r = u >> 3, c = u & 7;
            const int rf = wn * 32 + r;
            const uint32_t sw = SW128((uint32_t)(rf * 128 + c * 16));
            CP_ASYNC16(stB + sw, Bhp + (size_t)(col0 + rf) * 512 + kc + c * 8);
            if (TWOTERM)
                CP_ASYNC16(stB + OFF_BL + sw, Blp + (size_t)(col0 + rf) * 512 + kc + c * 8);
        }
        CP_COMMIT();
    };

    issue_load(0);

    const int l8   = lane & 7;
    const int lsel = lane >> 3;

    for (int t = 0; t < NITER; t++) {
        CP_WAIT0();
        BAR_SYNC(1 + wm, 256);
        BAR_SYNC(3 + wn, 64);
        if (t + 1 < NITER) issue_load(t + 1);

        const uint32_t stA = sb + (uint32_t)(t & 1) * A_STAGE;
        const uint32_t stB = sb + B_BASE + (uint32_t)(t & 1) * B_STAGE;

#pragma unroll
        for (int ks = 0; ks < 4; ks++) {
            const int ra = wm * 64 + l8 + (lsel & 1) * 8;
            const int ca = ks * 2 + (lsel >> 1);
            const int rb = wn * 32 + (lsel >> 1) * 8 + l8;
            const int cb = ks * 2 + (lsel & 1);

            uint32_t a[4][4], bh[4][2], bl[4][2];
#pragma unroll
            for (int am = 0; am < 4; am++) {
                const int r = ra + am * 16;
                const uint32_t off = (uint32_t)(r * 128 + ((ca ^ (r & 7)) << 4));
                LDMATRIX_X4(a[am][0], a[am][1], a[am][2], a[am][3], stA + off);
            }
#pragma unroll
            for (int bp = 0; bp < 2; bp++) {
                const int r = rb + bp * 16;
                const uint32_t off = (uint32_t)(r * 128 + ((cb ^ (r & 7)) << 4));
                LDMATRIX_X4(bh[2 * bp][0], bh[2 * bp][1], bh[2 * bp + 1][0], bh[2 * bp + 1][1],
                            stB + off);
            }
#pragma unroll
            for (int am = 0; am < 4; am++)
#pragma unroll
                for (int nt = 0; nt < 4; nt++)
                    MMA_F16(acc[am][nt], a[am], bh[nt]);
            if (TWOTERM) {
#pragma unroll
                for (int bp = 0; bp < 2; bp++) {
                    const int r = rb + bp * 16;
                    const uint32_t off = (uint32_t)(r * 128 + ((cb ^ (r & 7)) << 4));
                    LDMATRIX_X4(bl[2 * bp][0], bl[2 * bp][1], bl[2 * bp + 1][0], bl[2 * bp + 1][1],
                                stB + OFF_BL + off);
                }
#pragma unroll
                for (int am = 0; am < 4; am++)
#pragma unroll
                    for (int nt = 0; nt < 4; nt++)
                        MMA_F16(acc[am][nt], a[am], bl[nt]);
            }
        }
    }

    // ---- epilogue: unscale by 1/512; fp16 or fp32 output ----
    const int g  = lane >> 2;
    const int tg = lane & 3;
#pragma unroll
    for (int am = 0; am < 4; am++) {
        const int r0 = row0 + wm * 64 + am * 16 + g;
        const int r1 = r0 + 8;
        bool z0 = false, z1 = false;
        if (OUTPROJ) { z0 = (mask[r0] != 0u); z1 = (mask[r1] != 0u); }
#pragma unroll
        for (int nt = 0; nt < 4; nt++) {
            const int col = col0 + wn * 32 + nt * 8 + tg * 2;
            float2 v0 = make_float2(acc[am][nt][0] * INV_WSCALE, acc[am][nt][1] * INV_WSCALE);
            float2 v1 = make_float2(acc[am][nt][2] * INV_WSCALE, acc[am][nt][3] * INV_WSCALE);
            if (OUTPROJ) {
                const float bb0 = bias[col], bb1 = bias[col + 1];
                v0.x = z0 ? 0.0f : v0.x + bb0;  v0.y = z0 ? 0.0f : v0.y + bb1;
                v1.x = z1 ? 0.0f : v1.x + bb0;  v1.y = z1 ? 0.0f : v1.y + bb1;
            }
            if (HOUT) {
                __half* Ch = (__half*)Cv;
                *(__half2*)(Ch + (size_t)r0 * ldc + col) = __float22half2_rn(v0);
                *(__half2*)(Ch + (size_t)r1 * ldc + col) = __float22half2_rn(v1);
            } else {
                float* Cf = (float*)Cv;
                *(float2*)(Cf + (size_t)r0 * ldc + col) = v0;
                *(float2*)(Cf + (size_t)r1 * ldc + col) = v1;
            }
        }
    }
}

// Fused KV + Q projection: blocks [0,4096) = KV (fp16 out, 1-term),
// [4096,4608) = Q (fp32 out, 2-term exact weights).
__global__ void __launch_bounds__(512, 1)
fused_qkv_gemm()
{
    extern __shared__ char smem[];
    const uint32_t sb = smem_u32(smem);
    const int bid = blockIdx.x;
    if (bid < 4096) {
        const int bx = bid & 3, by = bid >> 2;
        gemm_core<false, true, false>(g_ef, g_wh + 512 * 512, nullptr,
                                      g_kv16, 1024, false, by * 128, bx * 256,
                                      nullptr, nullptr, sb);
    } else {
        const int b2 = bid - 4096;
        const int bx = b2 & 1, by = b2 >> 1;
        gemm_core<false, false, true>(g_ef, g_wh, g_wl,
                                      g_q, 512, true, by * 128, bx * 256,
                                      nullptr, nullptr, sb);
    }
}

// Output projection: bias + post_mask epilogue, fp32 out, 2-term.
__global__ void __launch_bounds__(512, 1)
out_gemm(float* __restrict__ Cout,
         const float* __restrict__ bias,
         const unsigned int* __restrict__ mask)
{
    extern __shared__ char smem[];
    const uint32_t sb = smem_u32(smem);
    gemm_core<true, false, true>(g_af, g_oh, g_ol, Cout, 512, false,
                                 blockIdx.y * 128, blockIdx.x * 256, bias, mask, sb);
}

// ---------------------------------------------------------------------------
// Attention: one block per (batch, head). 128 threads. fp16 K/V, fp32 Q/math.
// ---------------------------------------------------------------------------
__global__ void __launch_bounds__(128)
attn_kernel(const unsigned int* __restrict__ pre_mask)
{
    __shared__ float    qs[16][68];
    __shared__ uint32_t ks_u[64][36];
    __shared__ uint32_t vs_u[64][36];
    __shared__ float    at[16][68];

    const int b = blockIdx.x;
    const int h = blockIdx.y;
    const int tid = threadIdx.x;

#pragma unroll
    for (int rep = 0; rep < 2; rep++) {
        const int uu = tid + rep * 128;
        const int i = uu >> 4, d4 = uu & 15;
        *(float4*)&qs[i][d4 * 4] =
            *(const float4*)(g_q + ((size_t)(b * 16 + i)) * 512 + h * 64 + d4 * 4);
    }
#pragma unroll
    for (int rep = 0; rep < 4; rep++) {
        const int u = tid + rep * 128;
        const int n = u >> 3, d8 = u & 7;
        const size_t base = ((size_t)(b * 64 + n)) * 1024 + h * 64 + d8 * 8;
        *(uint4*)&ks_u[n][d8 * 4] = *(const uint4*)(g_kv16 + base);
        *(uint4*)&vs_u[n][d8 * 4] = *(const uint4*)(g_kv16 + base + 512);
    }
    __syncthreads();

    const int i = tid >> 3;
    const int c = tid & 7;
    const unsigned int* pm = pre_mask + ((size_t)b * 64 + i) * 64;

    float lg[8];
    {
        float dacc[8] = {0, 0, 0, 0, 0, 0, 0, 0};
        for (int d4 = 0; d4 < 16; d4++) {
            const float4 q = *(const float4*)&qs[i][d4 * 4];
#pragma unroll
            for (int j = 0; j < 8; j++) {
                const uint2 kk = *(const uint2*)&ks_u[c + j * 8][d4 * 2];
                const float2 k01 = __half22float2(*(const __half2*)&kk.x);
                const float2 k23 = __half22float2(*(const __half2*)&kk.y);
                dacc[j] = fmaf(q.x, k01.x, dacc[j]);
                dacc[j] = fmaf(q.y, k01.y, dacc[j]);
                dacc[j] = fmaf(q.z, k23.x, dacc[j]);
                dacc[j] = fmaf(q.w, k23.y, dacc[j]);
            }
        }
        const float NI = neg_inf();
        float mx = NI;
#pragma unroll
        for (int j = 0; j < 8; j++) {
            lg[j] = (pm[c + j * 8] != 0u) ? NI : dacc[j] * 0.125f;
            mx = fmaxf(mx, lg[j]);
        }
        mx = fmaxf(mx, __shfl_xor_sync(0xffffffffu, mx, 1, 8));
        mx = fmaxf(mx, __shfl_xor_sync(0xffffffffu, mx, 2, 8));
        mx = fmaxf(mx, __shfl_xor_sync(0xffffffffu, mx, 4, 8));
        const bool any = (mx != NI);
        float sum = 0.0f;
#pragma unroll
        for (int j = 0; j < 8; j++) {
            const float e = any ? __expf(lg[j] - mx) : 0.0f;
            lg[j] = e;
            sum += e;
        }
        sum += __shfl_xor_sync(0xffffffffu, sum, 1, 8);
        sum += __shfl_xor_sync(0xffffffffu, sum, 2, 8);
        sum += __shfl_xor_sync(0xffffffffu, sum, 4, 8);
        const float inv = (sum > 0.0f) ? (1.0f / sum) : 0.0f;
#pragma unroll
        for (int j = 0; j < 8; j++)
            at[i][c + j * 8] = lg[j] * inv;
    }
    __syncthreads();

    float o[8] = {0, 0, 0, 0, 0, 0, 0, 0};
#pragma unroll 8
    for (int n = 0; n < 64; n++) {
        const float a = at[i][n];
        const uint4 vv = *(const uint4*)&vs_u[n][c * 4];
        const float2 p0 = __half22float2(*(const __half2*)&vv.x);
        const float2 p1 = __half22float2(*(const __half2*)&vv.y);
        const float2 p2 = __half22float2(*(const __half2*)&vv.z);
        const float2 p3 = __half22float2(*(const __half2*)&vv.w);
        o[0] = fmaf(a, p0.x, o[0]); o[1] = fmaf(a, p0.y, o[1]);
        o[2] = fmaf(a, p1.x, o[2]); o[3] = fmaf(a, p1.y, o[3]);
        o[4] = fmaf(a, p2.x, o[4]); o[5] = fmaf(a, p2.y, o[5]);
        o[6] = fmaf(a, p3.x, o[6]); o[7] = fmaf(a, p3.y, o[7]);
    }
    uint4 pv;
    unsigned short s[8];
#pragma unroll
    for (int j = 0; j < 8; j++) s[j] = __half_as_ushort(__float2half_rn(o[j]));
    pv.x = (uint32_t)s[0] | ((uint32_t)s[1] << 16);
    pv.y = (uint32_t)s[2] | ((uint32_t)s[3] << 16);
    pv.z = (uint32_t)s[4] | ((uint32_t)s[5] << 16);
    pv.w = (uint32_t)s[6] | ((uint32_t)s[7] << 16);
    const size_t base = ((size_t)(b * 16 + i)) * 512 + h * 64 + c * 8;
    *(uint4*)(g_af + base) = pv;
}

// ---------------------------------------------------------------------------
extern "C" void kernel_launch(void* const* d_in, const int* in_sizes, int n_in,
                              void* d_out, int out_size)
{
    const float*        entities  = (const float*)d_in[0];
    const unsigned int* pre_mask  = (const unsigned int*)d_in[1];
    const unsigned int* post_mask = (const unsigned int*)d_in[2];
    const float*        W_in      = (const float*)d_in[3];
    const float*        W_out     = (const float*)d_in[4];
    const float*        b_out     = (const float*)d_in[5];
    float*              out       = (float*)d_out;

    cudaFuncSetAttribute(fused_qkv_gemm, cudaFuncAttributeMaxDynamicSharedMemorySize, GSMEM_TOTAL);
    cudaFuncSetAttribute(out_gemm,       cudaFuncAttributeMaxDynamicSharedMemorySize, GSMEM_TOTAL);

    // conversions: entities->fp16, weights->fp16 hi/lo (x512)
    split_all<<<9216, 256>>>(entities, W_in, W_out);

    // KV projection (fp16 out, 1-term) + Q projection (fp32 out, 2-term) fused
    fused_qkv_gemm<<<4608, 512, GSMEM_TOTAL>>>();

    // Attention (fp16 K/V)
    attn_kernel<<<dim3(BS, NHEAD), 128>>>(pre_mask);

    // Output projection + bias + post_mask
    out_gemm<<<dim3(2, 256), 512, GSMEM_TOTAL>>>(out, b_out, post_mask);
}

// round 14
// speedup vs baseline: 2.1561x; 1.0619x over previous
#include <cuda_runtime.h>
#include <cuda_fp16.h>
#include <math.h>
#include <stdint.h>

// Problem constants
#define BS      2048
#define NE      64
#define NQ      16
#define EMBED   512
#define NHEAD   8
#define HD      64

#define WSCALE     512.0f          // weights pre-scaled by 2^9 (exact)
#define INV_WSCALE (1.0f / 512.0f)

// ---------------------------------------------------------------------------
// Scratch (__device__ globals — allocation-free)
// ---------------------------------------------------------------------------
__device__ __half g_ef[(size_t)BS * NE * 512];    // entities fp16 (single)
__device__ __half g_wh[1536 * 512];               // W_in*512 hi
__device__ __half g_wl[1536 * 512];               // W_in*512 lo (Q rows used)
__device__ __half g_oh[512 * 512];                // W_out*512 hi (single term)
__device__ __half g_q16[(size_t)BS * NQ * 512];   // Q fp16
__device__ __half g_kv16[(size_t)BS * NE * 1024]; // K|V fp16 interleaved
__device__ __half g_af[(size_t)BS * NQ * 512];    // attn out fp16

__device__ __forceinline__ float neg_inf() { return __int_as_float(0xff800000u); }

__device__ __forceinline__ uint32_t smem_u32(const void* p) {
    uint32_t a;
    asm("{ .reg .u64 t; cvta.to.shared.u64 t, %1; cvt.u32.u64 %0, t; }" : "=r"(a) : "l"(p));
    return a;
}
#define SW128(bo) ((bo) ^ (((bo) >> 3) & 0x70))

#define CP_ASYNC16(dst, src) \
    asm volatile("cp.async.cg.shared.global [%0], [%1], 16;" :: "r"(dst), "l"(src) : "memory")
#define CP_COMMIT() asm volatile("cp.async.commit_group;" ::: "memory")
#define CP_WAIT0()  asm volatile("cp.async.wait_group 0;" ::: "memory")

#define BAR_SYNC(id, cnt) \
    asm volatile("bar.sync %0, %1;" :: "r"(id), "r"(cnt) : "memory")

#define LDMATRIX_X4(r0, r1, r2, r3, addr) \
    asm volatile("ldmatrix.sync.aligned.m8n8.x4.shared.b16 {%0,%1,%2,%3}, [%4];" \
        : "=r"(r0), "=r"(r1), "=r"(r2), "=r"(r3) : "r"(addr))

#define MMA_F16(c, a, b) \
    asm volatile("mma.sync.aligned.m16n8k16.row.col.f32.f16.f16.f32 " \
        "{%0,%1,%2,%3}, {%4,%5,%6,%7}, {%8,%9}, {%0,%1,%2,%3};" \
        : "+f"((c)[0]), "+f"((c)[1]), "+f"((c)[2]), "+f"((c)[3]) \
        : "r"((a)[0]), "r"((a)[1]), "r"((a)[2]), "r"((a)[3]), "r"((b)[0]), "r"((b)[1]))

// ---------------------------------------------------------------------------
// Merged conversion kernel:
//  entities -> fp16 single; W_in -> (hi, lo) of 512*W; W_out -> hi only.
// ---------------------------------------------------------------------------
__global__ void __launch_bounds__(256)
split_all(const float* __restrict__ ent,
          const float* __restrict__ win,
          const float* __restrict__ wout)
{
    const int b = blockIdx.x;
    if (b < 8192) {                       // entities: fp32 -> fp16 single
        const int n4 = (BS * NE * 512) / 4;
        for (int i = b * 256 + threadIdx.x; i < n4; i += 8192 * 256) {
            const float4 v = ((const float4*)ent)[i];
            uint2 o;
            o.x = (uint32_t)__half_as_ushort(__float2half_rn(v.x)) |
                  ((uint32_t)__half_as_ushort(__float2half_rn(v.y)) << 16);
            o.y = (uint32_t)__half_as_ushort(__float2half_rn(v.z)) |
                  ((uint32_t)__half_as_ushort(__float2half_rn(v.w)) << 16);
            ((uint2*)g_ef)[i] = o;
        }
        return;
    }
    if (b < 8960) {                       // W_in: hi + lo (x512)
        const int n4 = (1536 * 512) / 4;
        for (int i = (b - 8192) * 256 + threadIdx.x; i < n4; i += 768 * 256) {
            const float4 v = ((const float4*)win)[i];
            float f[4] = {v.x * WSCALE, v.y * WSCALE, v.z * WSCALE, v.w * WSCALE};
            unsigned short hs[4], ls[4];
#pragma unroll
            for (int j = 0; j < 4; j++) {
                const __half hb = __float2half_rn(f[j]);
                hs[j] = __half_as_ushort(hb);
                ls[j] = __half_as_ushort(__float2half_rn(f[j] - __half2float(hb)));
            }
            uint2 hv, lv;
            hv.x = (uint32_t)hs[0] | ((uint32_t)hs[1] << 16);
            hv.y = (uint32_t)hs[2] | ((uint32_t)hs[3] << 16);
            lv.x = (uint32_t)ls[0] | ((uint32_t)ls[1] << 16);
            lv.y = (uint32_t)ls[2] | ((uint32_t)ls[3] << 16);
            ((uint2*)g_wh)[i] = hv;
            ((uint2*)g_wl)[i] = lv;
        }
        return;
    }
    // W_out: hi only (x512)
    const int n4 = (512 * 512) / 4;
    for (int i = (b - 8960) * 256 + threadIdx.x; i < n4; i += 256 * 256) {
        const float4 v = ((const float4*)wout)[i];
        uint2 hv;
        hv.x = (uint32_t)__half_as_ushort(__float2half_rn(v.x * WSCALE)) |
               ((uint32_t)__half_as_ushort(__float2half_rn(v.y * WSCALE)) << 16);
        hv.y = (uint32_t)__half_as_ushort(__float2half_rn(v.z * WSCALE)) |
               ((uint32_t)__half_as_ushort(__float2half_rn(v.w * WSCALE)) << 16);
        ((uint2*)g_oh)[i] = hv;
    }
}

// ---------------------------------------------------------------------------
// GEMM core: fp16 x {1,2} terms (A*Bh [+ A*Bl], fp32 accum; B pre-scaled by
// 512, epilogue multiplies 1/512). CTA 128x256, 512 threads, warp 64x32.
// BK=64, SW128. Stage: A 16K | Bh 32K | Bl 32K, 2 stages = 160KB.
// Privatized loads + named barriers. HOUT: fp16 half2 output.
// ---------------------------------------------------------------------------
#define A_STAGE  16384
#define B_STAGE  65536
#define B_BASE   (2 * A_STAGE)
#define OFF_BL   32768
#define GSMEM_TOTAL (B_BASE + 2 * B_STAGE)   // 160KB
#define NITER 8

template <bool OUTPROJ, bool HOUT, bool TWOTERM>
__device__ __forceinline__ void gemm_core(
    const __half* __restrict__ Afp,
    const __half* __restrict__ Bhp, const __half* __restrict__ Blp,
    void* __restrict__ Cv, int ldc, bool gatherQ, int row0, int col0,
    const float* __restrict__ bias, const unsigned int* __restrict__ mask,
    uint32_t sb)
{
    const int tid  = threadIdx.x;
    const int wid  = tid >> 5;
    const int lane = tid & 31;
    const int wm   = wid >> 3;
    const int wn   = wid & 7;
    const int htid = tid & 255;
    const int ptid = ((tid >> 8) << 5) | (tid & 31);

    float acc[4][4][4];
#pragma unroll
    for (int i = 0; i < 4; i++)
#pragma unroll
        for (int j = 0; j < 4; j++)
#pragma unroll
            for (int k = 0; k < 4; k++) acc[i][j][k] = 0.0f;

    auto issue_load = [&](int t) {
        const int kc = t * 64;
        const uint32_t stA = sb + (uint32_t)(t & 1) * A_STAGE;
        const uint32_t stB = sb + B_BASE + (uint32_t)(t & 1) * B_STAGE;
#pragma unroll
        for (int i = 0; i < 2; i++) {
            const int u = htid + i * 256;
            const int r = u >> 3, c = u & 7;
            const int rf = wm * 64 + r;
            const int gr = row0 + rf;
            const int ar = gatherQ ? (((gr >> 4) << 6) + (gr & 15)) : gr;
            const uint32_t sw = SW128((uint32_t)(rf * 128 + c * 16));
            CP_ASYNC16(stA + sw, Afp + (size_t)ar * 512 + kc + c * 8);
        }
#pragma unroll
        for (int i = 0; i < 4; i++) {
            const int u = ptid + i * 64;
            const int r = u >> 3, c = u & 7;
            const int rf = wn * 32 + r;
            const uint32_t sw = SW128((uint32_t)(rf * 128 + c * 16));
            CP_ASYNC16(stB + sw, Bhp + (size_t)(col0 + rf) * 512 + kc + c * 8);
            if (TWOTERM)
                CP_ASYNC16(stB + OFF_BL + sw, Blp + (size_t)(col0 + rf) * 512 + kc + c * 8);
        }
        CP_COMMIT();
    };

    issue_load(0);

    const int l8   = lane & 7;
    const int lsel = lane >> 3;

    for (int t = 0; t < NITER; t++) {
        CP_WAIT0();
        BAR_SYNC(1 + wm, 256);
        BAR_SYNC(3 + wn, 64);
        if (t + 1 < NITER) issue_load(t + 1);

        const uint32_t stA = sb + (uint32_t)(t & 1) * A_STAGE;
        const uint32_t stB = sb + B_BASE + (uint32_t)(t & 1) * B_STAGE;

#pragma unroll
        for (int ks = 0; ks < 4; ks++) {
            const int ra = wm * 64 + l8 + (lsel & 1) * 8;
            const int ca = ks * 2 + (lsel >> 1);
            const int rb = wn * 32 + (lsel >> 1) * 8 + l8;
            const int cb = ks * 2 + (lsel & 1);

            uint32_t a[4][4], bh[4][2], bl[4][2];
#pragma unroll
            for (int am = 0; am < 4; am++) {
                const int r = ra + am * 16;
                const uint32_t off = (uint32_t)(r * 128 + ((ca ^ (r & 7)) << 4));
                LDMATRIX_X4(a[am][0], a[am][1], a[am][2], a[am][3], stA + off);
            }
#pragma unroll
            for (int bp = 0; bp < 2; bp++) {
                const int r = rb + bp * 16;
                const uint32_t off = (uint32_t)(r * 128 + ((cb ^ (r & 7)) << 4));
                LDMATRIX_X4(bh[2 * bp][0], bh[2 * bp][1], bh[2 * bp + 1][0], bh[2 * bp + 1][1],
                            stB + off);
            }
#pragma unroll
            for (int am = 0; am < 4; am++)
#pragma unroll
                for (int nt = 0; nt < 4; nt++)
                    MMA_F16(acc[am][nt], a[am], bh[nt]);
            if (TWOTERM) {
#pragma unroll
                for (int bp = 0; bp < 2; bp++) {
                    const int r = rb + bp * 16;
                    const uint32_t off = (uint32_t)(r * 128 + ((cb ^ (r & 7)) << 4));
                    LDMATRIX_X4(bl[2 * bp][0], bl[2 * bp][1], bl[2 * bp + 1][0], bl[2 * bp + 1][1],
                                stB + OFF_BL + off);
                }
#pragma unroll
                for (int am = 0; am < 4; am++)
#pragma unroll
                    for (int nt = 0; nt < 4; nt++)
                        MMA_F16(acc[am][nt], a[am], bl[nt]);
            }
        }
    }

    // ---- epilogue: unscale by 1/512; fp16 or fp32 output ----
    const int g  = lane >> 2;
    const int tg = lane & 3;
#pragma unroll
    for (int am = 0; am < 4; am++) {
        const int r0 = row0 + wm * 64 + am * 16 + g;
        const int r1 = r0 + 8;
        bool z0 = false, z1 = false;
        if (OUTPROJ) { z0 = (mask[r0] != 0u); z1 = (mask[r1] != 0u); }
#pragma unroll
        for (int nt = 0; nt < 4; nt++) {
            const int col = col0 + wn * 32 + nt * 8 + tg * 2;
            float2 v0 = make_float2(acc[am][nt][0] * INV_WSCALE, acc[am][nt][1] * INV_WSCALE);
            float2 v1 = make_float2(acc[am][nt][2] * INV_WSCALE, acc[am][nt][3] * INV_WSCALE);
            if (OUTPROJ) {
                const float bb0 = bias[col], bb1 = bias[col + 1];
                v0.x = z0 ? 0.0f : v0.x + bb0;  v0.y = z0 ? 0.0f : v0.y + bb1;
                v1.x = z1 ? 0.0f : v1.x + bb0;  v1.y = z1 ? 0.0f : v1.y + bb1;
            }
            if (HOUT) {
                __half* Ch = (__half*)Cv;
                *(__half2*)(Ch + (size_t)r0 * ldc + col) = __float22half2_rn(v0);
                *(__half2*)(Ch + (size_t)r1 * ldc + col) = __float22half2_rn(v1);
            } else {
                float* Cf = (float*)Cv;
                *(float2*)(Cf + (size_t)r0 * ldc + col) = v0;
                *(float2*)(Cf + (size_t)r1 * ldc + col) = v1;
            }
        }
    }
}

// Fused KV + Q projection: blocks [0,4096) = KV (fp16 out, 1-term),
// [4096,4608) = Q (fp16 out, 2-term exact weights).
__global__ void __launch_bounds__(512, 1)
fused_qkv_gemm()
{
    extern __shared__ char smem[];
    const uint32_t sb = smem_u32(smem);
    const int bid = blockIdx.x;
    if (bid < 4096) {
        const int bx = bid & 3, by = bid >> 2;
        gemm_core<false, true, false>(g_ef, g_wh + 512 * 512, nullptr,
                                      g_kv16, 1024, false, by * 128, bx * 256,
                                      nullptr, nullptr, sb);
    } else {
        const int b2 = bid - 4096;
        const int bx = b2 & 1, by = b2 >> 1;
        gemm_core<false, true, true>(g_ef, g_wh, g_wl,
                                     g_q16, 512, true, by * 128, bx * 256,
                                     nullptr, nullptr, sb);
    }
}

// Output projection: bias + post_mask epilogue, fp32 out, 1-term.
__global__ void __launch_bounds__(512, 1)
out_gemm(float* __restrict__ Cout,
         const float* __restrict__ bias,
         const unsigned int* __restrict__ mask)
{
    extern __shared__ char smem[];
    const uint32_t sb = smem_u32(smem);
    gemm_core<true, false, false>(g_af, g_oh, nullptr, Cout, 512, false,
                                  blockIdx.y * 128, blockIdx.x * 256, bias, mask, sb);
}

// ---------------------------------------------------------------------------
// Attention: one block per (batch, head). 128 threads. fp16 Q/K/V, fp32 math.
// ---------------------------------------------------------------------------
__global__ void __launch_bounds__(128)
attn_kernel(const unsigned int* __restrict__ pre_mask)
{
    __shared__ uint32_t qs_u[16][36];   // 32 data uints (64 halves) + 4 pad
    __shared__ uint32_t ks_u[64][36];
    __shared__ uint32_t vs_u[64][36];
    __shared__ float    at[16][68];

    const int b = blockIdx.x;
    const int h = blockIdx.y;
    const int tid = threadIdx.x;

    // Q tile (16x64 fp16): 128 uint4, 1 per thread
    {
        const int i = tid >> 3, d8 = tid & 7;
        *(uint4*)&qs_u[i][d8 * 4] =
            *(const uint4*)(g_q16 + ((size_t)(b * 16 + i)) * 512 + h * 64 + d8 * 8);
    }
    // K,V tiles (64x64 fp16): 8 x uint4 per row each
#pragma unroll
    for (int rep = 0; rep < 4; rep++) {
        const int u = tid + rep * 128;
        const int n = u >> 3, d8 = u & 7;
        const size_t base = ((size_t)(b * 64 + n)) * 1024 + h * 64 + d8 * 8;
        *(uint4*)&ks_u[n][d8 * 4] = *(const uint4*)(g_kv16 + base);
        *(uint4*)&vs_u[n][d8 * 4] = *(const uint4*)(g_kv16 + base + 512);
    }
    __syncthreads();

    const int i = tid >> 3;
    const int c = tid & 7;
    const unsigned int* pm = pre_mask + ((size_t)b * 64 + i) * 64;

    float lg[8];
    {
        float dacc[8] = {0, 0, 0, 0, 0, 0, 0, 0};
        for (int d4 = 0; d4 < 16; d4++) {
            const uint2 qq = *(const uint2*)&qs_u[i][d4 * 2];
            const float2 q01 = __half22float2(*(const __half2*)&qq.x);
            const float2 q23 = __half22float2(*(const __half2*)&qq.y);
#pragma unroll
            for (int j = 0; j < 8; j++) {
                const uint2 kk = *(const uint2*)&ks_u[c + j * 8][d4 * 2];
                const float2 k01 = __half22float2(*(const __half2*)&kk.x);
                const float2 k23 = __half22float2(*(const __half2*)&kk.y);
                dacc[j] = fmaf(q01.x, k01.x, dacc[j]);
                dacc[j] = fmaf(q01.y, k01.y, dacc[j]);
                dacc[j] = fmaf(q23.x, k23.x, dacc[j]);
                dacc[j] = fmaf(q23.y, k23.y, dacc[j]);
            }
        }
        const float NI = neg_inf();
        float mx = NI;
#pragma unroll
        for (int j = 0; j < 8; j++) {
            lg[j] = (pm[c + j * 8] != 0u) ? NI : dacc[j] * 0.125f;
            mx = fmaxf(mx, lg[j]);
        }
        mx = fmaxf(mx, __shfl_xor_sync(0xffffffffu, mx, 1, 8));
        mx = fmaxf(mx, __shfl_xor_sync(0xffffffffu, mx, 2, 8));
        mx = fmaxf(mx, __shfl_xor_sync(0xffffffffu, mx, 4, 8));
        const bool any = (mx != NI);
        float sum = 0.0f;
#pragma unroll
        for (int j = 0; j < 8; j++) {
            const float e = any ? __expf(lg[j] - mx) : 0.0f;
            lg[j] = e;
            sum += e;
        }
        sum += __shfl_xor_sync(0xffffffffu, sum, 1, 8);
        sum += __shfl_xor_sync(0xffffffffu, sum, 2, 8);
        sum += __shfl_xor_sync(0xffffffffu, sum, 4, 8);
        const float inv = (sum > 0.0f) ? (1.0f / sum) : 0.0f;
#pragma unroll
        for (int j = 0; j < 8; j++)
            at[i][c + j * 8] = lg[j] * inv;
    }
    __syncthreads();

    float o[8] = {0, 0, 0, 0, 0, 0, 0, 0};
#pragma unroll 8
    for (int n = 0; n < 64; n++) {
        const float a = at[i][n];
        const uint4 vv = *(const uint4*)&vs_u[n][c * 4];
        const float2 p0 = __half22float2(*(const __half2*)&vv.x);
        const float2 p1 = __half22float2(*(const __half2*)&vv.y);
        const float2 p2 = __half22float2(*(const __half2*)&vv.z);
        const float2 p3 = __half22float2(*(const __half2*)&vv.w);
        o[0] = fmaf(a, p0.x, o[0]); o[1] = fmaf(a, p0.y, o[1]);
        o[2] = fmaf(a, p1.x, o[2]); o[3] = fmaf(a, p1.y, o[3]);
        o[4] = fmaf(a, p2.x, o[4]); o[5] = fmaf(a, p2.y, o[5]);
        o[6] = fmaf(a, p3.x, o[6]); o[7] = fmaf(a, p3.y, o[7]);
    }
    uint4 pv;
    unsigned short s[8];
#pragma unroll
    for (int j = 0; j < 8; j++) s[j] = __half_as_ushort(__float2half_rn(o[j]));
    pv.x = (uint32_t)s[0] | ((uint32_t)s[1] << 16);
    pv.y = (uint32_t)s[2] | ((uint32_t)s[3] << 16);
    pv.z = (uint32_t)s[4] | ((uint32_t)s[5] << 16);
    pv.w = (uint32_t)s[6] | ((uint32_t)s[7] << 16);
    const size_t base = ((size_t)(b * 16 + i)) * 512 + h * 64 + c * 8;
    *(uint4*)(g_af + base) = pv;
}

// ---------------------------------------------------------------------------
extern "C" void kernel_launch(void* const* d_in, const int* in_sizes, int n_in,
                              void* d_out, int out_size)
{
    const float*        entities  = (const float*)d_in[0];
    const unsigned int* pre_mask  = (const unsigned int*)d_in[1];
    const unsigned int* post_mask = (const unsigned int*)d_in[2];
    const float*        W_in      = (const float*)d_in[3];
    const float*        W_out     = (const float*)d_in[4];
    const float*        b_out     = (const float*)d_in[5];
    float*              out       = (float*)d_out;

    cudaFuncSetAttribute(fused_qkv_gemm, cudaFuncAttributeMaxDynamicSharedMemorySize, GSMEM_TOTAL);
    cudaFuncSetAttribute(out_gemm,       cudaFuncAttributeMaxDynamicSharedMemorySize, GSMEM_TOTAL);

    // conversions: entities->fp16; W_in->hi/lo; W_out->hi (all x512 scaling on W)
    split_all<<<9216, 256>>>(entities, W_in, W_out);

    // KV projection (fp16 out, 1-term) + Q projection (fp16 out, 2-term) fused
    fused_qkv_gemm<<<4608, 512, GSMEM_TOTAL>>>();

    // Attention (fp16 Q/K/V)
    attn_kernel<<<dim3(BS, NHEAD), 128>>>(pre_mask);

    // Output projection + bias + post_mask (1-term W_out)
    out_gemm<<<dim3(2, 256), 512, GSMEM_TOTAL>>>(out, b_out, post_mask);
}

// round 15
// speedup vs baseline: 2.4553x; 1.1388x over previous
#include <cuda_runtime.h>
#include <cuda_fp16.h>
#include <math.h>
#include <stdint.h>

// Problem constants
#define BS      2048
#define NE      64
#define NQ      16
#define EMBED   512
#define NHEAD   8
#define HD      64

#define WSCALE     512.0f
#define INV_WSCALE (1.0f / 512.0f)

// ---------------------------------------------------------------------------
// Scratch (__device__ globals — allocation-free)
// ---------------------------------------------------------------------------
__device__ __half g_ef[(size_t)BS * NE * 512];    // entities fp16
__device__ __half g_wh[1536 * 512];               // W_in*512 hi
__device__ __half g_wl[1536 * 512];               // W_in*512 lo (Q rows used)
__device__ __half g_oh[512 * 512];                // W_out*512 hi
__device__ __half g_q16[(size_t)BS * NQ * 512];   // Q fp16
__device__ __half g_kv16[(size_t)BS * NE * 1024]; // K|V fp16 interleaved
__device__ __half g_af[(size_t)BS * NQ * 512];    // attn out fp16

__device__ __forceinline__ float neg_inf() { return __int_as_float(0xff800000u); }

__device__ __forceinline__ uint32_t smem_u32(const void* p) {
    uint32_t a;
    asm("{ .reg .u64 t; cvta.to.shared.u64 t, %1; cvt.u32.u64 %0, t; }" : "=r"(a) : "l"(p));
    return a;
}
#define SW128(bo) ((bo) ^ (((bo) >> 3) & 0x70))

#define CP_ASYNC16(dst, src) \
    asm volatile("cp.async.cg.shared.global [%0], [%1], 16;" :: "r"(dst), "l"(src) : "memory")
#define CP_COMMIT() asm volatile("cp.async.commit_group;" ::: "memory")
#define CP_WAIT0()  asm volatile("cp.async.wait_group 0;" ::: "memory")

#define BAR_SYNC(id, cnt) \
    asm volatile("bar.sync %0, %1;" :: "r"(id), "r"(cnt) : "memory")

#define LDMATRIX_X4(r0, r1, r2, r3, addr) \
    asm volatile("ldmatrix.sync.aligned.m8n8.x4.shared.b16 {%0,%1,%2,%3}, [%4];" \
        : "=r"(r0), "=r"(r1), "=r"(r2), "=r"(r3) : "r"(addr))

#define LDMATRIX_X4_T(r0, r1, r2, r3, addr) \
    asm volatile("ldmatrix.sync.aligned.m8n8.x4.trans.shared.b16 {%0,%1,%2,%3}, [%4];" \
        : "=r"(r0), "=r"(r1), "=r"(r2), "=r"(r3) : "r"(addr))

#define MMA_F16(c, a, b) \
    asm volatile("mma.sync.aligned.m16n8k16.row.col.f32.f16.f16.f32 " \
        "{%0,%1,%2,%3}, {%4,%5,%6,%7}, {%8,%9}, {%0,%1,%2,%3};" \
        : "+f"((c)[0]), "+f"((c)[1]), "+f"((c)[2]), "+f"((c)[3]) \
        : "r"((a)[0]), "r"((a)[1]), "r"((a)[2]), "r"((a)[3]), "r"((b)[0]), "r"((b)[1]))

// ---------------------------------------------------------------------------
// Merged conversion kernel (unchanged from R14).
// ---------------------------------------------------------------------------
__global__ void __launch_bounds__(256)
split_all(const float* __restrict__ ent,
          const float* __restrict__ win,
          const float* __restrict__ wout)
{
    const int b = blockIdx.x;
    if (b < 8192) {
        const int n4 = (BS * NE * 512) / 4;
        for (int i = b * 256 + threadIdx.x; i < n4; i += 8192 * 256) {
            const float4 v = ((const float4*)ent)[i];
            uint2 o;
            o.x = (uint32_t)__half_as_ushort(__float2half_rn(v.x)) |
                  ((uint32_t)__half_as_ushort(__float2half_rn(v.y)) << 16);
            o.y = (uint32_t)__half_as_ushort(__float2half_rn(v.z)) |
                  ((uint32_t)__half_as_ushort(__float2half_rn(v.w)) << 16);
            ((uint2*)g_ef)[i] = o;
        }
        return;
    }
    if (b < 8960) {
        const int n4 = (1536 * 512) / 4;
        for (int i = (b - 8192) * 256 + threadIdx.x; i < n4; i += 768 * 256) {
            const float4 v = ((const float4*)win)[i];
            float f[4] = {v.x * WSCALE, v.y * WSCALE, v.z * WSCALE, v.w * WSCALE};
            unsigned short hs[4], ls[4];
#pragma unroll
            for (int j = 0; j < 4; j++) {
                const __half hb = __float2half_rn(f[j]);
                hs[j] = __half_as_ushort(hb);
                ls[j] = __half_as_ushort(__float2half_rn(f[j] - __half2float(hb)));
            }
            uint2 hv, lv;
            hv.x = (uint32_t)hs[0] | ((uint32_t)hs[1] << 16);
            hv.y = (uint32_t)hs[2] | ((uint32_t)hs[3] << 16);
            lv.x = (uint32_t)ls[0] | ((uint32_t)ls[1] << 16);
            lv.y = (uint32_t)ls[2] | ((uint32_t)ls[3] << 16);
            ((uint2*)g_wh)[i] = hv;
            ((uint2*)g_wl)[i] = lv;
        }
        return;
    }
    const int n4 = (512 * 512) / 4;
    for (int i = (b - 8960) * 256 + threadIdx.x; i < n4; i += 256 * 256) {
        const float4 v = ((const float4*)wout)[i];
        uint2 hv;
        hv.x = (uint32_t)__half_as_ushort(__float2half_rn(v.x * WSCALE)) |
               ((uint32_t)__half_as_ushort(__float2half_rn(v.y * WSCALE)) << 16);
        hv.y = (uint32_t)__half_as_ushort(__float2half_rn(v.z * WSCALE)) |
               ((uint32_t)__half_as_ushort(__float2half_rn(v.w * WSCALE)) << 16);
        ((uint2*)g_oh)[i] = hv;
    }
}

// ---------------------------------------------------------------------------
// GEMM core (unchanged from R14).
// ---------------------------------------------------------------------------
#define A_STAGE  16384
#define B_STAGE  65536
#define B_BASE   (2 * A_STAGE)
#define OFF_BL   32768
#define GSMEM_TOTAL (B_BASE + 2 * B_STAGE)
#define NITER 8

template <bool OUTPROJ, bool HOUT, bool TWOTERM>
__device__ __forceinline__ void gemm_core(
    const __half* __restrict__ Afp,
    const __half* __restrict__ Bhp, const __half* __restrict__ Blp,
    void* __restrict__ Cv, int ldc, bool gatherQ, int row0, int col0,
    const float* __restrict__ bias, const unsigned int* __restrict__ mask,
    uint32_t sb)
{
    const int tid  = threadIdx.x;
    const int wid  = tid >> 5;
    const int lane = tid & 31;
    const int wm   = wid >> 3;
    const int wn   = wid & 7;
    const int htid = tid & 255;
    const int ptid = ((tid >> 8) << 5) | (tid & 31);

    float acc[4][4][4];
#pragma unroll
    for (int i = 0; i < 4; i++)
#pragma unroll
        for (int j = 0; j < 4; j++)
#pragma unroll
            for (int k = 0; k < 4; k++) acc[i][j][k] = 0.0f;

    auto issue_load = [&](int t) {
        const int kc = t * 64;
        const uint32_t stA = sb + (uint32_t)(t & 1) * A_STAGE;
        const uint32_t stB = sb + B_BASE + (uint32_t)(t & 1) * B_STAGE;
#pragma unroll
        for (int i = 0; i < 2; i++) {
            const int u = htid + i * 256;
            const int r = u >> 3, c = u & 7;
            const int rf = wm * 64 + r;
            const int gr = row0 + rf;
            const int ar = gatherQ ? (((gr >> 4) << 6) + (gr & 15)) : gr;
            const uint32_t sw = SW128((uint32_t)(rf * 128 + c * 16));
            CP_ASYNC16(stA + sw, Afp + (size_t)ar * 512 + kc + c * 8);
        }
#pragma unroll
        for (int i = 0; i < 4; i++) {
            const int u = ptid + i * 64;
            const int r = u >> 3, c = u & 7;
            const int rf = wn * 32 + r;
            const uint32_t sw = SW128((uint32_t)(rf * 128 + c * 16));
            CP_ASYNC16(stB + sw, Bhp + (size_t)(col0 + rf) * 512 + kc + c * 8);
            if (TWOTERM)
                CP_ASYNC16(stB + OFF_BL + sw, Blp + (size_t)(col0 + rf) * 512 + kc + c * 8);
        }
        CP_COMMIT();
    };

    issue_load(0);

    const int l8   = lane & 7;
    const int lsel = lane >> 3;

    for (int t = 0; t < NITER; t++) {
        CP_WAIT0();
        BAR_SYNC(1 + wm, 256);
        BAR_SYNC(3 + wn, 64);
        if (t + 1 < NITER) issue_load(t + 1);

        const uint32_t stA = sb + (uint32_t)(t & 1) * A_STAGE;
        const uint32_t stB = sb + B_BASE + (uint32_t)(t & 1) * B_STAGE;

#pragma unroll
        for (int ks = 0; ks < 4; ks++) {
            const int ra = wm * 64 + l8 + (lsel & 1) * 8;
            const int ca = ks * 2 + (lsel >> 1);
            const int rb = wn * 32 + (lsel >> 1) * 8 + l8;
            const int cb = ks * 2 + (lsel & 1);

            uint32_t a[4][4], bh[4][2], bl[4][2];
#pragma unroll
            for (int am = 0; am < 4; am++) {
                const int r = ra + am * 16;
                const uint32_t off = (uint32_t)(r * 128 + ((ca ^ (r & 7)) << 4));
                LDMATRIX_X4(a[am][0], a[am][1], a[am][2], a[am][3], stA + off);
            }
#pragma unroll
            for (int bp = 0; bp < 2; bp++) {
                const int r = rb + bp * 16;
                const uint32_t off = (uint32_t)(r * 128 + ((cb ^ (r & 7)) << 4));
                LDMATRIX_X4(bh[2 * bp][0], bh[2 * bp][1], bh[2 * bp + 1][0], bh[2 * bp + 1][1],
                            stB + off);
            }
#pragma unroll
            for (int am = 0; am < 4; am++)
#pragma unroll
                for (int nt = 0; nt < 4; nt++)
                    MMA_F16(acc[am][nt], a[am], bh[nt]);
            if (TWOTERM) {
#pragma unroll
                for (int bp = 0; bp < 2; bp++) {
                    const int r = rb + bp * 16;
                    const uint32_t off = (uint32_t)(r * 128 + ((cb ^ (r & 7)) << 4));
                    LDMATRIX_X4(bl[2 * bp][0], bl[2 * bp][1], bl[2 * bp + 1][0], bl[2 * bp + 1][1],
                                stB + OFF_BL + off);
                }
#pragma unroll
                for (int am = 0; am < 4; am++)
#pragma unroll
                    for (int nt = 0; nt < 4; nt++)
                        MMA_F16(acc[am][nt], a[am], bl[nt]);
            }
        }
    }

    const int g  = lane >> 2;
    const int tg = lane & 3;
#pragma unroll
    for (int am = 0; am < 4; am++) {
        const int r0 = row0 + wm * 64 + am * 16 + g;
        const int r1 = r0 + 8;
        bool z0 = false, z1 = false;
        if (OUTPROJ) { z0 = (mask[r0] != 0u); z1 = (mask[r1] != 0u); }
#pragma unroll
        for (int nt = 0; nt < 4; nt++) {
            const int col = col0 + wn * 32 + nt * 8 + tg * 2;
            float2 v0 = make_float2(acc[am][nt][0] * INV_WSCALE, acc[am][nt][1] * INV_WSCALE);
            float2 v1 = make_float2(acc[am][nt][2] * INV_WSCALE, acc[am][nt][3] * INV_WSCALE);
            if (OUTPROJ) {
                const float bb0 = bias[col], bb1 = bias[col + 1];
                v0.x = z0 ? 0.0f : v0.x + bb0;  v0.y = z0 ? 0.0f : v0.y + bb1;
                v1.x = z1 ? 0.0f : v1.x + bb0;  v1.y = z1 ? 0.0f : v1.y + bb1;
            }
            if (HOUT) {
                __half* Ch = (__half*)Cv;
                *(__half2*)(Ch + (size_t)r0 * ldc + col) = __float22half2_rn(v0);
                *(__half2*)(Ch + (size_t)r1 * ldc + col) = __float22half2_rn(v1);
            } else {
                float* Cf = (float*)Cv;
                *(float2*)(Cf + (size_t)r0 * ldc + col) = v0;
                *(float2*)(Cf + (size_t)r1 * ldc + col) = v1;
            }
        }
    }
}

__global__ void __launch_bounds__(512, 1)
fused_qkv_gemm()
{
    extern __shared__ char smem[];
    const uint32_t sb = smem_u32(smem);
    const int bid = blockIdx.x;
    if (bid < 4096) {
        const int bx = bid & 3, by = bid >> 2;
        gemm_core<false, true, false>(g_ef, g_wh + 512 * 512, nullptr,
                                      g_kv16, 1024, false, by * 128, bx * 256,
                                      nullptr, nullptr, sb);
    } else {
        const int b2 = bid - 4096;
        const int bx = b2 & 1, by = b2 >> 1;
        gemm_core<false, true, true>(g_ef, g_wh, g_wl,
                                     g_q16, 512, true, by * 128, bx * 256,
                                     nullptr, nullptr, sb);
    }
}

__global__ void __launch_bounds__(512, 1)
out_gemm(float* __restrict__ Cout,
         const float* __restrict__ bias,
         const unsigned int* __restrict__ mask)
{
    extern __shared__ char smem[];
    const uint32_t sb = smem_u32(smem);
    gemm_core<true, false, false>(g_af, g_oh, nullptr, Cout, 512, false,
                                  blockIdx.y * 128, blockIdx.x * 256, bias, mask, sb);
}

// ---------------------------------------------------------------------------
// Tensor-core attention: one block per (batch, head), 128 threads (4 warps).
// QK^T and AV via mma.m16n8k16; fragment-domain masked softmax.
// Warp w owns n-slice (QK) and d-slice (AV) [w*16, w*16+16).
// ---------------------------------------------------------------------------
__global__ void __launch_bounds__(128)
attn_kernel(const unsigned int* __restrict__ pre_mask)
{
    __shared__ __half qs[16][72];       // 144B rows: ldmatrix conflict-free
    __shared__ __half ks[64][72];
    __shared__ __half vs[64][72];
    __shared__ __half at[16][72];
    __shared__ unsigned int pm_s[16][64];
    __shared__ float mxr[4][16];
    __shared__ float smr[4][16];

    const int b = blockIdx.x;
    const int h = blockIdx.y;
    const int tid  = threadIdx.x;
    const int wid  = tid >> 5;
    const int lane = tid & 31;
    const int l8   = lane & 7;
    const int lsel = lane >> 3;
    const int g    = lane >> 2;
    const int tg   = lane & 3;

    // ---- loads ----
    {
        const int i = tid >> 3, d8 = tid & 7;
        *(uint4*)&qs[i][d8 * 8] =
            *(const uint4*)(g_q16 + ((size_t)(b * 16 + i)) * 512 + h * 64 + d8 * 8);
    }
#pragma unroll
    for (int rep = 0; rep < 4; rep++) {
        const int u = tid + rep * 128;
        const int n = u >> 3, d8 = u & 7;
        const size_t base = ((size_t)(b * 64 + n)) * 1024 + h * 64 + d8 * 8;
        *(uint4*)&ks[n][d8 * 8] = *(const uint4*)(g_kv16 + base);
        *(uint4*)&vs[n][d8 * 8] = *(const uint4*)(g_kv16 + base + 512);
    }
#pragma unroll
    for (int rep = 0; rep < 2; rep++) {
        const int idx = tid * 2 + rep;           // 0..255 uint4
        const int i = idx >> 4, c = idx & 15;
        *(uint4*)&pm_s[i][c * 4] =
            *(const uint4*)(pre_mask + ((size_t)b * 64 + i) * 64 + c * 4);
    }
    __syncthreads();

    const uint32_t qsb = smem_u32(&qs[0][0]);
    const uint32_t ksb = smem_u32(&ks[0][0]);
    const uint32_t vsb = smem_u32(&vs[0][0]);
    const uint32_t atb = smem_u32(&at[0][0]);

    // ---- QK^T: warp computes logits[16][wid*16 .. +16) ----
    float cqk[2][4] = {{0, 0, 0, 0}, {0, 0, 0, 0}};
    {
        const int arow = (lsel & 1) * 8 + l8;
        const int brow = wid * 16 + (lsel >> 1) * 8 + l8;
#pragma unroll
        for (int kt = 0; kt < 4; kt++) {
            uint32_t aq[4], bk[4];
            LDMATRIX_X4(aq[0], aq[1], aq[2], aq[3],
                        qsb + (uint32_t)(arow * 144 + (kt * 16 + (lsel >> 1) * 8) * 2));
            LDMATRIX_X4(bk[0], bk[1], bk[2], bk[3],
                        ksb + (uint32_t)(brow * 144 + (kt * 16 + (lsel & 1) * 8) * 2));
            uint32_t b0[2] = {bk[0], bk[1]}, b1[2] = {bk[2], bk[3]};
            MMA_F16(cqk[0], aq, b0);
            MMA_F16(cqk[1], aq, b1);
        }
    }

    // ---- masked softmax in fragment domain ----
    const float NI = neg_inf();
    float lg[2][4];
    float mxlo = NI, mxhi = NI;
#pragma unroll
    for (int nt = 0; nt < 2; nt++) {
        const int n0 = wid * 16 + nt * 8 + tg * 2;
        lg[nt][0] = (pm_s[g][n0]         != 0u) ? NI : cqk[nt][0] * 0.125f;
        lg[nt][1] = (pm_s[g][n0 + 1]     != 0u) ? NI : cqk[nt][1] * 0.125f;
        lg[nt][2] = (pm_s[g + 8][n0]     != 0u) ? NI : cqk[nt][2] * 0.125f;
        lg[nt][3] = (pm_s[g + 8][n0 + 1] != 0u) ? NI : cqk[nt][3] * 0.125f;
        mxlo = fmaxf(mxlo, fmaxf(lg[nt][0], lg[nt][1]));
        mxhi = fmaxf(mxhi, fmaxf(lg[nt][2], lg[nt][3]));
    }
    mxlo = fmaxf(mxlo, __shfl_xor_sync(0xffffffffu, mxlo, 1));
    mxlo = fmaxf(mxlo, __shfl_xor_sync(0xffffffffu, mxlo, 2));
    mxhi = fmaxf(mxhi, __shfl_xor_sync(0xffffffffu, mxhi, 1));
    mxhi = fmaxf(mxhi, __shfl_xor_sync(0xffffffffu, mxhi, 2));
    if (tg == 0) { mxr[wid][g] = mxlo; mxr[wid][g + 8] = mxhi; }
    __syncthreads();
    const float Mlo = fmaxf(fmaxf(mxr[0][g], mxr[1][g]), fmaxf(mxr[2][g], mxr[3][g]));
    const float Mhi = fmaxf(fmaxf(mxr[0][g + 8], mxr[1][g + 8]),
                            fmaxf(mxr[2][g + 8], mxr[3][g + 8]));
    const bool anylo = (Mlo != NI);
    const bool anyhi = (Mhi != NI);

    float slo = 0.0f, shi = 0.0f;
#pragma unroll
    for (int nt = 0; nt < 2; nt++) {
        lg[nt][0] = anylo ? __expf(lg[nt][0] - Mlo) : 0.0f;
        lg[nt][1] = anylo ? __expf(lg[nt][1] - Mlo) : 0.0f;
        lg[nt][2] = anyhi ? __expf(lg[nt][2] - Mhi) : 0.0f;
        lg[nt][3] = anyhi ? __expf(lg[nt][3] - Mhi) : 0.0f;
        slo += lg[nt][0] + lg[nt][1];
        shi += lg[nt][2] + lg[nt][3];
    }
    slo += __shfl_xor_sync(0xffffffffu, slo, 1);
    slo += __shfl_xor_sync(0xffffffffu, slo, 2);
    shi += __shfl_xor_sync(0xffffffffu, shi, 1);
    shi += __shfl_xor_sync(0xffffffffu, shi, 2);
    if (tg == 0) { smr[wid][g] = slo; smr[wid][g + 8] = shi; }
    __syncthreads();
    const float Slo = smr[0][g] + smr[1][g] + smr[2][g] + smr[3][g];
    const float Shi = smr[0][g + 8] + smr[1][g + 8] + smr[2][g + 8] + smr[3][g + 8];
    const float invlo = (Slo > 0.0f) ? (1.0f / Slo) : 0.0f;
    const float invhi = (Shi > 0.0f) ? (1.0f / Shi) : 0.0f;

#pragma unroll
    for (int nt = 0; nt < 2; nt++) {
        const int n0 = wid * 16 + nt * 8 + tg * 2;
        *(__half2*)&at[g][n0]     = __floats2half2_rn(lg[nt][0] * invlo, lg[nt][1] * invlo);
        *(__half2*)&at[g + 8][n0] = __floats2half2_rn(lg[nt][2] * invhi, lg[nt][3] * invhi);
    }
    __syncthreads();

    // ---- AV: warp computes out[16][wid*16 .. +16) ----
    float cav[2][4] = {{0, 0, 0, 0}, {0, 0, 0, 0}};
    {
        const int arow = (lsel & 1) * 8 + l8;
        const int tcol = wid * 16 + (lsel >> 1) * 8;   // d-col for trans tiles
#pragma unroll
        for (int kt = 0; kt < 4; kt++) {
            uint32_t aa[4], bv[4];
            LDMATRIX_X4(aa[0], aa[1], aa[2], aa[3],
                        atb + (uint32_t)(arow * 144 + (kt * 16 + (lsel >> 1) * 8) * 2));
            // trans tiles: rows k (=n) within kt, cols d
            LDMATRIX_X4_T(bv[0], bv[1], bv[2], bv[3],
                          vsb + (uint32_t)((kt * 16 + (lsel & 1) * 8 + l8) * 144 + tcol * 2));
            uint32_t b0[2] = {bv[0], bv[1]}, b1[2] = {bv[2], bv[3]};
            MMA_F16(cav[0], aa, b0);
            MMA_F16(cav[1], aa, b1);
        }
    }

    // ---- store fp16 attn-out ----
#pragma unroll
    for (int nt = 0; nt < 2; nt++) {
        const int d0 = wid * 16 + nt * 8 + tg * 2;
        *(__half2*)(g_af + ((size_t)(b * 16 + g)) * 512 + h * 64 + d0) =
            __floats2half2_rn(cav[nt][0], cav[nt][1]);
        *(__half2*)(g_af + ((size_t)(b * 16 + g + 8)) * 512 + h * 64 + d0) =
            __floats2half2_rn(cav[nt][2], cav[nt][3]);
    }
}

// ---------------------------------------------------------------------------
extern "C" void kernel_launch(void* const* d_in, const int* in_sizes, int n_in,
                              void* d_out, int out_size)
{
    const float*        entities  = (const float*)d_in[0];
    const unsigned int* pre_mask  = (const unsigned int*)d_in[1];
    const unsigned int* post_mask = (const unsigned int*)d_in[2];
    const float*        W_in      = (const float*)d_in[3];
    const float*        W_out     = (const float*)d_in[4];
    const float*        b_out     = (const float*)d_in[5];
    float*              out       = (float*)d_out;

    cudaFuncSetAttribute(fused_qkv_gemm, cudaFuncAttributeMaxDynamicSharedMemorySize, GSMEM_TOTAL);
    cudaFuncSetAttribute(out_gemm,       cudaFuncAttributeMaxDynamicSharedMemorySize, GSMEM_TOTAL);

    split_all<<<9216, 256>>>(entities, W_in, W_out);
    fused_qkv_gemm<<<4608, 512, GSMEM_TOTAL>>>();
    attn_kernel<<<dim3(BS, NHEAD), 128>>>(pre_mask);
    out_gemm<<<dim3(2, 256), 512, GSMEM_TOTAL>>>(out, b_out, post_mask);
}

// round 17
// speedup vs baseline: 2.5404x; 1.0347x over previous
#include <cuda_runtime.h>
#include <cuda_fp16.h>
#include <math.h>
#include <stdint.h>

// Problem constants
#define BS      2048
#define NE      64
#define NQ      16
#define EMBED   512
#define NHEAD   8
#define HD      64

#define WSCALE     512.0f
#define INV_WSCALE (1.0f / 512.0f)

// ---------------------------------------------------------------------------
// Scratch (__device__ globals — allocation-free)
// ---------------------------------------------------------------------------
__device__ __half g_ef[(size_t)BS * NE * 512];    // entities fp16
__device__ __half g_wh[1536 * 512];               // W_in*512 hi
__device__ __half g_wl[1536 * 512];               // W_in*512 lo (Q rows used)
__device__ __half g_oh[512 * 512];                // W_out*512 hi
__device__ __half g_q16[(size_t)BS * NQ * 512];   // Q fp16
__device__ __half g_kv16[(size_t)BS * NE * 1024]; // K|V fp16 interleaved
__device__ __half g_af[(size_t)BS * NQ * 512];    // attn out fp16

__device__ __forceinline__ float neg_inf() { return __int_as_float(0xff800000u); }

__device__ __forceinline__ uint32_t pack_half2(float lo, float hi) {
    const unsigned short a = __half_as_ushort(__float2half_rn(lo));
    const unsigned short c = __half_as_ushort(__float2half_rn(hi));
    return (uint32_t)a | ((uint32_t)c << 16);
}

__device__ __forceinline__ uint32_t smem_u32(const void* p) {
    uint32_t a;
    asm("{ .reg .u64 t; cvta.to.shared.u64 t, %1; cvt.u32.u64 %0, t; }" : "=r"(a) : "l"(p));
    return a;
}
#define SW128(bo) ((bo) ^ (((bo) >> 3) & 0x70))

#define CP_ASYNC16(dst, src) \
    asm volatile("cp.async.cg.shared.global [%0], [%1], 16;" :: "r"(dst), "l"(src) : "memory")
#define CP_COMMIT() asm volatile("cp.async.commit_group;" ::: "memory")
#define CP_WAIT0()  asm volatile("cp.async.wait_group 0;" ::: "memory")

#define BAR_SYNC(id, cnt) \
    asm volatile("bar.sync %0, %1;" :: "r"(id), "r"(cnt) : "memory")

#define LDMATRIX_X4(r0, r1, r2, r3, addr) \
    asm volatile("ldmatrix.sync.aligned.m8n8.x4.shared.b16 {%0,%1,%2,%3}, [%4];" \
        : "=r"(r0), "=r"(r1), "=r"(r2), "=r"(r3) : "r"(addr))

#define LDMATRIX_X4_T(r0, r1, r2, r3, addr) \
    asm volatile("ldmatrix.sync.aligned.m8n8.x4.trans.shared.b16 {%0,%1,%2,%3}, [%4];" \
        : "=r"(r0), "=r"(r1), "=r"(r2), "=r"(r3) : "r"(addr))

#define MMA_F16(c, a, b) \
    asm volatile("mma.sync.aligned.m16n8k16.row.col.f32.f16.f16.f32 " \
        "{%0,%1,%2,%3}, {%4,%5,%6,%7}, {%8,%9}, {%0,%1,%2,%3};" \
        : "+f"((c)[0]), "+f"((c)[1]), "+f"((c)[2]), "+f"((c)[3]) \
        : "r"((a)[0]), "r"((a)[1]), "r"((a)[2]), "r"((a)[3]), "r"((b)[0]), "r"((b)[1]))

// ---------------------------------------------------------------------------
// Merged conversion kernel (unchanged).
// ---------------------------------------------------------------------------
__global__ void __launch_bounds__(256)
split_all(const float* __restrict__ ent,
          const float* __restrict__ win,
          const float* __restrict__ wout)
{
    const int b = blockIdx.x;
    if (b < 8192) {
        const int n4 = (BS * NE * 512) / 4;
        for (int i = b * 256 + threadIdx.x; i < n4; i += 8192 * 256) {
            const float4 v = ((const float4*)ent)[i];
            uint2 o;
            o.x = pack_half2(v.x, v.y);
            o.y = pack_half2(v.z, v.w);
            ((uint2*)g_ef)[i] = o;
        }
        return;
    }
    if (b < 8960) {
        const int n4 = (1536 * 512) / 4;
        for (int i = (b - 8192) * 256 + threadIdx.x; i < n4; i += 768 * 256) {
            const float4 v = ((const float4*)win)[i];
            float f[4] = {v.x * WSCALE, v.y * WSCALE, v.z * WSCALE, v.w * WSCALE};
            unsigned short hs[4], ls[4];
#pragma unroll
            for (int j = 0; j < 4; j++) {
                const __half hb = __float2half_rn(f[j]);
                hs[j] = __half_as_ushort(hb);
                ls[j] = __half_as_ushort(__float2half_rn(f[j] - __half2float(hb)));
            }
            uint2 hv, lv;
            hv.x = (uint32_t)hs[0] | ((uint32_t)hs[1] << 16);
            hv.y = (uint32_t)hs[2] | ((uint32_t)hs[3] << 16);
            lv.x = (uint32_t)ls[0] | ((uint32_t)ls[1] << 16);
            lv.y = (uint32_t)ls[2] | ((uint32_t)ls[3] << 16);
            ((uint2*)g_wh)[i] = hv;
            ((uint2*)g_wl)[i] = lv;
        }
        return;
    }
    const int n4 = (512 * 512) / 4;
    for (int i = (b - 8960) * 256 + threadIdx.x; i < n4; i += 256 * 256) {
        const float4 v = ((const float4*)wout)[i];
        uint2 hv;
        hv.x = pack_half2(v.x * WSCALE, v.y * WSCALE);
        hv.y = pack_half2(v.z * WSCALE, v.w * WSCALE);
        ((uint2*)g_oh)[i] = hv;
    }
}

// ---------------------------------------------------------------------------
// GEMM core (unchanged).
// ---------------------------------------------------------------------------
#define A_STAGE  16384
#define B_STAGE  65536
#define B_BASE   (2 * A_STAGE)
#define OFF_BL   32768
#define GSMEM_TOTAL (B_BASE + 2 * B_STAGE)
#define NITER 8

template <bool OUTPROJ, bool HOUT, bool TWOTERM>
__device__ __forceinline__ void gemm_core(
    const __half* __restrict__ Afp,
    const __half* __restrict__ Bhp, const __half* __restrict__ Blp,
    void* __restrict__ Cv, int ldc, bool gatherQ, int row0, int col0,
    const float* __restrict__ bias, const unsigned int* __restrict__ mask,
    uint32_t sb)
{
    const int tid  = threadIdx.x;
    const int wid  = tid >> 5;
    const int lane = tid & 31;
    const int wm   = wid >> 3;
    const int wn   = wid & 7;
    const int htid = tid & 255;
    const int ptid = ((tid >> 8) << 5) | (tid & 31);

    float acc[4][4][4];
#pragma unroll
    for (int i = 0; i < 4; i++)
#pragma unroll
        for (int j = 0; j < 4; j++)
#pragma unroll
            for (int k = 0; k < 4; k++) acc[i][j][k] = 0.0f;

    auto issue_load = [&](int t) {
        const int kc = t * 64;
        const uint32_t stA = sb + (uint32_t)(t & 1) * A_STAGE;
        const uint32_t stB = sb + B_BASE + (uint32_t)(t & 1) * B_STAGE;
#pragma unroll
        for (int i = 0; i < 2; i++) {
            const int u = htid + i * 256;
            const int r = u >> 3, c = u & 7;
            const int rf = wm * 64 + r;
            const int gr = row0 + rf;
            const int ar = gatherQ ? (((gr >> 4) << 6) + (gr & 15)) : gr;
            const uint32_t sw = SW128((uint32_t)(rf * 128 + c * 16));
            CP_ASYNC16(stA + sw, Afp + (size_t)ar * 512 + kc + c * 8);
        }
#pragma unroll
        for (int i = 0; i < 4; i++) {
            const int u = ptid + i * 64;
            const int r = u >> 3, c = u & 7;
            const int rf = wn * 32 + r;
            const uint32_t sw = SW128((uint32_t)(rf * 128 + c * 16));
            CP_ASYNC16(stB + sw, Bhp + (size_t)(col0 + rf) * 512 + kc + c * 8);
            if (TWOTERM)
                CP_ASYNC16(stB + OFF_BL + sw, Blp + (size_t)(col0 + rf) * 512 + kc + c * 8);
        }
        CP_COMMIT();
    };

    issue_load(0);

    const int l8   = lane & 7;
    const int lsel = lane >> 3;

    for (int t = 0; t < NITER; t++) {
        CP_WAIT0();
        BAR_SYNC(1 + wm, 256);
        BAR_SYNC(3 + wn, 64);
        if (t + 1 < NITER) issue_load(t + 1);

        const uint32_t stA = sb + (uint32_t)(t & 1) * A_STAGE;
        const uint32_t stB = sb + B_BASE + (uint32_t)(t & 1) * B_STAGE;

#pragma unroll
        for (int ks = 0; ks < 4; ks++) {
            const int ra = wm * 64 + l8 + (lsel & 1) * 8;
            const int ca = ks * 2 + (lsel >> 1);
            const int rb = wn * 32 + (lsel >> 1) * 8 + l8;
            const int cb = ks * 2 + (lsel & 1);

            uint32_t a[4][4], bh[4][2], bl[4][2];
#pragma unroll
            for (int am = 0; am < 4; am++) {
                const int r = ra + am * 16;
                const uint32_t off = (uint32_t)(r * 128 + ((ca ^ (r & 7)) << 4));
                LDMATRIX_X4(a[am][0], a[am][1], a[am][2], a[am][3], stA + off);
            }
#pragma unroll
            for (int bp = 0; bp < 2; bp++) {
                const int r = rb + bp * 16;
                const uint32_t off = (uint32_t)(r * 128 + ((cb ^ (r & 7)) << 4));
                LDMATRIX_X4(bh[2 * bp][0], bh[2 * bp][1], bh[2 * bp + 1][0], bh[2 * bp + 1][1],
                            stB + off);
            }
#pragma unroll
            for (int am = 0; am < 4; am++)
#pragma unroll
                for (int nt = 0; nt < 4; nt++)
                    MMA_F16(acc[am][nt], a[am], bh[nt]);
            if (TWOTERM) {
#pragma unroll
                for (int bp = 0; bp < 2; bp++) {
                    const int r = rb + bp * 16;
                    const uint32_t off = (uint32_t)(r * 128 + ((cb ^ (r & 7)) << 4));
                    LDMATRIX_X4(bl[2 * bp][0], bl[2 * bp][1], bl[2 * bp + 1][0], bl[2 * bp + 1][1],
                                stB + OFF_BL + off);
                }
#pragma unroll
                for (int am = 0; am < 4; am++)
#pragma unroll
                    for (int nt = 0; nt < 4; nt++)
                        MMA_F16(acc[am][nt], a[am], bl[nt]);
            }
        }
    }

    const int g  = lane >> 2;
    const int tg = lane & 3;
#pragma unroll
    for (int am = 0; am < 4; am++) {
        const int r0 = row0 + wm * 64 + am * 16 + g;
        const int r1 = r0 + 8;
        bool z0 = false, z1 = false;
        if (OUTPROJ) { z0 = (mask[r0] != 0u); z1 = (mask[r1] != 0u); }
#pragma unroll
        for (int nt = 0; nt < 4; nt++) {
            const int col = col0 + wn * 32 + nt * 8 + tg * 2;
            float2 v0 = make_float2(acc[am][nt][0] * INV_WSCALE, acc[am][nt][1] * INV_WSCALE);
            float2 v1 = make_float2(acc[am][nt][2] * INV_WSCALE, acc[am][nt][3] * INV_WSCALE);
            if (OUTPROJ) {
                const float bb0 = bias[col], bb1 = bias[col + 1];
                v0.x = z0 ? 0.0f : v0.x + bb0;  v0.y = z0 ? 0.0f : v0.y + bb1;
                v1.x = z1 ? 0.0f : v1.x + bb0;  v1.y = z1 ? 0.0f : v1.y + bb1;
            }
            if (HOUT) {
                __half* Ch = (__half*)Cv;
                *(uint32_t*)(Ch + (size_t)r0 * ldc + col) = pack_half2(v0.x, v0.y);
                *(uint32_t*)(Ch + (size_t)r1 * ldc + col) = pack_half2(v1.x, v1.y);
            } else {
                float* Cf = (float*)Cv;
                *(float2*)(Cf + (size_t)r0 * ldc + col) = v0;
                *(float2*)(Cf + (size_t)r1 * ldc + col) = v1;
            }
        }
    }
}

__global__ void __launch_bounds__(512, 1)
fused_qkv_gemm()
{
    extern __shared__ char smem[];
    const uint32_t sb = smem_u32(smem);
    const int bid = blockIdx.x;
    if (bid < 4096) {
        const int bx = bid & 3, by = bid >> 2;
        gemm_core<false, true, false>(g_ef, g_wh + 512 * 512, nullptr,
                                      g_kv16, 1024, false, by * 128, bx * 256,
                                      nullptr, nullptr, sb);
    } else {
        const int b2 = bid - 4096;
        const int bx = b2 & 1, by = b2 >> 1;
        gemm_core<false, true, true>(g_ef, g_wh, g_wl,
                                     g_q16, 512, true, by * 128, bx * 256,
                                     nullptr, nullptr, sb);
    }
}

__global__ void __launch_bounds__(512, 1)
out_gemm(float* __restrict__ Cout,
         const float* __restrict__ bias,
         const unsigned int* __restrict__ mask)
{
    extern __shared__ char smem[];
    const uint32_t sb = smem_u32(smem);
    gemm_core<true, false, false>(g_af, g_oh, nullptr, Cout, 512, false,
                                  blockIdx.y * 128, blockIdx.x * 256, bias, mask, sb);
}

// ---------------------------------------------------------------------------
// Warp-per-head tensor-core attention. Block = (batch, head-group of 4),
// 128 threads. Warp w owns head hg*4+w completely: QK -> in-warp softmax ->
// register repack of weights into A-fragments -> AV. No inter-warp comms
// after the load barrier.
// Dynamic smem: Q[16][APITCH] | K[64][APITCH] | V[64][APITCH] halves + mask bytes.
// ---------------------------------------------------------------------------
#define APITCH 264    // 528B rows, odd multiple of 16B -> ldmatrix conflict-free
#define KS_OFF (16 * APITCH)
#define VS_OFF (KS_OFF + 64 * APITCH)
#define PM_OFF ((VS_OFF + 64 * APITCH) * 2)          // byte offset
#define ASMEM_TOTAL (PM_OFF + 1024)

__global__ void __launch_bounds__(128, 2)
attn_kernel(const unsigned int* __restrict__ pre_mask)
{
    extern __shared__ char dsm[];
    __half* qs = (__half*)dsm;
    __half* ks = qs + KS_OFF;
    __half* vs = qs + VS_OFF;
    unsigned char* pm_s = (unsigned char*)(dsm + PM_OFF);

    const int b   = blockIdx.x;
    const int hg  = blockIdx.y;          // 0..1 -> heads hg*4 + wid
    const int tid  = threadIdx.x;
    const int wid  = tid >> 5;
    const int lane = tid & 31;
    const int l8   = lane & 7;
    const int lsel = lane >> 3;
    const int g    = lane >> 2;
    const int tg   = lane & 3;

    // ---- cooperative loads (256-half slice: cols hg*256 of each row) ----
#pragma unroll
    for (int u = tid; u < 512; u += 128) {           // Q: 16 rows x 32 uint4
        const int i = u >> 5, c = u & 31;
        *(uint4*)&qs[i * APITCH + c * 8] =
            *(const uint4*)(g_q16 + ((size_t)(b * 16 + i)) * 512 + hg * 256 + c * 8);
    }
#pragma unroll
    for (int u = tid; u < 2048; u += 128) {          // K,V: 64 rows x 32 uint4
        const int n = u >> 5, c = u & 31;
        const size_t base = ((size_t)(b * 64 + n)) * 1024 + hg * 256 + c * 8;
        *(uint4*)&ks[n * APITCH + c * 8] = *(const uint4*)(g_kv16 + base);
        *(uint4*)&vs[n * APITCH + c * 8] = *(const uint4*)(g_kv16 + base + 512);
    }
#pragma unroll
    for (int u = tid; u < 1024; u += 128)            // masks -> bytes
        pm_s[u] = (pre_mask[(size_t)b * 4096 + u] != 0u) ? 1 : 0;
    __syncthreads();

    const uint32_t qsb = smem_u32(qs) + (uint32_t)(wid * 64) * 2;
    const uint32_t ksb = smem_u32(ks) + (uint32_t)(wid * 64) * 2;
    const uint32_t vsb = smem_u32(vs) + (uint32_t)(wid * 64) * 2;

    // ---- QK^T: full 16x64 logits for this head ----
    float cqk[8][4];
#pragma unroll
    for (int nt = 0; nt < 8; nt++)
#pragma unroll
        for (int k = 0; k < 4; k++) cqk[nt][k] = 0.0f;

#pragma unroll
    for (int kt = 0; kt < 4; kt++) {
        uint32_t aq[4];
        LDMATRIX_X4(aq[0], aq[1], aq[2], aq[3],
                    qsb + (uint32_t)(((lsel & 1) * 8 + l8) * APITCH
                                     + kt * 16 + (lsel >> 1) * 8) * 2);
#pragma unroll
        for (int nt2 = 0; nt2 < 4; nt2++) {
            uint32_t bk[4];
            const int brow = nt2 * 16 + (lsel >> 1) * 8 + l8;
            LDMATRIX_X4(bk[0], bk[1], bk[2], bk[3],
                        ksb + (uint32_t)(brow * APITCH + kt * 16 + (lsel & 1) * 8) * 2);
            uint32_t b0[2] = {bk[0], bk[1]}, b1[2] = {bk[2], bk[3]};
            MMA_F16(cqk[2 * nt2], aq, b0);
            MMA_F16(cqk[2 * nt2 + 1], aq, b1);
        }
    }

    // ---- in-warp masked softmax (rows g and g+8) ----
    const float NI = neg_inf();
    float mxlo = NI, mxhi = NI;
#pragma unroll
    for (int nt = 0; nt < 8; nt++) {
        const int n0 = nt * 8 + tg * 2;
        cqk[nt][0] = pm_s[g * 64 + n0]           ? NI : cqk[nt][0] * 0.125f;
        cqk[nt][1] = pm_s[g * 64 + n0 + 1]       ? NI : cqk[nt][1] * 0.125f;
        cqk[nt][2] = pm_s[(g + 8) * 64 + n0]     ? NI : cqk[nt][2] * 0.125f;
        cqk[nt][3] = pm_s[(g + 8) * 64 + n0 + 1] ? NI : cqk[nt][3] * 0.125f;
        mxlo = fmaxf(mxlo, fmaxf(cqk[nt][0], cqk[nt][1]));
        mxhi = fmaxf(mxhi, fmaxf(cqk[nt][2], cqk[nt][3]));
    }
    mxlo = fmaxf(mxlo, __shfl_xor_sync(0xffffffffu, mxlo, 1));
    mxlo = fmaxf(mxlo, __shfl_xor_sync(0xffffffffu, mxlo, 2));
    mxhi = fmaxf(mxhi, __shfl_xor_sync(0xffffffffu, mxhi, 1));
    mxhi = fmaxf(mxhi, __shfl_xor_sync(0xffffffffu, mxhi, 2));
    const bool anylo = (mxlo != NI);
    const bool anyhi = (mxhi != NI);

    float slo = 0.0f, shi = 0.0f;
#pragma unroll
    for (int nt = 0; nt < 8; nt++) {
        cqk[nt][0] = anylo ? __expf(cqk[nt][0] - mxlo) : 0.0f;
        cqk[nt][1] = anylo ? __expf(cqk[nt][1] - mxlo) : 0.0f;
        cqk[nt][2] = anyhi ? __expf(cqk[nt][2] - mxhi) : 0.0f;
        cqk[nt][3] = anyhi ? __expf(cqk[nt][3] - mxhi) : 0.0f;
        slo += cqk[nt][0] + cqk[nt][1];
        shi += cqk[nt][2] + cqk[nt][3];
    }
    slo += __shfl_xor_sync(0xffffffffu, slo, 1);
    slo += __shfl_xor_sync(0xffffffffu, slo, 2);
    shi += __shfl_xor_sync(0xffffffffu, shi, 1);
    shi += __shfl_xor_sync(0xffffffffu, shi, 2);
    const float invlo = (slo > 0.0f) ? (1.0f / slo) : 0.0f;
    const float invhi = (shi > 0.0f) ? (1.0f / shi) : 0.0f;

    // ---- repack weights (fp16) into A-fragments for AV: aw[kt2] covers
    // keys [16*kt2, 16*kt2+16) = n-tiles 2*kt2, 2*kt2+1 ----
    uint32_t aw[4][4];
#pragma unroll
    for (int kt2 = 0; kt2 < 4; kt2++) {
        const int n0 = 2 * kt2, n1 = n0 + 1;
        aw[kt2][0] = pack_half2(cqk[n0][0] * invlo, cqk[n0][1] * invlo);
        aw[kt2][1] = pack_half2(cqk[n0][2] * invhi, cqk[n0][3] * invhi);
        aw[kt2][2] = pack_half2(cqk[n1][0] * invlo, cqk[n1][1] * invlo);
        aw[kt2][3] = pack_half2(cqk[n1][2] * invhi, cqk[n1][3] * invhi);
    }

    // ---- AV: out[16][64] via trans-ldmatrix of V ----
    float cav[8][4];
#pragma unroll
    for (int dt = 0; dt < 8; dt++)
#pragma unroll
        for (int k = 0; k < 4; k++) cav[dt][k] = 0.0f;

#pragma unroll
    for (int kt2 = 0; kt2 < 4; kt2++) {
#pragma unroll
        for (int dp = 0; dp < 4; dp++) {
            uint32_t bv[4];
            const int vrow = kt2 * 16 + (lsel & 1) * 8 + l8;
            LDMATRIX_X4_T(bv[0], bv[1], bv[2], bv[3],
                          vsb + (uint32_t)(vrow * APITCH + dp * 16 + (lsel >> 1) * 8) * 2);
            uint32_t b0[2] = {bv[0], bv[1]}, b1[2] = {bv[2], bv[3]};
            MMA_F16(cav[2 * dp], aw[kt2], b0);
            MMA_F16(cav[2 * dp + 1], aw[kt2], b1);
        }
    }

    // ---- store fp16 attn-out for head hg*4+wid ----
    const int hcol = (hg * 4 + wid) * 64;
#pragma unroll
    for (int dt = 0; dt < 8; dt++) {
        const int d0 = hcol + dt * 8 + tg * 2;
        *(uint32_t*)(g_af + ((size_t)(b * 16 + g)) * 512 + d0) =
            pack_half2(cav[dt][0], cav[dt][1]);
        *(uint32_t*)(g_af + ((size_t)(b * 16 + g + 8)) * 512 + d0) =
            pack_half2(cav[dt][2], cav[dt][3]);
    }
}

// ---------------------------------------------------------------------------
extern "C" void kernel_launch(void* const* d_in, const int* in_sizes, int n_in,
                              void* d_out, int out_size)
{
    const float*        entities  = (const float*)d_in[0];
    const unsigned int* pre_mask  = (const unsigned int*)d_in[1];
    const unsigned int* post_mask = (const unsigned int*)d_in[2];
    const float*        W_in      = (const float*)d_in[3];
    const float*        W_out     = (const float*)d_in[4];
    const float*        b_out     = (const float*)d_in[5];
    float*              out       = (float*)d_out;

    cudaFuncSetAttribute(fused_qkv_gemm, cudaFuncAttributeMaxDynamicSharedMemorySize, GSMEM_TOTAL);
    cudaFuncSetAttribute(out_gemm,       cudaFuncAttributeMaxDynamicSharedMemorySize, GSMEM_TOTAL);
    cudaFuncSetAttribute(attn_kernel,    cudaFuncAttributeMaxDynamicSharedMemorySize, ASMEM_TOTAL);

    split_all<<<9216, 256>>>(entities, W_in, W_out);
    fused_qkv_gemm<<<4608, 512, GSMEM_TOTAL>>>();
    attn_kernel<<<dim3(BS, 2), 128, ASMEM_TOTAL>>>(pre_mask);
    out_gemm<<<dim3(2, 256), 512, GSMEM_TOTAL>>>(out, b_out, post_mask);
}